// round 10
// baseline (speedup 1.0000x reference)
#include <cuda_runtime.h>
#include <cuda_fp16.h>
#include <math.h>
#include <stdint.h>

#define BSZ 2
#define SEQ 1024
#define TXT 512
#define DIMM 1536
#define NH 12
#define HDD 128
#define NKV 4
#define JD 3584
#define NE 16
#define NI 1344
#define CAP 512
#define LTOT 1536      // SEQ + TXT
#define NTOK 2048      // BSZ*SEQ
#define MROWS 16384    // NE*BSZ*CAP
#define IKV 512        // NKV*HDD
#define REP 3          // NH/NKV
#define EPSL 1e-6f

// ------------------------- fp32 scratch -------------------------------------
__device__ float g_scale1[BSZ*DIMM];
__device__ float g_tg1[BSZ*DIMM];
__device__ float g_scale2[BSZ*DIMM];
__device__ float g_tg2[BSZ*DIMM];
__device__ float g_ctx[BSZ*TXT*DIMM];
__device__ float g_q[NTOK*DIMM];
__device__ float g_kimg[NTOK*IKV];
__device__ float g_vimg[NTOK*IKV];
__device__ float g_ktxt[BSZ*TXT*IKV];
__device__ float g_vtxt[BSZ*TXT*IKV];
__device__ float g_k[BSZ*NKV*LTOT*HDD];
__device__ float g_v[BSZ*NKV*LTOT*HDD];
__device__ float g_hs1[NTOK*DIMM];
__device__ float g_normed2[NTOK*DIMM];
__device__ float g_tembdot[BSZ*NE];
__device__ float g_aff[BSZ*NE*SEQ];
__device__ int   g_topidx[BSZ*NE*CAP];
__device__ float g_gating[BSZ*NE*CAP];
__device__ float g_sums[NTOK];
__device__ int   g_rowmap[MROWS];
__device__ float g_rscale[MROWS];
__device__ float g_hmoe[(size_t)MROWS*2*NI];
__device__ float g_hsh[NTOK*2*NI];
__device__ float g_outflat[NTOK*DIMM];

// ------------------------- half planes --------------------------------------
// weights: hi/lo split (fp32-grade);  activations: single half plane
__device__ __half g_enc_h[BSZ*TXT*JD];
__device__ __half g_Wenc_h[DIMM*JD],        g_Wenc_l[DIMM*JD];
__device__ __half g_Wq_h[DIMM*DIMM],        g_Wq_l[DIMM*DIMM];
__device__ __half g_Wk_h[IKV*DIMM],         g_Wk_l[IKV*DIMM];
__device__ __half g_Wv_h[IKV*DIMM],         g_Wv_l[IKV*DIMM];
__device__ __half g_Wak_h[IKV*DIMM],        g_Wak_l[IKV*DIMM];
__device__ __half g_Wav_h[IKV*DIMM],        g_Wav_l[IKV*DIMM];
__device__ __half g_Wo_h[DIMM*DIMM],        g_Wo_l[DIMM*DIMM];
__device__ __half g_Wein_h[(size_t)NE*2*NI*DIMM], g_Wein_l[(size_t)NE*2*NI*DIMM];
__device__ __half g_Weout_h[(size_t)NE*DIMM*NI],  g_Weout_l[(size_t)NE*DIMM*NI];
__device__ __half g_Wsin_h[2*NI*DIMM],      g_Wsin_l[2*NI*DIMM];
__device__ __half g_Wsout_h[DIMM*NI],       g_Wsout_l[DIMM*NI];
__device__ __half g_ctx_h[BSZ*TXT*DIMM];
__device__ __half g_img_h[NTOK*DIMM];
__device__ __half g_attn_h[NTOK*DIMM];
__device__ __half g_mod2_h[NTOK*DIMM];
__device__ __half g_actsh_h[NTOK*NI];
__device__ __half g_actmoe_h[(size_t)MROWS*NI];

// ======================= helpers ============================================
__device__ __forceinline__ uint32_t s2u(const void* p) {
    uint32_t a;
    asm("{ .reg .u64 t; cvta.to.shared.u64 t, %1; cvt.u32.u64 %0, t; }"
        : "=r"(a) : "l"(p));
    return a;
}
__device__ __forceinline__ void cpa16(uint32_t d, const void* s) {
    asm volatile("cp.async.cg.shared.global [%0], [%1], 16;" :: "r"(d), "l"(s));
}
__device__ __forceinline__ void split2(float x, __half& h, __half& l) {
    h = __float2half(x);
    l = __float2half(x - __half2float(h));
}
__device__ __forceinline__ void mma16816(float* c, const uint32_t* a, const uint32_t* b) {
    asm volatile(
        "mma.sync.aligned.m16n8k16.row.col.f32.f16.f16.f32 "
        "{%0,%1,%2,%3}, {%4,%5,%6,%7}, {%8,%9}, {%0,%1,%2,%3};"
        : "+f"(c[0]), "+f"(c[1]), "+f"(c[2]), "+f"(c[3])
        : "r"(a[0]), "r"(a[1]), "r"(a[2]), "r"(a[3]), "r"(b[0]), "r"(b[1]));
}
// ---- packed f32x2 (sm_100-family PTX) ----
__device__ __forceinline__ unsigned long long pk2(float a, float b) {
    unsigned long long r;
    asm("mov.b64 %0, {%1, %2};" : "=l"(r) : "f"(a), "f"(b));
    return r;
}
__device__ __forceinline__ unsigned long long fma2(unsigned long long a,
                                                   unsigned long long b,
                                                   unsigned long long c) {
    unsigned long long d;
    asm("fma.rn.f32x2 %0, %1, %2, %3;" : "=l"(d) : "l"(a), "l"(b), "l"(c));
    return d;
}
__device__ __forceinline__ unsigned long long mul2(unsigned long long a,
                                                   unsigned long long b) {
    unsigned long long d;
    asm("mul.rn.f32x2 %0, %1, %2;" : "=l"(d) : "l"(a), "l"(b));
    return d;
}
__device__ __forceinline__ void unpk2(unsigned long long v, float& lo, float& hi) {
    asm("mov.b64 {%0, %1}, %2;" : "=f"(lo), "=f"(hi) : "l"(v));
}

// ------------------------- conversions --------------------------------------
__global__ __launch_bounds__(256) void cvt_kernel(const float* __restrict__ src,
                                                  __half* __restrict__ dh,
                                                  __half* __restrict__ dl,
                                                  long long n) {
    long long i = ((long long)blockIdx.x * 256 + threadIdx.x) * 4;
    if (i >= n) return;
    float4 v = *(const float4*)(src + i);
    __half h0, h1, h2, h3, l0, l1, l2, l3;
    split2(v.x, h0, l0); split2(v.y, h1, l1);
    split2(v.z, h2, l2); split2(v.w, h3, l3);
    __half2* ph = (__half2*)(dh + i);
    ph[0] = __halves2half2(h0, h1); ph[1] = __halves2half2(h2, h3);
    __half2* pl = (__half2*)(dl + i);
    pl[0] = __halves2half2(l0, l1); pl[1] = __halves2half2(l2, l3);
}
__global__ __launch_bounds__(256) void cvt1_kernel(const float* __restrict__ src,
                                                   __half* __restrict__ dh,
                                                   long long n) {
    long long i = ((long long)blockIdx.x * 256 + threadIdx.x) * 4;
    if (i >= n) return;
    float4 v = *(const float4*)(src + i);
    __half2* ph = (__half2*)(dh + i);
    ph[0] = __halves2half2(__float2half(v.x), __float2half(v.y));
    ph[1] = __halves2half2(__float2half(v.z), __float2half(v.w));
}

// ======================= pipelined 2-term fp16 GEMM =========================
// C[M,N] = A[M,K]*B[N,K]^T;  A single half plane, B split (hi,lo):
//   acc = Ah*Bh + Ah*Bl      (A fp16-rounded, B fp32-grade; err ~2^-12)
// cp.async double-buffered smem (3 planes x 2 bufs x 10KB = 60KB), CTA tile
// 128x128, K-chunk 32, 8 warps (2x4), warp tile 64x32.
// EPI 0: store  1: +bias[n]  2: resid + gate[b][n]*acc  3: atomic scatter
// AG: gather A rows through agather[z*M + m].
#define PRS 80
#define PLSZ (128*PRS)          // 10240
#define BUFSZ (3*PLSZ)          // 30720
#define MMSM (2*BUFSZ)          // 61440

template<int EPI, bool AG>
__global__ __launch_bounds__(256, 2) void mma_gemm(
    const __half* __restrict__ Ah,
    const __half* __restrict__ Bh, const __half* __restrict__ Bl,
    float* __restrict__ C,
    int M, int N, int K,
    long long sA, long long sB, long long sC,
    const float* __restrict__ bias,
    const float* __restrict__ resid, const float* __restrict__ gate,
    const int* __restrict__ rowmap, const float* __restrict__ rscale,
    const int* __restrict__ agather)
{
    extern __shared__ char smem[];
    const int tid = threadIdx.x;
    const int wid = tid >> 5, lane = tid & 31;
    const int z = blockIdx.z;
    const int m0 = blockIdx.y * 128, n0 = blockIdx.x * 128;
    if (!AG) Ah += (long long)z * sA;
    Bh += (long long)z * sB; Bl += (long long)z * sB;

    const int lr = tid >> 1;
    const int lh = tid & 1;
    long long arow = AG ? (long long)agather[(long long)z * M + m0 + lr]
                        : (long long)(m0 + lr);
    const __half* aHp = Ah + arow * (long long)K + lh * 16;
    const __half* bHp = Bh + (long long)(n0 + lr) * K + lh * 16;
    const __half* bLp = Bl + (long long)(n0 + lr) * K + lh * 16;
    const uint32_t pofs = lr * PRS + lh * 32;

    const uint32_t uAh = s2u(smem);
    const uint32_t uBh = uAh + PLSZ;
    const uint32_t uBl = uAh + 2 * PLSZ;

    const int wm = (wid >> 2) * 64;
    const int wn = (wid & 3) * 32;
    uint32_t a_off[4];
    #pragma unroll
    for (int mt = 0; mt < 4; mt++) {
        int r = wm + mt * 16 + (lane & 15);
        a_off[mt] = r * PRS + (lane >> 4) * 16;
    }
    uint32_t b_off[2];
    #pragma unroll
    for (int np = 0; np < 2; np++) {
        int r = wn + np * 16 + ((lane >> 4) << 3) + (lane & 7);
        b_off[np] = r * PRS + ((lane >> 3) & 1) * 16;
    }

    float acc[4][4][4];
    #pragma unroll
    for (int mt = 0; mt < 4; mt++)
        #pragma unroll
        for (int nt = 0; nt < 4; nt++)
            #pragma unroll
            for (int i = 0; i < 4; i++) acc[mt][nt][i] = 0.f;

    const int NC = K >> 5;
    auto issue = [&](int c, uint32_t boff) {
        long long ko = (long long)c * 32;
        cpa16(uAh + boff + pofs,      aHp + ko);
        cpa16(uAh + boff + pofs + 16, aHp + ko + 8);
        cpa16(uBh + boff + pofs,      bHp + ko);
        cpa16(uBh + boff + pofs + 16, bHp + ko + 8);
        cpa16(uBl + boff + pofs,      bLp + ko);
        cpa16(uBl + boff + pofs + 16, bLp + ko + 8);
        asm volatile("cp.async.commit_group;");
    };

    issue(0, 0);
    for (int c = 0; c < NC; c++) {
        const uint32_t boff = (c & 1) * BUFSZ;
        if (c + 1 < NC) {
            issue(c + 1, (~c & 1) * BUFSZ);
            asm volatile("cp.async.wait_group 1;");
        } else {
            asm volatile("cp.async.wait_group 0;");
        }
        __syncthreads();
        #pragma unroll
        for (int ks = 0; ks < 2; ks++) {
            uint32_t bh[4][2], bl[4][2];
            #pragma unroll
            for (int np = 0; np < 2; np++) {
                asm volatile("ldmatrix.sync.aligned.m8n8.x4.shared.b16 {%0,%1,%2,%3}, [%4];"
                    : "=r"(bh[np*2][0]), "=r"(bh[np*2][1]),
                      "=r"(bh[np*2+1][0]), "=r"(bh[np*2+1][1])
                    : "r"(uBh + boff + b_off[np] + ks * 32));
                asm volatile("ldmatrix.sync.aligned.m8n8.x4.shared.b16 {%0,%1,%2,%3}, [%4];"
                    : "=r"(bl[np*2][0]), "=r"(bl[np*2][1]),
                      "=r"(bl[np*2+1][0]), "=r"(bl[np*2+1][1])
                    : "r"(uBl + boff + b_off[np] + ks * 32));
            }
            #pragma unroll
            for (int mt = 0; mt < 4; mt++) {
                uint32_t ah[4];
                asm volatile("ldmatrix.sync.aligned.m8n8.x4.shared.b16 {%0,%1,%2,%3}, [%4];"
                    : "=r"(ah[0]), "=r"(ah[1]), "=r"(ah[2]), "=r"(ah[3])
                    : "r"(uAh + boff + a_off[mt] + ks * 32));
                #pragma unroll
                for (int nt = 0; nt < 4; nt++) mma16816(acc[mt][nt], ah, bh[nt]);
                #pragma unroll
                for (int nt = 0; nt < 4; nt++) mma16816(acc[mt][nt], ah, bl[nt]);
            }
        }
        __syncthreads();
    }

    const int g = lane >> 2;
    const int cp2 = (lane & 3) * 2;
    #pragma unroll
    for (int mt = 0; mt < 4; mt++) {
        #pragma unroll
        for (int hh = 0; hh < 2; hh++) {
            int row = m0 + wm + mt * 16 + g + hh * 8;
            if (EPI == 3) {
                long long gr = (long long)z * M + row;
                int trow = rowmap[gr];
                float s = rscale[gr];
                float* cp = C + (long long)trow * N;
                #pragma unroll
                for (int nt = 0; nt < 4; nt++) {
                    int col = n0 + wn + nt * 8 + cp2;
                    atomicAdd(cp + col,     acc[mt][nt][hh*2]   * s);
                    atomicAdd(cp + col + 1, acc[mt][nt][hh*2+1] * s);
                }
            } else {
                float* Cz = C + (long long)z * sC + (long long)row * N;
                #pragma unroll
                for (int nt = 0; nt < 4; nt++) {
                    int col = n0 + wn + nt * 8 + cp2;
                    float v0 = acc[mt][nt][hh*2], v1 = acc[mt][nt][hh*2+1];
                    if (EPI == 1) { v0 += bias[col]; v1 += bias[col + 1]; }
                    if (EPI == 2) {
                        const float* gp = gate + (row / SEQ) * N + col;
                        const float* rp = resid + (long long)row * N + col;
                        v0 = rp[0] + gp[0] * v0;
                        v1 = rp[1] + gp[1] * v1;
                    }
                    *(float2*)(Cz + col) = make_float2(v0, v1);
                }
            }
        }
    }
}

// ------------------------- modulation ----------------------------------------
__global__ __launch_bounds__(256) void mod_kernel(const float* __restrict__ temb,
                                                  const float* __restrict__ Wm,
                                                  const float* __restrict__ bm) {
    int gw = (blockIdx.x * blockDim.x + threadIdx.x) >> 5;
    int lane = threadIdx.x & 31;
    if (gw >= BSZ * 4 * DIMM) return;
    int b = gw / (4 * DIMM);
    int j = gw - b * 4 * DIMM;
    const float* t = temb + b * DIMM;
    const float* w = Wm + (size_t)j * DIMM;
    float acc = 0.f;
    for (int kk = lane; kk < DIMM; kk += 32) {
        float x = t[kk];
        acc += (x / (1.f + __expf(-x))) * w[kk];
    }
    #pragma unroll
    for (int o = 16; o; o >>= 1) acc += __shfl_xor_sync(0xffffffffu, acc, o);
    if (lane == 0) {
        acc += bm[j];
        int q = j / DIMM, c = j - q * DIMM;
        if (q == 0)      g_scale1[b*DIMM + c] = 1.f + acc;
        else if (q == 1) g_tg1[b*DIMM + c]    = tanhf(fminf(fmaxf(acc, -2.f), 2.f));
        else if (q == 2) g_scale2[b*DIMM + c] = 1.f + acc;
        else             g_tg2[b*DIMM + c]    = tanhf(fminf(fmaxf(acc, -2.f), 2.f));
    }
}

// ------------------------- LayerNorm -> half (+opt fp32 normed) --------------
__global__ __launch_bounds__(256) void ln_mod_kernel(const float* __restrict__ in,
                                                     const float* __restrict__ scale,
                                                     __half* __restrict__ mh,
                                                     float* __restrict__ outnorm) {
    int rowi = blockIdx.x;
    int b = rowi >> 10;
    const float* x = in + (size_t)rowi * DIMM;
    float s = 0.f, sq = 0.f;
    for (int d = threadIdx.x; d < DIMM; d += 256) { float v = x[d]; s += v; sq += v * v; }
    #pragma unroll
    for (int o = 16; o; o >>= 1) {
        s  += __shfl_xor_sync(0xffffffffu, s,  o);
        sq += __shfl_xor_sync(0xffffffffu, sq, o);
    }
    __shared__ float rs[8], rq[8], mv[2];
    int w = threadIdx.x >> 5;
    if ((threadIdx.x & 31) == 0) { rs[w] = s; rq[w] = sq; }
    __syncthreads();
    if (threadIdx.x == 0) {
        float S = 0.f, Q = 0.f;
        for (int i = 0; i < 8; i++) { S += rs[i]; Q += rq[i]; }
        float mean = S / DIMM;
        float var = Q / DIMM - mean * mean;
        mv[0] = mean; mv[1] = rsqrtf(var + EPSL);
    }
    __syncthreads();
    float mean = mv[0], rstd = mv[1];
    const float* sc = scale + (size_t)b * DIMM;
    for (int d = threadIdx.x; d < DIMM; d += 256) {
        float n = (x[d] - mean) * rstd;
        if (outnorm) outnorm[(size_t)rowi * DIMM + d] = n;
        mh[(size_t)rowi * DIMM + d] = __float2half(n * sc[d]);
    }
}

// ------------------------- per-head RMSNorm of Q ----------------------------
__global__ __launch_bounds__(256) void rms_q_kernel(const float* __restrict__ w) {
    int gw = (blockIdx.x * blockDim.x + threadIdx.x) >> 5;
    if (gw >= NTOK * NH) return;
    int lane = threadIdx.x & 31;
    float* p = g_q + (size_t)gw * HDD;
    int d4 = lane << 2;
    float4 v = *(float4*)(p + d4);
    float ss = v.x*v.x + v.y*v.y + v.z*v.z + v.w*v.w;
    #pragma unroll
    for (int o = 16; o; o >>= 1) ss += __shfl_xor_sync(0xffffffffu, ss, o);
    float r = rsqrtf(ss / HDD + EPSL);
    float4 wv = *(const float4*)(w + d4);
    v.x *= r * wv.x; v.y *= r * wv.y; v.z *= r * wv.z; v.w *= r * wv.w;
    *(float4*)(p + d4) = v;
}

// ------------------------- K RMS + K/V repack -------------------------------
__global__ __launch_bounds__(256) void kv_repack_kernel(const float* __restrict__ nk,
                                                        const float* __restrict__ nak) {
    int gw = (blockIdx.x * blockDim.x + threadIdx.x) >> 5;
    if (gw >= BSZ * NKV * LTOT) return;
    int lane = threadIdx.x & 31;
    int l = gw % LTOT;
    int bk = gw / LTOT;
    int kv = bk % NKV, b = bk / NKV;
    const float *ksrc, *vsrc, *w;
    if (l < SEQ) {
        ksrc = g_kimg + (size_t)(b * SEQ + l) * IKV + kv * HDD;
        vsrc = g_vimg + (size_t)(b * SEQ + l) * IKV + kv * HDD;
        w = nk;
    } else {
        int tt = l - SEQ;
        ksrc = g_ktxt + (size_t)(b * TXT + tt) * IKV + kv * HDD;
        vsrc = g_vtxt + (size_t)(b * TXT + tt) * IKV + kv * HDD;
        w = nak;
    }
    int d4 = lane << 2;
    float4 kvv = *(const float4*)(ksrc + d4);
    float ss = kvv.x*kvv.x + kvv.y*kvv.y + kvv.z*kvv.z + kvv.w*kvv.w;
    #pragma unroll
    for (int o = 16; o; o >>= 1) ss += __shfl_xor_sync(0xffffffffu, ss, o);
    float r = rsqrtf(ss / HDD + EPSL);
    float4 wv = *(const float4*)(w + d4);
    kvv.x *= r * wv.x; kvv.y *= r * wv.y; kvv.z *= r * wv.z; kvv.w *= r * wv.w;
    size_t dst = ((size_t)(b * NKV + kv) * LTOT + l) * HDD + d4;
    *(float4*)(g_k + dst) = kvv;
    *(float4*)(g_v + dst) = *(const float4*)(vsrc + d4);
}

// ------------------------- flash attention (packed f32x2) -------------------
__global__ __launch_bounds__(256) void flash_kernel() {
    __shared__ float Qs[32][132];
    __shared__ float KVs[32][132];
    __shared__ float Ss[32][33];
    const int q0 = blockIdx.x * 32;
    const int h = blockIdx.y;
    const int b = blockIdx.z;
    const int kv = h / REP;
    const int t = threadIdx.x;
    for (int idx = t; idx < 1024; idx += 256) {
        int qi = idx >> 5, d4 = (idx & 31) << 2;
        float4 v = *(const float4*)(g_q + (size_t)(b * SEQ + q0 + qi) * DIMM + h * HDD + d4);
        Qs[qi][d4] = v.x; Qs[qi][d4+1] = v.y; Qs[qi][d4+2] = v.z; Qs[qi][d4+3] = v.w;
    }
    const int q = t >> 3, dg = t & 7;    // thread owns dims [dg*16, dg*16+16)
    unsigned long long acc2[8];
    #pragma unroll
    for (int i = 0; i < 8; i++) acc2[i] = 0ull;
    float m = -1e30f, l = 0.f;
    const float sc = 0.08838834764831845f;  // 1/sqrt(128)
    const float* kbase = g_k + (size_t)(b * NKV + kv) * LTOT * HDD;
    const float* vbase = g_v + (size_t)(b * NKV + kv) * LTOT * HDD;
    __syncthreads();
    for (int k0 = 0; k0 < LTOT; k0 += 32) {
        for (int idx = t; idx < 1024; idx += 256) {
            int ki = idx >> 5, d4 = (idx & 31) << 2;
            float4 v = *(const float4*)(kbase + (size_t)(k0 + ki) * HDD + d4);
            KVs[ki][d4] = v.x; KVs[ki][d4+1] = v.y; KVs[ki][d4+2] = v.z; KVs[ki][d4+3] = v.w;
        }
        __syncthreads();
        {
            int kb = dg << 2;
            unsigned long long s2[4] = {0ull, 0ull, 0ull, 0ull};
            #pragma unroll 8
            for (int d = 0; d < 128; d += 4) {
                union { float4 f; unsigned long long u[2]; } qv, kvv;
                qv.f = *(const float4*)&Qs[q][d];
                #pragma unroll
                for (int j = 0; j < 4; j++) {
                    kvv.f = *(const float4*)&KVs[kb + j][d];
                    s2[j] = fma2(qv.u[0], kvv.u[0], s2[j]);
                    s2[j] = fma2(qv.u[1], kvv.u[1], s2[j]);
                }
            }
            #pragma unroll
            for (int j = 0; j < 4; j++) {
                float lo, hi; unpk2(s2[j], lo, hi);
                Ss[q][kb + j] = (lo + hi) * sc;
            }
        }
        __syncthreads();
        float srow[32];
        float rmax = -1e30f;
        #pragma unroll
        for (int k = 0; k < 32; k++) { srow[k] = Ss[q][k]; rmax = fmaxf(rmax, srow[k]); }
        for (int idx = t; idx < 1024; idx += 256) {
            int ki = idx >> 5, d4 = (idx & 31) << 2;
            float4 v = *(const float4*)(vbase + (size_t)(k0 + ki) * HDD + d4);
            KVs[ki][d4] = v.x; KVs[ki][d4+1] = v.y; KVs[ki][d4+2] = v.z; KVs[ki][d4+3] = v.w;
        }
        float newm = fmaxf(m, rmax);
        float corr = __expf(m - newm);
        float psum = 0.f;
        #pragma unroll
        for (int k = 0; k < 32; k++) { srow[k] = __expf(srow[k] - newm); psum += srow[k]; }
        l = l * corr + psum;
        m = newm;
        unsigned long long cc = pk2(corr, corr);
        #pragma unroll
        for (int i = 0; i < 8; i++) acc2[i] = mul2(acc2[i], cc);
        __syncthreads();
        #pragma unroll
        for (int k = 0; k < 32; k++) {
            unsigned long long pp = pk2(srow[k], srow[k]);
            const float* kr = &KVs[k][dg * 16];
            #pragma unroll
            for (int i = 0; i < 4; i++) {
                union { float4 f; unsigned long long u[2]; } vv;
                vv.f = *(const float4*)(kr + 4 * i);
                acc2[2*i]     = fma2(pp, vv.u[0], acc2[2*i]);
                acc2[2*i + 1] = fma2(pp, vv.u[1], acc2[2*i + 1]);
            }
        }
        __syncthreads();
    }
    float inv = 1.f / l;
    size_t obase = (size_t)(b * SEQ + q0 + q) * DIMM + h * HDD + dg * 16;
    #pragma unroll
    for (int i = 0; i < 8; i++) {
        float lo, hi; unpk2(acc2[i], lo, hi);
        g_attn_h[obase + 2*i]     = __float2half(lo * inv);
        g_attn_h[obase + 2*i + 1] = __float2half(hi * inv);
    }
}

// ------------------------- router ------------------------------------------
__global__ __launch_bounds__(1024) void tembdot_kernel(const float* __restrict__ temb,
                                                       const float* __restrict__ Wg) {
    int wid = threadIdx.x >> 5, lane = threadIdx.x & 31;
    int b = wid / NE, e = wid % NE;
    const float* t = temb + b * DIMM;
    const float* w = Wg + (size_t)e * 2 * DIMM;
    float acc = 0.f;
    for (int d = lane; d < DIMM; d += 32) acc += t[d] * w[d];
    #pragma unroll
    for (int o = 16; o; o >>= 1) acc += __shfl_xor_sync(0xffffffffu, acc, o);
    if (lane == 0) g_tembdot[wid] = acc;
}

__global__ __launch_bounds__(128) void router_kernel(const float* __restrict__ Wg) {
    __shared__ float lg[NE];
    int tokid = blockIdx.x;
    int b = tokid >> 10, s = tokid & 1023;
    int w = threadIdx.x >> 5, lane = threadIdx.x & 31;
    const float* x = g_normed2 + (size_t)tokid * DIMM;
    for (int e = w * 4; e < w * 4 + 4; e++) {
        const float* wg = Wg + (size_t)e * 2 * DIMM + DIMM;
        float acc = 0.f;
        for (int d = lane; d < DIMM; d += 32) acc += x[d] * wg[d];
        #pragma unroll
        for (int o = 16; o; o >>= 1) acc += __shfl_xor_sync(0xffffffffu, acc, o);
        if (lane == 0) lg[e] = acc + g_tembdot[b * NE + e];
    }
    __syncthreads();
    if (threadIdx.x == 0) {
        float mx = -1e30f;
        for (int e = 0; e < NE; e++) mx = fmaxf(mx, lg[e]);
        float ex[NE], sm = 0.f;
        for (int e = 0; e < NE; e++) { ex[e] = __expf(lg[e] - mx); sm += ex[e]; }
        float inv = 1.f / sm;
        for (int e = 0; e < NE; e++)
            g_aff[((size_t)(b * NE + e)) * SEQ + s] = ex[e] * inv;
    }
}

// ------------------------- exact top-k via bitonic sort ---------------------
__global__ __launch_bounds__(512) void topk_kernel() {
    __shared__ float v[1024];
    __shared__ int   id[1024];
    int be = blockIdx.x;
    const float* rowp = g_aff + (size_t)be * SEQ;
    int t = threadIdx.x;
    for (int i = t; i < 1024; i += 512) { v[i] = rowp[i]; id[i] = i; }
    __syncthreads();
    for (int k = 2; k <= 1024; k <<= 1) {
        for (int j = k >> 1; j > 0; j >>= 1) {
            for (int i = t; i < 1024; i += 512) {
                int ixj = i ^ j;
                if (ixj > i) {
                    bool up = ((i & k) == 0);
                    float va = v[i], vb = v[ixj];
                    int ia = id[i], ib = id[ixj];
                    bool a_first = (va > vb) || (va == vb && ia < ib);
                    bool sw = up ? !a_first : a_first;
                    if (sw) { v[i] = vb; v[ixj] = va; id[i] = ib; id[ixj] = ia; }
                }
            }
            __syncthreads();
        }
    }
    if (t < CAP) {
        g_gating[be * CAP + t] = v[t];
        g_topidx[be * CAP + t] = id[t];
    }
}

__global__ void zero_sums_kernel() {
    int i = blockIdx.x * blockDim.x + threadIdx.x;
    if (i < NTOK) g_sums[i] = 0.f;
}

__global__ void sum_acc_kernel() {
    int i = blockIdx.x * blockDim.x + threadIdx.x;
    if (i >= BSZ * NE * CAP) return;
    int be = i / CAP;
    int b = be / NE;
    int tok = b * SEQ + g_topidx[i];
    atomicAdd(&g_sums[tok], g_gating[i]);
}

__global__ void gate_norm_kernel() {
    int i = blockIdx.x * blockDim.x + threadIdx.x;
    if (i >= BSZ * NE * CAP) return;
    int c = i % CAP;
    int be = i / CAP;
    int b = be / NE, e = be % NE;
    int tok = b * SEQ + g_topidx[i];
    float g = g_gating[i] / (g_sums[tok] + 1e-12f) * 2.5f;
    int rowflat = (e * BSZ + b) * CAP + c;
    g_rowmap[rowflat] = tok;
    g_rscale[rowflat] = g;
}

// ------------------------- swiglu -> half ------------------------------------
__global__ __launch_bounds__(256) void swiglu_kernel(const float* __restrict__ h,
                                                     __half* __restrict__ oh) {
    int r = blockIdx.x;
    const float4* a = (const float4*)(h + (size_t)r * 2 * NI);
    const float4* g = (const float4*)(h + (size_t)r * 2 * NI + NI);
    for (int i = threadIdx.x; i < NI / 4; i += 256) {
        float4 av = a[i], gv = g[i];
        float f0 = av.x * (gv.x / (1.f + __expf(-gv.x)));
        float f1 = av.y * (gv.y / (1.f + __expf(-gv.y)));
        float f2 = av.z * (gv.z / (1.f + __expf(-gv.z)));
        float f3 = av.w * (gv.w / (1.f + __expf(-gv.w)));
        __half2* ph = (__half2*)(oh + (size_t)r * NI + i * 4);
        ph[0] = __halves2half2(__float2half(f0), __float2half(f1));
        ph[1] = __halves2half2(__float2half(f2), __float2half(f3));
    }
}

// ------------------------- final residual -----------------------------------
__global__ __launch_bounds__(256) void final_kernel(float* __restrict__ out) {
    int r = blockIdx.x;
    int b = r >> 10;
    const float4* hs = (const float4*)(g_hs1 + (size_t)r * DIMM);
    const float4* mo = (const float4*)(g_outflat + (size_t)r * DIMM);
    const float4* gg = (const float4*)(g_tg2 + (size_t)b * DIMM);
    float4* o = (float4*)(out + (size_t)r * DIMM);
    for (int i = threadIdx.x; i < DIMM / 4; i += 256) {
        float4 h = hs[i], m = mo[i], g = gg[i], v;
        v.x = h.x + g.x * m.x; v.y = h.y + g.y * m.y;
        v.z = h.z + g.z * m.z; v.w = h.w + g.w * m.w;
        o[i] = v;
    }
}

// ------------------------- launcher -----------------------------------------
extern "C" void kernel_launch(void* const* d_in, const int* in_sizes, int n_in,
                              void* d_out, int out_size) {
    const float* hidden = (const float*)d_in[0];
    const float* enc    = (const float*)d_in[1];
    const float* temb   = (const float*)d_in[2];
    const float* W_mod  = (const float*)d_in[3];
    const float* b_mod  = (const float*)d_in[4];
    const float* W_enc  = (const float*)d_in[5];
    const float* b_enc  = (const float*)d_in[6];
    const float* Wq     = (const float*)d_in[7];
    const float* Wk     = (const float*)d_in[8];
    const float* Wv     = (const float*)d_in[9];
    const float* Wak    = (const float*)d_in[10];
    const float* Wav    = (const float*)d_in[11];
    const float* nq_w   = (const float*)d_in[12];
    const float* nk_w   = (const float*)d_in[13];
    const float* nak_w  = (const float*)d_in[14];
    const float* Wo     = (const float*)d_in[15];
    const float* Wg     = (const float*)d_in[16];
    const float* We_in  = (const float*)d_in[17];
    const float* We_out = (const float*)d_in[18];
    const float* Ws_in  = (const float*)d_in[19];
    const float* Ws_out = (const float*)d_in[20];
    float* out = (float*)d_out;

    void* pv;
    #define GF(sym) (cudaGetSymbolAddress(&pv, sym), (float*)pv)
    #define GH(sym) (cudaGetSymbolAddress(&pv, sym), (__half*)pv)
    #define GI(sym) (cudaGetSymbolAddress(&pv, sym), (int*)pv)
    float* p_ctx     = GF(g_ctx);
    float* p_q       = GF(g_q);
    float* p_kimg    = GF(g_kimg);
    float* p_vimg    = GF(g_vimg);
    float* p_ktxt    = GF(g_ktxt);
    float* p_vtxt    = GF(g_vtxt);
    float* p_hs1     = GF(g_hs1);
    float* p_normed2 = GF(g_normed2);
    float* p_hmoe    = GF(g_hmoe);
    float* p_hsh     = GF(g_hsh);
    float* p_outflat = GF(g_outflat);
    float* p_scale1  = GF(g_scale1);
    float* p_scale2  = GF(g_scale2);
    float* p_tg1     = GF(g_tg1);
    int*   p_rowmap  = GI(g_rowmap);
    float* p_rscale  = GF(g_rscale);
    __half *p_enc_h = GH(g_enc_h);
    __half *p_Wenc_h = GH(g_Wenc_h), *p_Wenc_l = GH(g_Wenc_l);
    __half *p_Wq_h = GH(g_Wq_h),     *p_Wq_l = GH(g_Wq_l);
    __half *p_Wk_h = GH(g_Wk_h),     *p_Wk_l = GH(g_Wk_l);
    __half *p_Wv_h = GH(g_Wv_h),     *p_Wv_l = GH(g_Wv_l);
    __half *p_Wak_h = GH(g_Wak_h),   *p_Wak_l = GH(g_Wak_l);
    __half *p_Wav_h = GH(g_Wav_h),   *p_Wav_l = GH(g_Wav_l);
    __half *p_Wo_h = GH(g_Wo_h),     *p_Wo_l = GH(g_Wo_l);
    __half *p_Wein_h = GH(g_Wein_h), *p_Wein_l = GH(g_Wein_l);
    __half *p_Weout_h = GH(g_Weout_h), *p_Weout_l = GH(g_Weout_l);
    __half *p_Wsin_h = GH(g_Wsin_h), *p_Wsin_l = GH(g_Wsin_l);
    __half *p_Wsout_h = GH(g_Wsout_h), *p_Wsout_l = GH(g_Wsout_l);
    __half *p_ctx_h = GH(g_ctx_h);
    __half *p_img_h = GH(g_img_h);
    __half *p_attn_h = GH(g_attn_h);
    __half *p_mod2_h = GH(g_mod2_h);
    __half *p_actsh_h = GH(g_actsh_h);
    __half *p_actmoe_h = GH(g_actmoe_h);

    cudaFuncSetAttribute(mma_gemm<0,false>, cudaFuncAttributeMaxDynamicSharedMemorySize, MMSM);
    cudaFuncSetAttribute(mma_gemm<1,false>, cudaFuncAttributeMaxDynamicSharedMemorySize, MMSM);
    cudaFuncSetAttribute(mma_gemm<2,false>, cudaFuncAttributeMaxDynamicSharedMemorySize, MMSM);
    cudaFuncSetAttribute(mma_gemm<3,false>, cudaFuncAttributeMaxDynamicSharedMemorySize, MMSM);
    cudaFuncSetAttribute(mma_gemm<0,true>,  cudaFuncAttributeMaxDynamicSharedMemorySize, MMSM);

    const float* NFP = nullptr;
    const int*   NIP = nullptr;

    #define CVT(src, dh, dl, n) \
        cvt_kernel<<<(int)(((n)/4 + 255)/256), 256>>>(src, dh, dl, (long long)(n))
    #define CVT1(src, dh, n) \
        cvt1_kernel<<<(int)(((n)/4 + 255)/256), 256>>>(src, dh, (long long)(n))

    // 0. convert weights (hi/lo) + enc (single half)
    CVT(W_enc, p_Wenc_h, p_Wenc_l, (long long)DIMM*JD);
    CVT(Wq,  p_Wq_h,  p_Wq_l,  (long long)DIMM*DIMM);
    CVT(Wk,  p_Wk_h,  p_Wk_l,  (long long)IKV*DIMM);
    CVT(Wv,  p_Wv_h,  p_Wv_l,  (long long)IKV*DIMM);
    CVT(Wak, p_Wak_h, p_Wak_l, (long long)IKV*DIMM);
    CVT(Wav, p_Wav_h, p_Wav_l, (long long)IKV*DIMM);
    CVT(Wo,  p_Wo_h,  p_Wo_l,  (long long)DIMM*DIMM);
    CVT(We_in,  p_Wein_h,  p_Wein_l,  (long long)NE*2*NI*DIMM);
    CVT(We_out, p_Weout_h, p_Weout_l, (long long)NE*DIMM*NI);
    CVT(Ws_in,  p_Wsin_h,  p_Wsin_l,  (long long)2*NI*DIMM);
    CVT(Ws_out, p_Wsout_h, p_Wsout_l, (long long)DIMM*NI);
    CVT1(enc, p_enc_h, (long long)BSZ*TXT*JD);

    // 1. modulation
    mod_kernel<<<1536, 256>>>(temb, W_mod, b_mod);
    // 2. context projection (+bias), then convert ctx
    mma_gemm<1,false><<<dim3(12, 8, 1), 256, MMSM>>>(p_enc_h,
        p_Wenc_h, p_Wenc_l, p_ctx, BSZ*TXT, DIMM, JD, 0, 0, 0,
        b_enc, NFP, NFP, NIP, NFP, NIP);
    CVT1(p_ctx, p_ctx_h, (long long)BSZ*TXT*DIMM);
    // 3. LN1 * scale1 -> half
    ln_mod_kernel<<<NTOK, 256>>>(hidden, p_scale1, p_img_h, nullptr);
    // 4. projections
    mma_gemm<0,false><<<dim3(12, 16, 1), 256, MMSM>>>(p_img_h,
        p_Wq_h, p_Wq_l, p_q, NTOK, DIMM, DIMM, 0, 0, 0, NFP, NFP, NFP, NIP, NFP, NIP);
    mma_gemm<0,false><<<dim3(4, 16, 1), 256, MMSM>>>(p_img_h,
        p_Wk_h, p_Wk_l, p_kimg, NTOK, IKV, DIMM, 0, 0, 0, NFP, NFP, NFP, NIP, NFP, NIP);
    mma_gemm<0,false><<<dim3(4, 16, 1), 256, MMSM>>>(p_img_h,
        p_Wv_h, p_Wv_l, p_vimg, NTOK, IKV, DIMM, 0, 0, 0, NFP, NFP, NFP, NIP, NFP, NIP);
    mma_gemm<0,false><<<dim3(4, 8, 1), 256, MMSM>>>(p_ctx_h,
        p_Wak_h, p_Wak_l, p_ktxt, BSZ*TXT, IKV, DIMM, 0, 0, 0, NFP, NFP, NFP, NIP, NFP, NIP);
    mma_gemm<0,false><<<dim3(4, 8, 1), 256, MMSM>>>(p_ctx_h,
        p_Wav_h, p_Wav_l, p_vtxt, BSZ*TXT, IKV, DIMM, 0, 0, 0, NFP, NFP, NFP, NIP, NFP, NIP);
    // 5. norms + repack
    rms_q_kernel<<<3072, 256>>>(nq_w);
    kv_repack_kernel<<<1536, 256>>>(nk_w, nak_w);
    // 6. attention (-> half)
    flash_kernel<<<dim3(SEQ/32, NH, BSZ), 256>>>();
    // 7. output proj + gated residual
    mma_gemm<2,false><<<dim3(12, 16, 1), 256, MMSM>>>(p_attn_h,
        p_Wo_h, p_Wo_l, p_hs1, NTOK, DIMM, DIMM, 0, 0, 0,
        NFP, hidden, p_tg1, NIP, NFP, NIP);
    // 8. LN2 -> mod2 half + normed2 fp32
    ln_mod_kernel<<<NTOK, 256>>>(p_hs1, p_scale2, p_mod2_h, p_normed2);
    // 9. router
    tembdot_kernel<<<1, 1024>>>(temb, Wg);
    router_kernel<<<NTOK, 128>>>(Wg);
    topk_kernel<<<BSZ*NE, 512>>>();
    zero_sums_kernel<<<8, 256>>>();
    sum_acc_kernel<<<64, 256>>>();
    gate_norm_kernel<<<64, 256>>>();
    // 10. expert GEMM 1 (gathered A rows, batched over 16 experts)
    mma_gemm<0,true><<<dim3(21, 8, 16), 256, MMSM>>>(p_mod2_h,
        p_Wein_h, p_Wein_l, p_hmoe, BSZ*CAP, 2*NI, DIMM,
        0, (long long)2*NI*DIMM, (long long)BSZ*CAP*2*NI,
        NFP, NFP, NFP, NIP, NFP, p_rowmap);
    swiglu_kernel<<<MROWS, 256>>>(p_hmoe, p_actmoe_h);
    // 11. shared expert
    mma_gemm<0,false><<<dim3(21, 16, 1), 256, MMSM>>>(p_mod2_h,
        p_Wsin_h, p_Wsin_l, p_hsh, NTOK, 2*NI, DIMM, 0, 0, 0,
        NFP, NFP, NFP, NIP, NFP, NIP);
    swiglu_kernel<<<NTOK, 256>>>(p_hsh, p_actsh_h);
    mma_gemm<0,false><<<dim3(12, 16, 1), 256, MMSM>>>(p_actsh_h,
        p_Wsout_h, p_Wsout_l, p_outflat, NTOK, DIMM, NI, 0, 0, 0,
        NFP, NFP, NFP, NIP, NFP, NIP);
    // 12. expert GEMM 2 with atomic scatter onto shared output
    mma_gemm<3,false><<<dim3(12, 8, 16), 256, MMSM>>>(p_actmoe_h,
        p_Weout_h, p_Weout_l, p_outflat, BSZ*CAP, DIMM, NI,
        (long long)BSZ*CAP*NI, (long long)DIMM*NI, 0,
        NFP, NFP, NFP, p_rowmap, p_rscale, NIP);
    // 13. final gated residual
    final_kernel<<<NTOK, 256>>>(out);
}

// round 11
// speedup vs baseline: 1.7891x; 1.7891x over previous
#include <cuda_runtime.h>
#include <cuda_fp16.h>
#include <math.h>
#include <stdint.h>

#define BSZ 2
#define SEQ 1024
#define TXT 512
#define DIMM 1536
#define NH 12
#define HDD 128
#define NKV 4
#define JD 3584
#define NE 16
#define NI 1344
#define CAP 512
#define LTOT 1536      // SEQ + TXT
#define NTOK 2048      // BSZ*SEQ
#define MROWS 16384    // NE*BSZ*CAP
#define IKV 512        // NKV*HDD
#define REP 3          // NH/NKV
#define EPSL 1e-6f

// ------------------------- fp32 scratch -------------------------------------
__device__ float g_scale1[BSZ*DIMM];
__device__ float g_tg1[BSZ*DIMM];
__device__ float g_scale2[BSZ*DIMM];
__device__ float g_tg2[BSZ*DIMM];
__device__ float g_ctx[BSZ*TXT*DIMM];
__device__ float g_q[NTOK*DIMM];
__device__ float g_kimg[NTOK*IKV];
__device__ float g_vimg[NTOK*IKV];
__device__ float g_ktxt[BSZ*TXT*IKV];
__device__ float g_vtxt[BSZ*TXT*IKV];
__device__ float g_k[BSZ*NKV*LTOT*HDD];
__device__ float g_v[BSZ*NKV*LTOT*HDD];
__device__ float g_hs1[NTOK*DIMM];
__device__ float g_normed2[NTOK*DIMM];
__device__ float g_tembdot[BSZ*NE];
__device__ float g_aff[BSZ*NE*SEQ];
__device__ int   g_topidx[BSZ*NE*CAP];
__device__ float g_gating[BSZ*NE*CAP];
__device__ float g_sums[NTOK];
__device__ int   g_rowmap[MROWS];
__device__ float g_rscale[MROWS];
__device__ float g_hmoe[(size_t)MROWS*2*NI];
__device__ float g_hsh[NTOK*2*NI];
__device__ float g_outflat[NTOK*DIMM];

// ------------------------- half planes --------------------------------------
// weights: hi/lo split (fp32-grade);  activations: single half plane
__device__ __half g_enc_h[BSZ*TXT*JD];
__device__ __half g_Wenc_h[DIMM*JD],        g_Wenc_l[DIMM*JD];
__device__ __half g_Wq_h[DIMM*DIMM],        g_Wq_l[DIMM*DIMM];
__device__ __half g_Wk_h[IKV*DIMM],         g_Wk_l[IKV*DIMM];
__device__ __half g_Wv_h[IKV*DIMM],         g_Wv_l[IKV*DIMM];
__device__ __half g_Wak_h[IKV*DIMM],        g_Wak_l[IKV*DIMM];
__device__ __half g_Wav_h[IKV*DIMM],        g_Wav_l[IKV*DIMM];
__device__ __half g_Wo_h[DIMM*DIMM],        g_Wo_l[DIMM*DIMM];
__device__ __half g_Wein_h[(size_t)NE*2*NI*DIMM], g_Wein_l[(size_t)NE*2*NI*DIMM];
__device__ __half g_Weout_h[(size_t)NE*DIMM*NI],  g_Weout_l[(size_t)NE*DIMM*NI];
__device__ __half g_Wsin_h[2*NI*DIMM],      g_Wsin_l[2*NI*DIMM];
__device__ __half g_Wsout_h[DIMM*NI],       g_Wsout_l[DIMM*NI];
__device__ __half g_ctx_h[BSZ*TXT*DIMM];
__device__ __half g_img_h[NTOK*DIMM];
__device__ __half g_attn_h[NTOK*DIMM];
__device__ __half g_mod2_h[NTOK*DIMM];
__device__ __half g_actsh_h[NTOK*NI];
__device__ __half g_actmoe_h[(size_t)MROWS*NI];

// ======================= helpers ============================================
__device__ __forceinline__ uint32_t s2u(const void* p) {
    uint32_t a;
    asm("{ .reg .u64 t; cvta.to.shared.u64 t, %1; cvt.u32.u64 %0, t; }"
        : "=r"(a) : "l"(p));
    return a;
}
__device__ __forceinline__ void cpa16(uint32_t d, const void* s) {
    asm volatile("cp.async.cg.shared.global [%0], [%1], 16;" :: "r"(d), "l"(s));
}
__device__ __forceinline__ void split2(float x, __half& h, __half& l) {
    h = __float2half(x);
    l = __float2half(x - __half2float(h));
}
__device__ __forceinline__ void mma16816(float* c, const uint32_t* a, const uint32_t* b) {
    asm volatile(
        "mma.sync.aligned.m16n8k16.row.col.f32.f16.f16.f32 "
        "{%0,%1,%2,%3}, {%4,%5,%6,%7}, {%8,%9}, {%0,%1,%2,%3};"
        : "+f"(c[0]), "+f"(c[1]), "+f"(c[2]), "+f"(c[3])
        : "r"(a[0]), "r"(a[1]), "r"(a[2]), "r"(a[3]), "r"(b[0]), "r"(b[1]));
}

// ------------------------- conversions --------------------------------------
__global__ __launch_bounds__(256) void cvt_kernel(const float* __restrict__ src,
                                                  __half* __restrict__ dh,
                                                  __half* __restrict__ dl,
                                                  long long n) {
    long long i = ((long long)blockIdx.x * 256 + threadIdx.x) * 4;
    if (i >= n) return;
    float4 v = *(const float4*)(src + i);
    __half h0, h1, h2, h3, l0, l1, l2, l3;
    split2(v.x, h0, l0); split2(v.y, h1, l1);
    split2(v.z, h2, l2); split2(v.w, h3, l3);
    __half2* ph = (__half2*)(dh + i);
    ph[0] = __halves2half2(h0, h1); ph[1] = __halves2half2(h2, h3);
    __half2* pl = (__half2*)(dl + i);
    pl[0] = __halves2half2(l0, l1); pl[1] = __halves2half2(l2, l3);
}
__global__ __launch_bounds__(256) void cvt1_kernel(const float* __restrict__ src,
                                                   __half* __restrict__ dh,
                                                   long long n) {
    long long i = ((long long)blockIdx.x * 256 + threadIdx.x) * 4;
    if (i >= n) return;
    float4 v = *(const float4*)(src + i);
    __half2* ph = (__half2*)(dh + i);
    ph[0] = __halves2half2(__float2half(v.x), __float2half(v.y));
    ph[1] = __halves2half2(__float2half(v.z), __float2half(v.w));
}

// ======================= pipelined 2-term fp16 GEMM =========================
// C[M,N] = A[M,K]*B[N,K]^T;  A single half plane, B split (hi,lo):
//   acc = Ah*Bh + Ah*Bl      (A fp16-rounded, B fp32-grade; err ~2^-12)
// cp.async double-buffered smem (3 planes x 2 bufs x 10KB = 60KB), CTA tile
// 128x128, K-chunk 32, 8 warps (2x4), warp tile 64x32.
// EPI 0: store  1: +bias[n]  2: resid + gate[b][n]*acc  3: atomic scatter
// AG: gather A rows through agather[z*M + m].
#define PRS 80
#define PLSZ (128*PRS)          // 10240
#define BUFSZ (3*PLSZ)          // 30720
#define MMSM (2*BUFSZ)          // 61440

template<int EPI, bool AG>
__global__ __launch_bounds__(256, 2) void mma_gemm(
    const __half* __restrict__ Ah,
    const __half* __restrict__ Bh, const __half* __restrict__ Bl,
    float* __restrict__ C,
    int M, int N, int K,
    long long sA, long long sB, long long sC,
    const float* __restrict__ bias,
    const float* __restrict__ resid, const float* __restrict__ gate,
    const int* __restrict__ rowmap, const float* __restrict__ rscale,
    const int* __restrict__ agather)
{
    extern __shared__ char smem[];
    const int tid = threadIdx.x;
    const int wid = tid >> 5, lane = tid & 31;
    const int z = blockIdx.z;
    const int m0 = blockIdx.y * 128, n0 = blockIdx.x * 128;
    if (!AG) Ah += (long long)z * sA;
    Bh += (long long)z * sB; Bl += (long long)z * sB;

    const int lr = tid >> 1;
    const int lh = tid & 1;
    long long arow = AG ? (long long)agather[(long long)z * M + m0 + lr]
                        : (long long)(m0 + lr);
    const __half* aHp = Ah + arow * (long long)K + lh * 16;
    const __half* bHp = Bh + (long long)(n0 + lr) * K + lh * 16;
    const __half* bLp = Bl + (long long)(n0 + lr) * K + lh * 16;
    const uint32_t pofs = lr * PRS + lh * 32;

    const uint32_t uAh = s2u(smem);
    const uint32_t uBh = uAh + PLSZ;
    const uint32_t uBl = uAh + 2 * PLSZ;

    const int wm = (wid >> 2) * 64;
    const int wn = (wid & 3) * 32;
    uint32_t a_off[4];
    #pragma unroll
    for (int mt = 0; mt < 4; mt++) {
        int r = wm + mt * 16 + (lane & 15);
        a_off[mt] = r * PRS + (lane >> 4) * 16;
    }
    uint32_t b_off[2];
    #pragma unroll
    for (int np = 0; np < 2; np++) {
        int r = wn + np * 16 + ((lane >> 4) << 3) + (lane & 7);
        b_off[np] = r * PRS + ((lane >> 3) & 1) * 16;
    }

    float acc[4][4][4];
    #pragma unroll
    for (int mt = 0; mt < 4; mt++)
        #pragma unroll
        for (int nt = 0; nt < 4; nt++)
            #pragma unroll
            for (int i = 0; i < 4; i++) acc[mt][nt][i] = 0.f;

    const int NC = K >> 5;
    auto issue = [&](int c, uint32_t boff) {
        long long ko = (long long)c * 32;
        cpa16(uAh + boff + pofs,      aHp + ko);
        cpa16(uAh + boff + pofs + 16, aHp + ko + 8);
        cpa16(uBh + boff + pofs,      bHp + ko);
        cpa16(uBh + boff + pofs + 16, bHp + ko + 8);
        cpa16(uBl + boff + pofs,      bLp + ko);
        cpa16(uBl + boff + pofs + 16, bLp + ko + 8);
        asm volatile("cp.async.commit_group;");
    };

    issue(0, 0);
    for (int c = 0; c < NC; c++) {
        const uint32_t boff = (c & 1) * BUFSZ;
        if (c + 1 < NC) {
            issue(c + 1, (~c & 1) * BUFSZ);
            asm volatile("cp.async.wait_group 1;");
        } else {
            asm volatile("cp.async.wait_group 0;");
        }
        __syncthreads();
        #pragma unroll
        for (int ks = 0; ks < 2; ks++) {
            uint32_t bh[4][2], bl[4][2];
            #pragma unroll
            for (int np = 0; np < 2; np++) {
                asm volatile("ldmatrix.sync.aligned.m8n8.x4.shared.b16 {%0,%1,%2,%3}, [%4];"
                    : "=r"(bh[np*2][0]), "=r"(bh[np*2][1]),
                      "=r"(bh[np*2+1][0]), "=r"(bh[np*2+1][1])
                    : "r"(uBh + boff + b_off[np] + ks * 32));
                asm volatile("ldmatrix.sync.aligned.m8n8.x4.shared.b16 {%0,%1,%2,%3}, [%4];"
                    : "=r"(bl[np*2][0]), "=r"(bl[np*2][1]),
                      "=r"(bl[np*2+1][0]), "=r"(bl[np*2+1][1])
                    : "r"(uBl + boff + b_off[np] + ks * 32));
            }
            #pragma unroll
            for (int mt = 0; mt < 4; mt++) {
                uint32_t ah[4];
                asm volatile("ldmatrix.sync.aligned.m8n8.x4.shared.b16 {%0,%1,%2,%3}, [%4];"
                    : "=r"(ah[0]), "=r"(ah[1]), "=r"(ah[2]), "=r"(ah[3])
                    : "r"(uAh + boff + a_off[mt] + ks * 32));
                #pragma unroll
                for (int nt = 0; nt < 4; nt++) mma16816(acc[mt][nt], ah, bh[nt]);
                #pragma unroll
                for (int nt = 0; nt < 4; nt++) mma16816(acc[mt][nt], ah, bl[nt]);
            }
        }
        __syncthreads();
    }

    const int g = lane >> 2;
    const int cp2 = (lane & 3) * 2;
    #pragma unroll
    for (int mt = 0; mt < 4; mt++) {
        #pragma unroll
        for (int hh = 0; hh < 2; hh++) {
            int row = m0 + wm + mt * 16 + g + hh * 8;
            if (EPI == 3) {
                long long gr = (long long)z * M + row;
                int trow = rowmap[gr];
                float s = rscale[gr];
                float* cp = C + (long long)trow * N;
                #pragma unroll
                for (int nt = 0; nt < 4; nt++) {
                    int col = n0 + wn + nt * 8 + cp2;
                    atomicAdd(cp + col,     acc[mt][nt][hh*2]   * s);
                    atomicAdd(cp + col + 1, acc[mt][nt][hh*2+1] * s);
                }
            } else {
                float* Cz = C + (long long)z * sC + (long long)row * N;
                #pragma unroll
                for (int nt = 0; nt < 4; nt++) {
                    int col = n0 + wn + nt * 8 + cp2;
                    float v0 = acc[mt][nt][hh*2], v1 = acc[mt][nt][hh*2+1];
                    if (EPI == 1) { v0 += bias[col]; v1 += bias[col + 1]; }
                    if (EPI == 2) {
                        const float* gp = gate + (row / SEQ) * N + col;
                        const float* rp = resid + (long long)row * N + col;
                        v0 = rp[0] + gp[0] * v0;
                        v1 = rp[1] + gp[1] * v1;
                    }
                    *(float2*)(Cz + col) = make_float2(v0, v1);
                }
            }
        }
    }
}

// ------------------------- modulation ----------------------------------------
__global__ __launch_bounds__(256) void mod_kernel(const float* __restrict__ temb,
                                                  const float* __restrict__ Wm,
                                                  const float* __restrict__ bm) {
    int gw = (blockIdx.x * blockDim.x + threadIdx.x) >> 5;
    int lane = threadIdx.x & 31;
    if (gw >= BSZ * 4 * DIMM) return;
    int b = gw / (4 * DIMM);
    int j = gw - b * 4 * DIMM;
    const float* t = temb + b * DIMM;
    const float* w = Wm + (size_t)j * DIMM;
    float acc = 0.f;
    for (int kk = lane; kk < DIMM; kk += 32) {
        float x = t[kk];
        acc += (x / (1.f + __expf(-x))) * w[kk];
    }
    #pragma unroll
    for (int o = 16; o; o >>= 1) acc += __shfl_xor_sync(0xffffffffu, acc, o);
    if (lane == 0) {
        acc += bm[j];
        int q = j / DIMM, c = j - q * DIMM;
        if (q == 0)      g_scale1[b*DIMM + c] = 1.f + acc;
        else if (q == 1) g_tg1[b*DIMM + c]    = tanhf(fminf(fmaxf(acc, -2.f), 2.f));
        else if (q == 2) g_scale2[b*DIMM + c] = 1.f + acc;
        else             g_tg2[b*DIMM + c]    = tanhf(fminf(fmaxf(acc, -2.f), 2.f));
    }
}

// ------------------------- LayerNorm -> half (+opt fp32 normed) --------------
__global__ __launch_bounds__(256) void ln_mod_kernel(const float* __restrict__ in,
                                                     const float* __restrict__ scale,
                                                     __half* __restrict__ mh,
                                                     float* __restrict__ outnorm) {
    int rowi = blockIdx.x;
    int b = rowi >> 10;
    const float* x = in + (size_t)rowi * DIMM;
    float s = 0.f, sq = 0.f;
    for (int d = threadIdx.x; d < DIMM; d += 256) { float v = x[d]; s += v; sq += v * v; }
    #pragma unroll
    for (int o = 16; o; o >>= 1) {
        s  += __shfl_xor_sync(0xffffffffu, s,  o);
        sq += __shfl_xor_sync(0xffffffffu, sq, o);
    }
    __shared__ float rs[8], rq[8], mv[2];
    int w = threadIdx.x >> 5;
    if ((threadIdx.x & 31) == 0) { rs[w] = s; rq[w] = sq; }
    __syncthreads();
    if (threadIdx.x == 0) {
        float S = 0.f, Q = 0.f;
        for (int i = 0; i < 8; i++) { S += rs[i]; Q += rq[i]; }
        float mean = S / DIMM;
        float var = Q / DIMM - mean * mean;
        mv[0] = mean; mv[1] = rsqrtf(var + EPSL);
    }
    __syncthreads();
    float mean = mv[0], rstd = mv[1];
    const float* sc = scale + (size_t)b * DIMM;
    for (int d = threadIdx.x; d < DIMM; d += 256) {
        float n = (x[d] - mean) * rstd;
        if (outnorm) outnorm[(size_t)rowi * DIMM + d] = n;
        mh[(size_t)rowi * DIMM + d] = __float2half(n * sc[d]);
    }
}

// ------------------------- per-head RMSNorm of Q ----------------------------
__global__ __launch_bounds__(256) void rms_q_kernel(const float* __restrict__ w) {
    int gw = (blockIdx.x * blockDim.x + threadIdx.x) >> 5;
    if (gw >= NTOK * NH) return;
    int lane = threadIdx.x & 31;
    float* p = g_q + (size_t)gw * HDD;
    int d4 = lane << 2;
    float4 v = *(float4*)(p + d4);
    float ss = v.x*v.x + v.y*v.y + v.z*v.z + v.w*v.w;
    #pragma unroll
    for (int o = 16; o; o >>= 1) ss += __shfl_xor_sync(0xffffffffu, ss, o);
    float r = rsqrtf(ss / HDD + EPSL);
    float4 wv = *(const float4*)(w + d4);
    v.x *= r * wv.x; v.y *= r * wv.y; v.z *= r * wv.z; v.w *= r * wv.w;
    *(float4*)(p + d4) = v;
}

// ------------------------- K RMS + K/V repack -------------------------------
__global__ __launch_bounds__(256) void kv_repack_kernel(const float* __restrict__ nk,
                                                        const float* __restrict__ nak) {
    int gw = (blockIdx.x * blockDim.x + threadIdx.x) >> 5;
    if (gw >= BSZ * NKV * LTOT) return;
    int lane = threadIdx.x & 31;
    int l = gw % LTOT;
    int bk = gw / LTOT;
    int kv = bk % NKV, b = bk / NKV;
    const float *ksrc, *vsrc, *w;
    if (l < SEQ) {
        ksrc = g_kimg + (size_t)(b * SEQ + l) * IKV + kv * HDD;
        vsrc = g_vimg + (size_t)(b * SEQ + l) * IKV + kv * HDD;
        w = nk;
    } else {
        int tt = l - SEQ;
        ksrc = g_ktxt + (size_t)(b * TXT + tt) * IKV + kv * HDD;
        vsrc = g_vtxt + (size_t)(b * TXT + tt) * IKV + kv * HDD;
        w = nak;
    }
    int d4 = lane << 2;
    float4 kvv = *(const float4*)(ksrc + d4);
    float ss = kvv.x*kvv.x + kvv.y*kvv.y + kvv.z*kvv.z + kvv.w*kvv.w;
    #pragma unroll
    for (int o = 16; o; o >>= 1) ss += __shfl_xor_sync(0xffffffffu, ss, o);
    float r = rsqrtf(ss / HDD + EPSL);
    float4 wv = *(const float4*)(w + d4);
    kvv.x *= r * wv.x; kvv.y *= r * wv.y; kvv.z *= r * wv.z; kvv.w *= r * wv.w;
    size_t dst = ((size_t)(b * NKV + kv) * LTOT + l) * HDD + d4;
    *(float4*)(g_k + dst) = kvv;
    *(float4*)(g_v + dst) = *(const float4*)(vsrc + d4);
}

// ------------------------- flash attention (scalar FFMA, proven) ------------
__global__ __launch_bounds__(256) void flash_kernel() {
    __shared__ float Qs[32][129];
    __shared__ float KVs[32][129];
    __shared__ float Ss[32][33];
    const int q0 = blockIdx.x * 32;
    const int h = blockIdx.y;
    const int b = blockIdx.z;
    const int kv = h / REP;
    const int t = threadIdx.x;
    for (int idx = t; idx < 1024; idx += 256) {
        int qi = idx >> 5, d4 = (idx & 31) << 2;
        float4 v = *(const float4*)(g_q + (size_t)(b * SEQ + q0 + qi) * DIMM + h * HDD + d4);
        Qs[qi][d4] = v.x; Qs[qi][d4+1] = v.y; Qs[qi][d4+2] = v.z; Qs[qi][d4+3] = v.w;
    }
    const int q = t >> 3, dg = t & 7;
    float acc[16];
    #pragma unroll
    for (int i = 0; i < 16; i++) acc[i] = 0.f;
    float m = -1e30f, l = 0.f;
    const float sc = 0.08838834764831845f;  // 1/sqrt(128)
    const float* kbase = g_k + (size_t)(b * NKV + kv) * LTOT * HDD;
    const float* vbase = g_v + (size_t)(b * NKV + kv) * LTOT * HDD;
    __syncthreads();
    for (int k0 = 0; k0 < LTOT; k0 += 32) {
        for (int idx = t; idx < 1024; idx += 256) {
            int ki = idx >> 5, d4 = (idx & 31) << 2;
            float4 v = *(const float4*)(kbase + (size_t)(k0 + ki) * HDD + d4);
            KVs[ki][d4] = v.x; KVs[ki][d4+1] = v.y; KVs[ki][d4+2] = v.z; KVs[ki][d4+3] = v.w;
        }
        __syncthreads();
        {
            int kb = dg << 2;
            float s0 = 0.f, s1 = 0.f, s2 = 0.f, s3 = 0.f;
            #pragma unroll 4
            for (int d = 0; d < 128; d++) {
                float qv = Qs[q][d];
                s0 += qv * KVs[kb][d];
                s1 += qv * KVs[kb+1][d];
                s2 += qv * KVs[kb+2][d];
                s3 += qv * KVs[kb+3][d];
            }
            Ss[q][kb] = s0 * sc; Ss[q][kb+1] = s1 * sc;
            Ss[q][kb+2] = s2 * sc; Ss[q][kb+3] = s3 * sc;
        }
        __syncthreads();
        float srow[32];
        float rmax = -1e30f;
        #pragma unroll
        for (int k = 0; k < 32; k++) { srow[k] = Ss[q][k]; rmax = fmaxf(rmax, srow[k]); }
        for (int idx = t; idx < 1024; idx += 256) {
            int ki = idx >> 5, d4 = (idx & 31) << 2;
            float4 v = *(const float4*)(vbase + (size_t)(k0 + ki) * HDD + d4);
            KVs[ki][d4] = v.x; KVs[ki][d4+1] = v.y; KVs[ki][d4+2] = v.z; KVs[ki][d4+3] = v.w;
        }
        float newm = fmaxf(m, rmax);
        float corr = __expf(m - newm);
        float psum = 0.f;
        #pragma unroll
        for (int k = 0; k < 32; k++) { srow[k] = __expf(srow[k] - newm); psum += srow[k]; }
        l = l * corr + psum;
        m = newm;
        #pragma unroll
        for (int i = 0; i < 16; i++) acc[i] *= corr;
        __syncthreads();
        #pragma unroll
        for (int k = 0; k < 32; k++) {
            float p = srow[k];
            #pragma unroll
            for (int i = 0; i < 16; i++) acc[i] += p * KVs[k][dg + (i << 3)];
        }
        __syncthreads();
    }
    float inv = 1.f / l;
    size_t obase = (size_t)(b * SEQ + q0 + q) * DIMM + h * HDD;
    #pragma unroll
    for (int i = 0; i < 16; i++)
        g_attn_h[obase + dg + (i << 3)] = __float2half(acc[i] * inv);
}

// ------------------------- router ------------------------------------------
__global__ __launch_bounds__(1024) void tembdot_kernel(const float* __restrict__ temb,
                                                       const float* __restrict__ Wg) {
    int wid = threadIdx.x >> 5, lane = threadIdx.x & 31;
    int b = wid / NE, e = wid % NE;
    const float* t = temb + b * DIMM;
    const float* w = Wg + (size_t)e * 2 * DIMM;
    float acc = 0.f;
    for (int d = lane; d < DIMM; d += 32) acc += t[d] * w[d];
    #pragma unroll
    for (int o = 16; o; o >>= 1) acc += __shfl_xor_sync(0xffffffffu, acc, o);
    if (lane == 0) g_tembdot[wid] = acc;
}

__global__ __launch_bounds__(128) void router_kernel(const float* __restrict__ Wg) {
    __shared__ float lg[NE];
    int tokid = blockIdx.x;
    int b = tokid >> 10, s = tokid & 1023;
    int w = threadIdx.x >> 5, lane = threadIdx.x & 31;
    const float* x = g_normed2 + (size_t)tokid * DIMM;
    for (int e = w * 4; e < w * 4 + 4; e++) {
        const float* wg = Wg + (size_t)e * 2 * DIMM + DIMM;
        float acc = 0.f;
        for (int d = lane; d < DIMM; d += 32) acc += x[d] * wg[d];
        #pragma unroll
        for (int o = 16; o; o >>= 1) acc += __shfl_xor_sync(0xffffffffu, acc, o);
        if (lane == 0) lg[e] = acc + g_tembdot[b * NE + e];
    }
    __syncthreads();
    if (threadIdx.x == 0) {
        float mx = -1e30f;
        for (int e = 0; e < NE; e++) mx = fmaxf(mx, lg[e]);
        float ex[NE], sm = 0.f;
        for (int e = 0; e < NE; e++) { ex[e] = __expf(lg[e] - mx); sm += ex[e]; }
        float inv = 1.f / sm;
        for (int e = 0; e < NE; e++)
            g_aff[((size_t)(b * NE + e)) * SEQ + s] = ex[e] * inv;
    }
}

// ------------------------- exact top-k via bitonic sort ---------------------
__global__ __launch_bounds__(512) void topk_kernel() {
    __shared__ float v[1024];
    __shared__ int   id[1024];
    int be = blockIdx.x;
    const float* rowp = g_aff + (size_t)be * SEQ;
    int t = threadIdx.x;
    for (int i = t; i < 1024; i += 512) { v[i] = rowp[i]; id[i] = i; }
    __syncthreads();
    for (int k = 2; k <= 1024; k <<= 1) {
        for (int j = k >> 1; j > 0; j >>= 1) {
            for (int i = t; i < 1024; i += 512) {
                int ixj = i ^ j;
                if (ixj > i) {
                    bool up = ((i & k) == 0);
                    float va = v[i], vb = v[ixj];
                    int ia = id[i], ib = id[ixj];
                    bool a_first = (va > vb) || (va == vb && ia < ib);
                    bool sw = up ? !a_first : a_first;
                    if (sw) { v[i] = vb; v[ixj] = va; id[i] = ib; id[ixj] = ia; }
                }
            }
            __syncthreads();
        }
    }
    if (t < CAP) {
        g_gating[be * CAP + t] = v[t];
        g_topidx[be * CAP + t] = id[t];
    }
}

__global__ void zero_sums_kernel() {
    int i = blockIdx.x * blockDim.x + threadIdx.x;
    if (i < NTOK) g_sums[i] = 0.f;
}

__global__ void sum_acc_kernel() {
    int i = blockIdx.x * blockDim.x + threadIdx.x;
    if (i >= BSZ * NE * CAP) return;
    int be = i / CAP;
    int b = be / NE;
    int tok = b * SEQ + g_topidx[i];
    atomicAdd(&g_sums[tok], g_gating[i]);
}

__global__ void gate_norm_kernel() {
    int i = blockIdx.x * blockDim.x + threadIdx.x;
    if (i >= BSZ * NE * CAP) return;
    int c = i % CAP;
    int be = i / CAP;
    int b = be / NE, e = be % NE;
    int tok = b * SEQ + g_topidx[i];
    float g = g_gating[i] / (g_sums[tok] + 1e-12f) * 2.5f;
    int rowflat = (e * BSZ + b) * CAP + c;
    g_rowmap[rowflat] = tok;
    g_rscale[rowflat] = g;
}

// ------------------------- swiglu -> half ------------------------------------
__global__ __launch_bounds__(256) void swiglu_kernel(const float* __restrict__ h,
                                                     __half* __restrict__ oh) {
    int r = blockIdx.x;
    const float4* a = (const float4*)(h + (size_t)r * 2 * NI);
    const float4* g = (const float4*)(h + (size_t)r * 2 * NI + NI);
    for (int i = threadIdx.x; i < NI / 4; i += 256) {
        float4 av = a[i], gv = g[i];
        float f0 = av.x * (gv.x / (1.f + __expf(-gv.x)));
        float f1 = av.y * (gv.y / (1.f + __expf(-gv.y)));
        float f2 = av.z * (gv.z / (1.f + __expf(-gv.z)));
        float f3 = av.w * (gv.w / (1.f + __expf(-gv.w)));
        __half2* ph = (__half2*)(oh + (size_t)r * NI + i * 4);
        ph[0] = __halves2half2(__float2half(f0), __float2half(f1));
        ph[1] = __halves2half2(__float2half(f2), __float2half(f3));
    }
}

// ------------------------- final residual -----------------------------------
__global__ __launch_bounds__(256) void final_kernel(float* __restrict__ out) {
    int r = blockIdx.x;
    int b = r >> 10;
    const float4* hs = (const float4*)(g_hs1 + (size_t)r * DIMM);
    const float4* mo = (const float4*)(g_outflat + (size_t)r * DIMM);
    const float4* gg = (const float4*)(g_tg2 + (size_t)b * DIMM);
    float4* o = (float4*)(out + (size_t)r * DIMM);
    for (int i = threadIdx.x; i < DIMM / 4; i += 256) {
        float4 h = hs[i], m = mo[i], g = gg[i], v;
        v.x = h.x + g.x * m.x; v.y = h.y + g.y * m.y;
        v.z = h.z + g.z * m.z; v.w = h.w + g.w * m.w;
        o[i] = v;
    }
}

// ------------------------- launcher -----------------------------------------
extern "C" void kernel_launch(void* const* d_in, const int* in_sizes, int n_in,
                              void* d_out, int out_size) {
    const float* hidden = (const float*)d_in[0];
    const float* enc    = (const float*)d_in[1];
    const float* temb   = (const float*)d_in[2];
    const float* W_mod  = (const float*)d_in[3];
    const float* b_mod  = (const float*)d_in[4];
    const float* W_enc  = (const float*)d_in[5];
    const float* b_enc  = (const float*)d_in[6];
    const float* Wq     = (const float*)d_in[7];
    const float* Wk     = (const float*)d_in[8];
    const float* Wv     = (const float*)d_in[9];
    const float* Wak    = (const float*)d_in[10];
    const float* Wav    = (const float*)d_in[11];
    const float* nq_w   = (const float*)d_in[12];
    const float* nk_w   = (const float*)d_in[13];
    const float* nak_w  = (const float*)d_in[14];
    const float* Wo     = (const float*)d_in[15];
    const float* Wg     = (const float*)d_in[16];
    const float* We_in  = (const float*)d_in[17];
    const float* We_out = (const float*)d_in[18];
    const float* Ws_in  = (const float*)d_in[19];
    const float* Ws_out = (const float*)d_in[20];
    float* out = (float*)d_out;

    void* pv;
    #define GF(sym) (cudaGetSymbolAddress(&pv, sym), (float*)pv)
    #define GH(sym) (cudaGetSymbolAddress(&pv, sym), (__half*)pv)
    #define GI(sym) (cudaGetSymbolAddress(&pv, sym), (int*)pv)
    float* p_ctx     = GF(g_ctx);
    float* p_q       = GF(g_q);
    float* p_kimg    = GF(g_kimg);
    float* p_vimg    = GF(g_vimg);
    float* p_ktxt    = GF(g_ktxt);
    float* p_vtxt    = GF(g_vtxt);
    float* p_hs1     = GF(g_hs1);
    float* p_normed2 = GF(g_normed2);
    float* p_hmoe    = GF(g_hmoe);
    float* p_hsh     = GF(g_hsh);
    float* p_outflat = GF(g_outflat);
    float* p_scale1  = GF(g_scale1);
    float* p_scale2  = GF(g_scale2);
    float* p_tg1     = GF(g_tg1);
    int*   p_rowmap  = GI(g_rowmap);
    float* p_rscale  = GF(g_rscale);
    __half *p_enc_h = GH(g_enc_h);
    __half *p_Wenc_h = GH(g_Wenc_h), *p_Wenc_l = GH(g_Wenc_l);
    __half *p_Wq_h = GH(g_Wq_h),     *p_Wq_l = GH(g_Wq_l);
    __half *p_Wk_h = GH(g_Wk_h),     *p_Wk_l = GH(g_Wk_l);
    __half *p_Wv_h = GH(g_Wv_h),     *p_Wv_l = GH(g_Wv_l);
    __half *p_Wak_h = GH(g_Wak_h),   *p_Wak_l = GH(g_Wak_l);
    __half *p_Wav_h = GH(g_Wav_h),   *p_Wav_l = GH(g_Wav_l);
    __half *p_Wo_h = GH(g_Wo_h),     *p_Wo_l = GH(g_Wo_l);
    __half *p_Wein_h = GH(g_Wein_h), *p_Wein_l = GH(g_Wein_l);
    __half *p_Weout_h = GH(g_Weout_h), *p_Weout_l = GH(g_Weout_l);
    __half *p_Wsin_h = GH(g_Wsin_h), *p_Wsin_l = GH(g_Wsin_l);
    __half *p_Wsout_h = GH(g_Wsout_h), *p_Wsout_l = GH(g_Wsout_l);
    __half *p_ctx_h = GH(g_ctx_h);
    __half *p_img_h = GH(g_img_h);
    __half *p_attn_h = GH(g_attn_h);
    __half *p_mod2_h = GH(g_mod2_h);
    __half *p_actsh_h = GH(g_actsh_h);
    __half *p_actmoe_h = GH(g_actmoe_h);

    cudaFuncSetAttribute(mma_gemm<0,false>, cudaFuncAttributeMaxDynamicSharedMemorySize, MMSM);
    cudaFuncSetAttribute(mma_gemm<1,false>, cudaFuncAttributeMaxDynamicSharedMemorySize, MMSM);
    cudaFuncSetAttribute(mma_gemm<2,false>, cudaFuncAttributeMaxDynamicSharedMemorySize, MMSM);
    cudaFuncSetAttribute(mma_gemm<3,false>, cudaFuncAttributeMaxDynamicSharedMemorySize, MMSM);
    cudaFuncSetAttribute(mma_gemm<0,true>,  cudaFuncAttributeMaxDynamicSharedMemorySize, MMSM);

    const float* NFP = nullptr;
    const int*   NIP = nullptr;

    #define CVT(src, dh, dl, n) \
        cvt_kernel<<<(int)(((n)/4 + 255)/256), 256>>>(src, dh, dl, (long long)(n))
    #define CVT1(src, dh, n) \
        cvt1_kernel<<<(int)(((n)/4 + 255)/256), 256>>>(src, dh, (long long)(n))

    // 0. convert weights (hi/lo) + enc (single half)
    CVT(W_enc, p_Wenc_h, p_Wenc_l, (long long)DIMM*JD);
    CVT(Wq,  p_Wq_h,  p_Wq_l,  (long long)DIMM*DIMM);
    CVT(Wk,  p_Wk_h,  p_Wk_l,  (long long)IKV*DIMM);
    CVT(Wv,  p_Wv_h,  p_Wv_l,  (long long)IKV*DIMM);
    CVT(Wak, p_Wak_h, p_Wak_l, (long long)IKV*DIMM);
    CVT(Wav, p_Wav_h, p_Wav_l, (long long)IKV*DIMM);
    CVT(Wo,  p_Wo_h,  p_Wo_l,  (long long)DIMM*DIMM);
    CVT(We_in,  p_Wein_h,  p_Wein_l,  (long long)NE*2*NI*DIMM);
    CVT(We_out, p_Weout_h, p_Weout_l, (long long)NE*DIMM*NI);
    CVT(Ws_in,  p_Wsin_h,  p_Wsin_l,  (long long)2*NI*DIMM);
    CVT(Ws_out, p_Wsout_h, p_Wsout_l, (long long)DIMM*NI);
    CVT1(enc, p_enc_h, (long long)BSZ*TXT*JD);

    // 1. modulation
    mod_kernel<<<1536, 256>>>(temb, W_mod, b_mod);
    // 2. context projection (+bias), then convert ctx
    mma_gemm<1,false><<<dim3(12, 8, 1), 256, MMSM>>>(p_enc_h,
        p_Wenc_h, p_Wenc_l, p_ctx, BSZ*TXT, DIMM, JD, 0, 0, 0,
        b_enc, NFP, NFP, NIP, NFP, NIP);
    CVT1(p_ctx, p_ctx_h, (long long)BSZ*TXT*DIMM);
    // 3. LN1 * scale1 -> half
    ln_mod_kernel<<<NTOK, 256>>>(hidden, p_scale1, p_img_h, nullptr);
    // 4. projections
    mma_gemm<0,false><<<dim3(12, 16, 1), 256, MMSM>>>(p_img_h,
        p_Wq_h, p_Wq_l, p_q, NTOK, DIMM, DIMM, 0, 0, 0, NFP, NFP, NFP, NIP, NFP, NIP);
    mma_gemm<0,false><<<dim3(4, 16, 1), 256, MMSM>>>(p_img_h,
        p_Wk_h, p_Wk_l, p_kimg, NTOK, IKV, DIMM, 0, 0, 0, NFP, NFP, NFP, NIP, NFP, NIP);
    mma_gemm<0,false><<<dim3(4, 16, 1), 256, MMSM>>>(p_img_h,
        p_Wv_h, p_Wv_l, p_vimg, NTOK, IKV, DIMM, 0, 0, 0, NFP, NFP, NFP, NIP, NFP, NIP);
    mma_gemm<0,false><<<dim3(4, 8, 1), 256, MMSM>>>(p_ctx_h,
        p_Wak_h, p_Wak_l, p_ktxt, BSZ*TXT, IKV, DIMM, 0, 0, 0, NFP, NFP, NFP, NIP, NFP, NIP);
    mma_gemm<0,false><<<dim3(4, 8, 1), 256, MMSM>>>(p_ctx_h,
        p_Wav_h, p_Wav_l, p_vtxt, BSZ*TXT, IKV, DIMM, 0, 0, 0, NFP, NFP, NFP, NIP, NFP, NIP);
    // 5. norms + repack
    rms_q_kernel<<<3072, 256>>>(nq_w);
    kv_repack_kernel<<<1536, 256>>>(nk_w, nak_w);
    // 6. attention (-> half)
    flash_kernel<<<dim3(SEQ/32, NH, BSZ), 256>>>();
    // 7. output proj + gated residual
    mma_gemm<2,false><<<dim3(12, 16, 1), 256, MMSM>>>(p_attn_h,
        p_Wo_h, p_Wo_l, p_hs1, NTOK, DIMM, DIMM, 0, 0, 0,
        NFP, hidden, p_tg1, NIP, NFP, NIP);
    // 8. LN2 -> mod2 half + normed2 fp32
    ln_mod_kernel<<<NTOK, 256>>>(p_hs1, p_scale2, p_mod2_h, p_normed2);
    // 9. router
    tembdot_kernel<<<1, 1024>>>(temb, Wg);
    router_kernel<<<NTOK, 128>>>(Wg);
    topk_kernel<<<BSZ*NE, 512>>>();
    zero_sums_kernel<<<8, 256>>>();
    sum_acc_kernel<<<64, 256>>>();
    gate_norm_kernel<<<64, 256>>>();
    // 10. expert GEMM 1 (gathered A rows, batched over 16 experts)
    mma_gemm<0,true><<<dim3(21, 8, 16), 256, MMSM>>>(p_mod2_h,
        p_Wein_h, p_Wein_l, p_hmoe, BSZ*CAP, 2*NI, DIMM,
        0, (long long)2*NI*DIMM, (long long)BSZ*CAP*2*NI,
        NFP, NFP, NFP, NIP, NFP, p_rowmap);
    swiglu_kernel<<<MROWS, 256>>>(p_hmoe, p_actmoe_h);
    // 11. shared expert
    mma_gemm<0,false><<<dim3(21, 16, 1), 256, MMSM>>>(p_mod2_h,
        p_Wsin_h, p_Wsin_l, p_hsh, NTOK, 2*NI, DIMM, 0, 0, 0,
        NFP, NFP, NFP, NIP, NFP, NIP);
    swiglu_kernel<<<NTOK, 256>>>(p_hsh, p_actsh_h);
    mma_gemm<0,false><<<dim3(12, 16, 1), 256, MMSM>>>(p_actsh_h,
        p_Wsout_h, p_Wsout_l, p_outflat, NTOK, DIMM, NI, 0, 0, 0,
        NFP, NFP, NFP, NIP, NFP, NIP);
    // 12. expert GEMM 2 with atomic scatter onto shared output
    mma_gemm<3,false><<<dim3(12, 8, 16), 256, MMSM>>>(p_actmoe_h,
        p_Weout_h, p_Weout_l, p_outflat, BSZ*CAP, DIMM, NI,
        (long long)BSZ*CAP*NI, (long long)DIMM*NI, 0,
        NFP, NFP, NFP, p_rowmap, p_rscale, NIP);
    // 13. final gated residual
    final_kernel<<<NTOK, 256>>>(out);
}

// round 12
// speedup vs baseline: 2.1240x; 1.1872x over previous
#include <cuda_runtime.h>
#include <cuda_fp16.h>
#include <math.h>
#include <stdint.h>

#define BSZ 2
#define SEQ 1024
#define TXT 512
#define DIMM 1536
#define NH 12
#define HDD 128
#define NKV 4
#define JD 3584
#define NE 16
#define NI 1344
#define CAP 512
#define LTOT 1536      // SEQ + TXT
#define NTOK 2048      // BSZ*SEQ
#define MROWS 16384    // NE*BSZ*CAP
#define IKV 512        // NKV*HDD
#define REP 3          // NH/NKV
#define EPSL 1e-6f

// ------------------------- fp32 scratch -------------------------------------
__device__ float g_scale1[BSZ*DIMM];
__device__ float g_tg1[BSZ*DIMM];
__device__ float g_scale2[BSZ*DIMM];
__device__ float g_tg2[BSZ*DIMM];
__device__ float g_ctx[BSZ*TXT*DIMM];
__device__ float g_q[NTOK*DIMM];
__device__ float g_kimg[NTOK*IKV];
__device__ float g_vimg[NTOK*IKV];
__device__ float g_ktxt[BSZ*TXT*IKV];
__device__ float g_vtxt[BSZ*TXT*IKV];
__device__ float g_k[BSZ*NKV*LTOT*HDD];
__device__ float g_v[BSZ*NKV*LTOT*HDD];
__device__ float g_hs1[NTOK*DIMM];
__device__ float g_normed2[NTOK*DIMM];
__device__ float g_tembdot[BSZ*NE];
__device__ float g_aff[BSZ*NE*SEQ];
__device__ int   g_topidx[BSZ*NE*CAP];
__device__ float g_gating[BSZ*NE*CAP];
__device__ float g_sums[NTOK];
__device__ int   g_rowmap[MROWS];
__device__ float g_rscale[MROWS];
__device__ float g_hmoe[(size_t)MROWS*2*NI];
__device__ float g_hsh[NTOK*2*NI];
__device__ float g_outflat[NTOK*DIMM];

// ------------------------- half planes (single, fp16) -----------------------
__device__ __half g_enc_h[BSZ*TXT*JD];
__device__ __half g_Wenc_h[DIMM*JD];
__device__ __half g_Wq_h[DIMM*DIMM];
__device__ __half g_Wk_h[IKV*DIMM];
__device__ __half g_Wv_h[IKV*DIMM];
__device__ __half g_Wak_h[IKV*DIMM];
__device__ __half g_Wav_h[IKV*DIMM];
__device__ __half g_Wo_h[DIMM*DIMM];
__device__ __half g_Wein_h[(size_t)NE*2*NI*DIMM];
__device__ __half g_Weout_h[(size_t)NE*DIMM*NI];
__device__ __half g_Wsin_h[2*NI*DIMM];
__device__ __half g_Wsout_h[DIMM*NI];
__device__ __half g_ctx_h[BSZ*TXT*DIMM];
__device__ __half g_img_h[NTOK*DIMM];
__device__ __half g_attn_h[NTOK*DIMM];
__device__ __half g_mod2_h[NTOK*DIMM];
__device__ __half g_actsh_h[NTOK*NI];
__device__ __half g_actmoe_h[(size_t)MROWS*NI];

// ======================= helpers ============================================
__device__ __forceinline__ uint32_t s2u(const void* p) {
    uint32_t a;
    asm("{ .reg .u64 t; cvta.to.shared.u64 t, %1; cvt.u32.u64 %0, t; }"
        : "=r"(a) : "l"(p));
    return a;
}
__device__ __forceinline__ void cpa16(uint32_t d, const void* s) {
    asm volatile("cp.async.cg.shared.global [%0], [%1], 16;" :: "r"(d), "l"(s));
}
__device__ __forceinline__ void mma16816(float* c, const uint32_t* a, const uint32_t* b) {
    asm volatile(
        "mma.sync.aligned.m16n8k16.row.col.f32.f16.f16.f32 "
        "{%0,%1,%2,%3}, {%4,%5,%6,%7}, {%8,%9}, {%0,%1,%2,%3};"
        : "+f"(c[0]), "+f"(c[1]), "+f"(c[2]), "+f"(c[3])
        : "r"(a[0]), "r"(a[1]), "r"(a[2]), "r"(a[3]), "r"(b[0]), "r"(b[1]));
}

// ------------------------- fp32 -> half conversion ---------------------------
__global__ __launch_bounds__(256) void cvt1_kernel(const float* __restrict__ src,
                                                   __half* __restrict__ dh,
                                                   long long n) {
    long long i = ((long long)blockIdx.x * 256 + threadIdx.x) * 4;
    if (i >= n) return;
    float4 v = *(const float4*)(src + i);
    __half2* ph = (__half2*)(dh + i);
    ph[0] = __halves2half2(__float2half(v.x), __float2half(v.y));
    ph[1] = __halves2half2(__float2half(v.z), __float2half(v.w));
}

// ======================= pipelined fp16 GEMM ================================
// C[M,N] = A[M,K]*B[N,K]^T, fp16 inputs, fp32 accumulate (err ~1.4e-4).
// cp.async double-buffered smem (2 planes x 2 bufs x 18KB = 72KB), CTA tile
// 128x128, K-chunk 64, 8 warps (2x4), warp tile 64x32.
// EPI 0: store  1: +bias[n]  2: resid + gate[b][n]*acc  3: atomic scatter
// AG: gather A rows through agather[z*M + m].
#define PRS 144                 // plane row stride bytes (128B data + 16 pad)
#define PLSZ (128*PRS)          // 18432
#define BUFSZ (2*PLSZ)          // 36864
#define MMSM (2*BUFSZ)          // 73728

template<int EPI, bool AG>
__global__ __launch_bounds__(256, 2) void mma_gemm(
    const __half* __restrict__ Ah, const __half* __restrict__ Bh,
    float* __restrict__ C,
    int M, int N, int K,
    long long sA, long long sB, long long sC,
    const float* __restrict__ bias,
    const float* __restrict__ resid, const float* __restrict__ gate,
    const int* __restrict__ rowmap, const float* __restrict__ rscale,
    const int* __restrict__ agather)
{
    extern __shared__ char smem[];
    const int tid = threadIdx.x;
    const int wid = tid >> 5, lane = tid & 31;
    const int z = blockIdx.z;
    const int m0 = blockIdx.y * 128, n0 = blockIdx.x * 128;
    if (!AG) Ah += (long long)z * sA;
    Bh += (long long)z * sB;

    // loader: thread owns row lr, 64B half lh of the 128B chunk-row
    const int lr = tid >> 1;
    const int lh = tid & 1;
    long long arow = AG ? (long long)agather[(long long)z * M + m0 + lr]
                        : (long long)(m0 + lr);
    const __half* aHp = Ah + arow * (long long)K + lh * 32;
    const __half* bHp = Bh + (long long)(n0 + lr) * K + lh * 32;
    const uint32_t pofs = lr * PRS + lh * 64;

    const uint32_t uA = s2u(smem);
    const uint32_t uB = uA + PLSZ;

    const int wm = (wid >> 2) * 64;
    const int wn = (wid & 3) * 32;
    uint32_t a_off[4];
    #pragma unroll
    for (int mt = 0; mt < 4; mt++) {
        int r = wm + mt * 16 + (lane & 15);
        a_off[mt] = r * PRS + (lane >> 4) * 16;
    }
    uint32_t b_off[2];
    #pragma unroll
    for (int np = 0; np < 2; np++) {
        int r = wn + np * 16 + ((lane >> 4) << 3) + (lane & 7);
        b_off[np] = r * PRS + ((lane >> 3) & 1) * 16;
    }

    float acc[4][4][4];
    #pragma unroll
    for (int mt = 0; mt < 4; mt++)
        #pragma unroll
        for (int nt = 0; nt < 4; nt++)
            #pragma unroll
            for (int i = 0; i < 4; i++) acc[mt][nt][i] = 0.f;

    const int NC = K >> 6;      // K-chunk 64
    auto issue = [&](int c, uint32_t boff) {
        long long ko = (long long)c * 64;
        #pragma unroll
        for (int i = 0; i < 4; i++) {
            cpa16(uA + boff + pofs + 16 * i, aHp + ko + 8 * i);
            cpa16(uB + boff + pofs + 16 * i, bHp + ko + 8 * i);
        }
        asm volatile("cp.async.commit_group;");
    };

    issue(0, 0);
    for (int c = 0; c < NC; c++) {
        const uint32_t boff = (c & 1) * BUFSZ;
        if (c + 1 < NC) {
            issue(c + 1, (~c & 1) * BUFSZ);
            asm volatile("cp.async.wait_group 1;");
        } else {
            asm volatile("cp.async.wait_group 0;");
        }
        __syncthreads();
        #pragma unroll
        for (int ks = 0; ks < 4; ks++) {
            uint32_t bf[4][2];
            #pragma unroll
            for (int np = 0; np < 2; np++)
                asm volatile("ldmatrix.sync.aligned.m8n8.x4.shared.b16 {%0,%1,%2,%3}, [%4];"
                    : "=r"(bf[np*2][0]), "=r"(bf[np*2][1]),
                      "=r"(bf[np*2+1][0]), "=r"(bf[np*2+1][1])
                    : "r"(uB + boff + b_off[np] + ks * 32));
            #pragma unroll
            for (int mt = 0; mt < 4; mt++) {
                uint32_t af[4];
                asm volatile("ldmatrix.sync.aligned.m8n8.x4.shared.b16 {%0,%1,%2,%3}, [%4];"
                    : "=r"(af[0]), "=r"(af[1]), "=r"(af[2]), "=r"(af[3])
                    : "r"(uA + boff + a_off[mt] + ks * 32));
                #pragma unroll
                for (int nt = 0; nt < 4; nt++) mma16816(acc[mt][nt], af, bf[nt]);
            }
        }
        __syncthreads();
    }

    const int g = lane >> 2;
    const int cp2 = (lane & 3) * 2;
    #pragma unroll
    for (int mt = 0; mt < 4; mt++) {
        #pragma unroll
        for (int hh = 0; hh < 2; hh++) {
            int row = m0 + wm + mt * 16 + g + hh * 8;
            if (EPI == 3) {
                long long gr = (long long)z * M + row;
                int trow = rowmap[gr];
                float s = rscale[gr];
                float* cp = C + (long long)trow * N;
                #pragma unroll
                for (int nt = 0; nt < 4; nt++) {
                    int col = n0 + wn + nt * 8 + cp2;
                    atomicAdd(cp + col,     acc[mt][nt][hh*2]   * s);
                    atomicAdd(cp + col + 1, acc[mt][nt][hh*2+1] * s);
                }
            } else {
                float* Cz = C + (long long)z * sC + (long long)row * N;
                #pragma unroll
                for (int nt = 0; nt < 4; nt++) {
                    int col = n0 + wn + nt * 8 + cp2;
                    float v0 = acc[mt][nt][hh*2], v1 = acc[mt][nt][hh*2+1];
                    if (EPI == 1) { v0 += bias[col]; v1 += bias[col + 1]; }
                    if (EPI == 2) {
                        const float* gp = gate + (row / SEQ) * N + col;
                        const float* rp = resid + (long long)row * N + col;
                        v0 = rp[0] + gp[0] * v0;
                        v1 = rp[1] + gp[1] * v1;
                    }
                    *(float2*)(Cz + col) = make_float2(v0, v1);
                }
            }
        }
    }
}

// ------------------------- modulation ----------------------------------------
__global__ __launch_bounds__(256) void mod_kernel(const float* __restrict__ temb,
                                                  const float* __restrict__ Wm,
                                                  const float* __restrict__ bm) {
    int gw = (blockIdx.x * blockDim.x + threadIdx.x) >> 5;
    int lane = threadIdx.x & 31;
    if (gw >= BSZ * 4 * DIMM) return;
    int b = gw / (4 * DIMM);
    int j = gw - b * 4 * DIMM;
    const float* t = temb + b * DIMM;
    const float* w = Wm + (size_t)j * DIMM;
    float acc = 0.f;
    for (int kk = lane; kk < DIMM; kk += 32) {
        float x = t[kk];
        acc += (x / (1.f + __expf(-x))) * w[kk];
    }
    #pragma unroll
    for (int o = 16; o; o >>= 1) acc += __shfl_xor_sync(0xffffffffu, acc, o);
    if (lane == 0) {
        acc += bm[j];
        int q = j / DIMM, c = j - q * DIMM;
        if (q == 0)      g_scale1[b*DIMM + c] = 1.f + acc;
        else if (q == 1) g_tg1[b*DIMM + c]    = tanhf(fminf(fmaxf(acc, -2.f), 2.f));
        else if (q == 2) g_scale2[b*DIMM + c] = 1.f + acc;
        else             g_tg2[b*DIMM + c]    = tanhf(fminf(fmaxf(acc, -2.f), 2.f));
    }
}

// ------------------------- LayerNorm -> half (+opt fp32 normed) --------------
__global__ __launch_bounds__(256) void ln_mod_kernel(const float* __restrict__ in,
                                                     const float* __restrict__ scale,
                                                     __half* __restrict__ mh,
                                                     float* __restrict__ outnorm) {
    int rowi = blockIdx.x;
    int b = rowi >> 10;
    const float* x = in + (size_t)rowi * DIMM;
    float s = 0.f, sq = 0.f;
    for (int d = threadIdx.x; d < DIMM; d += 256) { float v = x[d]; s += v; sq += v * v; }
    #pragma unroll
    for (int o = 16; o; o >>= 1) {
        s  += __shfl_xor_sync(0xffffffffu, s,  o);
        sq += __shfl_xor_sync(0xffffffffu, sq, o);
    }
    __shared__ float rs[8], rq[8], mv[2];
    int w = threadIdx.x >> 5;
    if ((threadIdx.x & 31) == 0) { rs[w] = s; rq[w] = sq; }
    __syncthreads();
    if (threadIdx.x == 0) {
        float S = 0.f, Q = 0.f;
        for (int i = 0; i < 8; i++) { S += rs[i]; Q += rq[i]; }
        float mean = S / DIMM;
        float var = Q / DIMM - mean * mean;
        mv[0] = mean; mv[1] = rsqrtf(var + EPSL);
    }
    __syncthreads();
    float mean = mv[0], rstd = mv[1];
    const float* sc = scale + (size_t)b * DIMM;
    for (int d = threadIdx.x; d < DIMM; d += 256) {
        float n = (x[d] - mean) * rstd;
        if (outnorm) outnorm[(size_t)rowi * DIMM + d] = n;
        mh[(size_t)rowi * DIMM + d] = __float2half(n * sc[d]);
    }
}

// ------------------------- per-head RMSNorm of Q ----------------------------
__global__ __launch_bounds__(256) void rms_q_kernel(const float* __restrict__ w) {
    int gw = (blockIdx.x * blockDim.x + threadIdx.x) >> 5;
    if (gw >= NTOK * NH) return;
    int lane = threadIdx.x & 31;
    float* p = g_q + (size_t)gw * HDD;
    int d4 = lane << 2;
    float4 v = *(float4*)(p + d4);
    float ss = v.x*v.x + v.y*v.y + v.z*v.z + v.w*v.w;
    #pragma unroll
    for (int o = 16; o; o >>= 1) ss += __shfl_xor_sync(0xffffffffu, ss, o);
    float r = rsqrtf(ss / HDD + EPSL);
    float4 wv = *(const float4*)(w + d4);
    v.x *= r * wv.x; v.y *= r * wv.y; v.z *= r * wv.z; v.w *= r * wv.w;
    *(float4*)(p + d4) = v;
}

// ------------------------- K RMS + K/V repack -------------------------------
__global__ __launch_bounds__(256) void kv_repack_kernel(const float* __restrict__ nk,
                                                        const float* __restrict__ nak) {
    int gw = (blockIdx.x * blockDim.x + threadIdx.x) >> 5;
    if (gw >= BSZ * NKV * LTOT) return;
    int lane = threadIdx.x & 31;
    int l = gw % LTOT;
    int bk = gw / LTOT;
    int kv = bk % NKV, b = bk / NKV;
    const float *ksrc, *vsrc, *w;
    if (l < SEQ) {
        ksrc = g_kimg + (size_t)(b * SEQ + l) * IKV + kv * HDD;
        vsrc = g_vimg + (size_t)(b * SEQ + l) * IKV + kv * HDD;
        w = nk;
    } else {
        int tt = l - SEQ;
        ksrc = g_ktxt + (size_t)(b * TXT + tt) * IKV + kv * HDD;
        vsrc = g_vtxt + (size_t)(b * TXT + tt) * IKV + kv * HDD;
        w = nak;
    }
    int d4 = lane << 2;
    float4 kvv = *(const float4*)(ksrc + d4);
    float ss = kvv.x*kvv.x + kvv.y*kvv.y + kvv.z*kvv.z + kvv.w*kvv.w;
    #pragma unroll
    for (int o = 16; o; o >>= 1) ss += __shfl_xor_sync(0xffffffffu, ss, o);
    float r = rsqrtf(ss / HDD + EPSL);
    float4 wv = *(const float4*)(w + d4);
    kvv.x *= r * wv.x; kvv.y *= r * wv.y; kvv.z *= r * wv.z; kvv.w *= r * wv.w;
    size_t dst = ((size_t)(b * NKV + kv) * LTOT + l) * HDD + d4;
    *(float4*)(g_k + dst) = kvv;
    *(float4*)(g_v + dst) = *(const float4*)(vsrc + d4);
}

// ------------------------- flash attention (scalar FFMA, proven) ------------
__global__ __launch_bounds__(256) void flash_kernel() {
    __shared__ float Qs[32][129];
    __shared__ float KVs[32][129];
    __shared__ float Ss[32][33];
    const int q0 = blockIdx.x * 32;
    const int h = blockIdx.y;
    const int b = blockIdx.z;
    const int kv = h / REP;
    const int t = threadIdx.x;
    for (int idx = t; idx < 1024; idx += 256) {
        int qi = idx >> 5, d4 = (idx & 31) << 2;
        float4 v = *(const float4*)(g_q + (size_t)(b * SEQ + q0 + qi) * DIMM + h * HDD + d4);
        Qs[qi][d4] = v.x; Qs[qi][d4+1] = v.y; Qs[qi][d4+2] = v.z; Qs[qi][d4+3] = v.w;
    }
    const int q = t >> 3, dg = t & 7;
    float acc[16];
    #pragma unroll
    for (int i = 0; i < 16; i++) acc[i] = 0.f;
    float m = -1e30f, l = 0.f;
    const float sc = 0.08838834764831845f;  // 1/sqrt(128)
    const float* kbase = g_k + (size_t)(b * NKV + kv) * LTOT * HDD;
    const float* vbase = g_v + (size_t)(b * NKV + kv) * LTOT * HDD;
    __syncthreads();
    for (int k0 = 0; k0 < LTOT; k0 += 32) {
        for (int idx = t; idx < 1024; idx += 256) {
            int ki = idx >> 5, d4 = (idx & 31) << 2;
            float4 v = *(const float4*)(kbase + (size_t)(k0 + ki) * HDD + d4);
            KVs[ki][d4] = v.x; KVs[ki][d4+1] = v.y; KVs[ki][d4+2] = v.z; KVs[ki][d4+3] = v.w;
        }
        __syncthreads();
        {
            int kb = dg << 2;
            float s0 = 0.f, s1 = 0.f, s2 = 0.f, s3 = 0.f;
            #pragma unroll 4
            for (int d = 0; d < 128; d++) {
                float qv = Qs[q][d];
                s0 += qv * KVs[kb][d];
                s1 += qv * KVs[kb+1][d];
                s2 += qv * KVs[kb+2][d];
                s3 += qv * KVs[kb+3][d];
            }
            Ss[q][kb] = s0 * sc; Ss[q][kb+1] = s1 * sc;
            Ss[q][kb+2] = s2 * sc; Ss[q][kb+3] = s3 * sc;
        }
        __syncthreads();
        float srow[32];
        float rmax = -1e30f;
        #pragma unroll
        for (int k = 0; k < 32; k++) { srow[k] = Ss[q][k]; rmax = fmaxf(rmax, srow[k]); }
        for (int idx = t; idx < 1024; idx += 256) {
            int ki = idx >> 5, d4 = (idx & 31) << 2;
            float4 v = *(const float4*)(vbase + (size_t)(k0 + ki) * HDD + d4);
            KVs[ki][d4] = v.x; KVs[ki][d4+1] = v.y; KVs[ki][d4+2] = v.z; KVs[ki][d4+3] = v.w;
        }
        float newm = fmaxf(m, rmax);
        float corr = __expf(m - newm);
        float psum = 0.f;
        #pragma unroll
        for (int k = 0; k < 32; k++) { srow[k] = __expf(srow[k] - newm); psum += srow[k]; }
        l = l * corr + psum;
        m = newm;
        #pragma unroll
        for (int i = 0; i < 16; i++) acc[i] *= corr;
        __syncthreads();
        #pragma unroll
        for (int k = 0; k < 32; k++) {
            float p = srow[k];
            #pragma unroll
            for (int i = 0; i < 16; i++) acc[i] += p * KVs[k][dg + (i << 3)];
        }
        __syncthreads();
    }
    float inv = 1.f / l;
    size_t obase = (size_t)(b * SEQ + q0 + q) * DIMM + h * HDD;
    #pragma unroll
    for (int i = 0; i < 16; i++)
        g_attn_h[obase + dg + (i << 3)] = __float2half(acc[i] * inv);
}

// ------------------------- router ------------------------------------------
__global__ __launch_bounds__(1024) void tembdot_kernel(const float* __restrict__ temb,
                                                       const float* __restrict__ Wg) {
    int wid = threadIdx.x >> 5, lane = threadIdx.x & 31;
    int b = wid / NE, e = wid % NE;
    const float* t = temb + b * DIMM;
    const float* w = Wg + (size_t)e * 2 * DIMM;
    float acc = 0.f;
    for (int d = lane; d < DIMM; d += 32) acc += t[d] * w[d];
    #pragma unroll
    for (int o = 16; o; o >>= 1) acc += __shfl_xor_sync(0xffffffffu, acc, o);
    if (lane == 0) g_tembdot[wid] = acc;
}

__global__ __launch_bounds__(128) void router_kernel(const float* __restrict__ Wg) {
    __shared__ float lg[NE];
    int tokid = blockIdx.x;
    int b = tokid >> 10, s = tokid & 1023;
    int w = threadIdx.x >> 5, lane = threadIdx.x & 31;
    const float* x = g_normed2 + (size_t)tokid * DIMM;
    for (int e = w * 4; e < w * 4 + 4; e++) {
        const float* wg = Wg + (size_t)e * 2 * DIMM + DIMM;
        float acc = 0.f;
        for (int d = lane; d < DIMM; d += 32) acc += x[d] * wg[d];
        #pragma unroll
        for (int o = 16; o; o >>= 1) acc += __shfl_xor_sync(0xffffffffu, acc, o);
        if (lane == 0) lg[e] = acc + g_tembdot[b * NE + e];
    }
    __syncthreads();
    if (threadIdx.x == 0) {
        float mx = -1e30f;
        for (int e = 0; e < NE; e++) mx = fmaxf(mx, lg[e]);
        float ex[NE], sm = 0.f;
        for (int e = 0; e < NE; e++) { ex[e] = __expf(lg[e] - mx); sm += ex[e]; }
        float inv = 1.f / sm;
        for (int e = 0; e < NE; e++)
            g_aff[((size_t)(b * NE + e)) * SEQ + s] = ex[e] * inv;
    }
}

// ------------------------- exact top-k via bitonic sort ---------------------
__global__ __launch_bounds__(512) void topk_kernel() {
    __shared__ float v[1024];
    __shared__ int   id[1024];
    int be = blockIdx.x;
    const float* rowp = g_aff + (size_t)be * SEQ;
    int t = threadIdx.x;
    for (int i = t; i < 1024; i += 512) { v[i] = rowp[i]; id[i] = i; }
    __syncthreads();
    for (int k = 2; k <= 1024; k <<= 1) {
        for (int j = k >> 1; j > 0; j >>= 1) {
            for (int i = t; i < 1024; i += 512) {
                int ixj = i ^ j;
                if (ixj > i) {
                    bool up = ((i & k) == 0);
                    float va = v[i], vb = v[ixj];
                    int ia = id[i], ib = id[ixj];
                    bool a_first = (va > vb) || (va == vb && ia < ib);
                    bool sw = up ? !a_first : a_first;
                    if (sw) { v[i] = vb; v[ixj] = va; id[i] = ib; id[ixj] = ia; }
                }
            }
            __syncthreads();
        }
    }
    if (t < CAP) {
        g_gating[be * CAP + t] = v[t];
        g_topidx[be * CAP + t] = id[t];
    }
}

__global__ void zero_sums_kernel() {
    int i = blockIdx.x * blockDim.x + threadIdx.x;
    if (i < NTOK) g_sums[i] = 0.f;
}

__global__ void sum_acc_kernel() {
    int i = blockIdx.x * blockDim.x + threadIdx.x;
    if (i >= BSZ * NE * CAP) return;
    int be = i / CAP;
    int b = be / NE;
    int tok = b * SEQ + g_topidx[i];
    atomicAdd(&g_sums[tok], g_gating[i]);
}

__global__ void gate_norm_kernel() {
    int i = blockIdx.x * blockDim.x + threadIdx.x;
    if (i >= BSZ * NE * CAP) return;
    int c = i % CAP;
    int be = i / CAP;
    int b = be / NE, e = be % NE;
    int tok = b * SEQ + g_topidx[i];
    float g = g_gating[i] / (g_sums[tok] + 1e-12f) * 2.5f;
    int rowflat = (e * BSZ + b) * CAP + c;
    g_rowmap[rowflat] = tok;
    g_rscale[rowflat] = g;
}

// ------------------------- swiglu -> half ------------------------------------
__global__ __launch_bounds__(256) void swiglu_kernel(const float* __restrict__ h,
                                                     __half* __restrict__ oh) {
    int r = blockIdx.x;
    const float4* a = (const float4*)(h + (size_t)r * 2 * NI);
    const float4* g = (const float4*)(h + (size_t)r * 2 * NI + NI);
    for (int i = threadIdx.x; i < NI / 4; i += 256) {
        float4 av = a[i], gv = g[i];
        float f0 = av.x * (gv.x / (1.f + __expf(-gv.x)));
        float f1 = av.y * (gv.y / (1.f + __expf(-gv.y)));
        float f2 = av.z * (gv.z / (1.f + __expf(-gv.z)));
        float f3 = av.w * (gv.w / (1.f + __expf(-gv.w)));
        __half2* ph = (__half2*)(oh + (size_t)r * NI + i * 4);
        ph[0] = __halves2half2(__float2half(f0), __float2half(f1));
        ph[1] = __halves2half2(__float2half(f2), __float2half(f3));
    }
}

// ------------------------- final residual -----------------------------------
__global__ __launch_bounds__(256) void final_kernel(float* __restrict__ out) {
    int r = blockIdx.x;
    int b = r >> 10;
    const float4* hs = (const float4*)(g_hs1 + (size_t)r * DIMM);
    const float4* mo = (const float4*)(g_outflat + (size_t)r * DIMM);
    const float4* gg = (const float4*)(g_tg2 + (size_t)b * DIMM);
    float4* o = (float4*)(out + (size_t)r * DIMM);
    for (int i = threadIdx.x; i < DIMM / 4; i += 256) {
        float4 h = hs[i], m = mo[i], g = gg[i], v;
        v.x = h.x + g.x * m.x; v.y = h.y + g.y * m.y;
        v.z = h.z + g.z * m.z; v.w = h.w + g.w * m.w;
        o[i] = v;
    }
}

// ------------------------- launcher -----------------------------------------
extern "C" void kernel_launch(void* const* d_in, const int* in_sizes, int n_in,
                              void* d_out, int out_size) {
    const float* hidden = (const float*)d_in[0];
    const float* enc    = (const float*)d_in[1];
    const float* temb   = (const float*)d_in[2];
    const float* W_mod  = (const float*)d_in[3];
    const float* b_mod  = (const float*)d_in[4];
    const float* W_enc  = (const float*)d_in[5];
    const float* b_enc  = (const float*)d_in[6];
    const float* Wq     = (const float*)d_in[7];
    const float* Wk     = (const float*)d_in[8];
    const float* Wv     = (const float*)d_in[9];
    const float* Wak    = (const float*)d_in[10];
    const float* Wav    = (const float*)d_in[11];
    const float* nq_w   = (const float*)d_in[12];
    const float* nk_w   = (const float*)d_in[13];
    const float* nak_w  = (const float*)d_in[14];
    const float* Wo     = (const float*)d_in[15];
    const float* Wg     = (const float*)d_in[16];
    const float* We_in  = (const float*)d_in[17];
    const float* We_out = (const float*)d_in[18];
    const float* Ws_in  = (const float*)d_in[19];
    const float* Ws_out = (const float*)d_in[20];
    float* out = (float*)d_out;

    void* pv;
    #define GF(sym) (cudaGetSymbolAddress(&pv, sym), (float*)pv)
    #define GH(sym) (cudaGetSymbolAddress(&pv, sym), (__half*)pv)
    #define GI(sym) (cudaGetSymbolAddress(&pv, sym), (int*)pv)
    float* p_ctx     = GF(g_ctx);
    float* p_q       = GF(g_q);
    float* p_kimg    = GF(g_kimg);
    float* p_vimg    = GF(g_vimg);
    float* p_ktxt    = GF(g_ktxt);
    float* p_vtxt    = GF(g_vtxt);
    float* p_hs1     = GF(g_hs1);
    float* p_normed2 = GF(g_normed2);
    float* p_hmoe    = GF(g_hmoe);
    float* p_hsh     = GF(g_hsh);
    float* p_outflat = GF(g_outflat);
    float* p_scale1  = GF(g_scale1);
    float* p_scale2  = GF(g_scale2);
    float* p_tg1     = GF(g_tg1);
    int*   p_rowmap  = GI(g_rowmap);
    float* p_rscale  = GF(g_rscale);
    __half *p_enc_h = GH(g_enc_h);
    __half *p_Wenc_h = GH(g_Wenc_h);
    __half *p_Wq_h = GH(g_Wq_h);
    __half *p_Wk_h = GH(g_Wk_h);
    __half *p_Wv_h = GH(g_Wv_h);
    __half *p_Wak_h = GH(g_Wak_h);
    __half *p_Wav_h = GH(g_Wav_h);
    __half *p_Wo_h = GH(g_Wo_h);
    __half *p_Wein_h = GH(g_Wein_h);
    __half *p_Weout_h = GH(g_Weout_h);
    __half *p_Wsin_h = GH(g_Wsin_h);
    __half *p_Wsout_h = GH(g_Wsout_h);
    __half *p_ctx_h = GH(g_ctx_h);
    __half *p_img_h = GH(g_img_h);
    __half *p_attn_h = GH(g_attn_h);
    __half *p_mod2_h = GH(g_mod2_h);
    __half *p_actsh_h = GH(g_actsh_h);
    __half *p_actmoe_h = GH(g_actmoe_h);

    cudaFuncSetAttribute(mma_gemm<0,false>, cudaFuncAttributeMaxDynamicSharedMemorySize, MMSM);
    cudaFuncSetAttribute(mma_gemm<1,false>, cudaFuncAttributeMaxDynamicSharedMemorySize, MMSM);
    cudaFuncSetAttribute(mma_gemm<2,false>, cudaFuncAttributeMaxDynamicSharedMemorySize, MMSM);
    cudaFuncSetAttribute(mma_gemm<3,false>, cudaFuncAttributeMaxDynamicSharedMemorySize, MMSM);
    cudaFuncSetAttribute(mma_gemm<0,true>,  cudaFuncAttributeMaxDynamicSharedMemorySize, MMSM);

    const float* NFP = nullptr;
    const int*   NIP = nullptr;

    #define CVT1(src, dh, n) \
        cvt1_kernel<<<(int)(((n)/4 + 255)/256), 256>>>(src, dh, (long long)(n))

    // 0. convert weights + enc to fp16
    CVT1(W_enc, p_Wenc_h, (long long)DIMM*JD);
    CVT1(Wq,  p_Wq_h,  (long long)DIMM*DIMM);
    CVT1(Wk,  p_Wk_h,  (long long)IKV*DIMM);
    CVT1(Wv,  p_Wv_h,  (long long)IKV*DIMM);
    CVT1(Wak, p_Wak_h, (long long)IKV*DIMM);
    CVT1(Wav, p_Wav_h, (long long)IKV*DIMM);
    CVT1(Wo,  p_Wo_h,  (long long)DIMM*DIMM);
    CVT1(We_in,  p_Wein_h,  (long long)NE*2*NI*DIMM);
    CVT1(We_out, p_Weout_h, (long long)NE*DIMM*NI);
    CVT1(Ws_in,  p_Wsin_h,  (long long)2*NI*DIMM);
    CVT1(Ws_out, p_Wsout_h, (long long)DIMM*NI);
    CVT1(enc, p_enc_h, (long long)BSZ*TXT*JD);

    // 1. modulation
    mod_kernel<<<1536, 256>>>(temb, W_mod, b_mod);
    // 2. context projection (+bias), then convert ctx
    mma_gemm<1,false><<<dim3(12, 8, 1), 256, MMSM>>>(p_enc_h, p_Wenc_h, p_ctx,
        BSZ*TXT, DIMM, JD, 0, 0, 0, b_enc, NFP, NFP, NIP, NFP, NIP);
    CVT1(p_ctx, p_ctx_h, (long long)BSZ*TXT*DIMM);
    // 3. LN1 * scale1 -> half
    ln_mod_kernel<<<NTOK, 256>>>(hidden, p_scale1, p_img_h, nullptr);
    // 4. projections
    mma_gemm<0,false><<<dim3(12, 16, 1), 256, MMSM>>>(p_img_h, p_Wq_h, p_q,
        NTOK, DIMM, DIMM, 0, 0, 0, NFP, NFP, NFP, NIP, NFP, NIP);
    mma_gemm<0,false><<<dim3(4, 16, 1), 256, MMSM>>>(p_img_h, p_Wk_h, p_kimg,
        NTOK, IKV, DIMM, 0, 0, 0, NFP, NFP, NFP, NIP, NFP, NIP);
    mma_gemm<0,false><<<dim3(4, 16, 1), 256, MMSM>>>(p_img_h, p_Wv_h, p_vimg,
        NTOK, IKV, DIMM, 0, 0, 0, NFP, NFP, NFP, NIP, NFP, NIP);
    mma_gemm<0,false><<<dim3(4, 8, 1), 256, MMSM>>>(p_ctx_h, p_Wak_h, p_ktxt,
        BSZ*TXT, IKV, DIMM, 0, 0, 0, NFP, NFP, NFP, NIP, NFP, NIP);
    mma_gemm<0,false><<<dim3(4, 8, 1), 256, MMSM>>>(p_ctx_h, p_Wav_h, p_vtxt,
        BSZ*TXT, IKV, DIMM, 0, 0, 0, NFP, NFP, NFP, NIP, NFP, NIP);
    // 5. norms + repack
    rms_q_kernel<<<3072, 256>>>(nq_w);
    kv_repack_kernel<<<1536, 256>>>(nk_w, nak_w);
    // 6. attention (-> half)
    flash_kernel<<<dim3(SEQ/32, NH, BSZ), 256>>>();
    // 7. output proj + gated residual
    mma_gemm<2,false><<<dim3(12, 16, 1), 256, MMSM>>>(p_attn_h, p_Wo_h, p_hs1,
        NTOK, DIMM, DIMM, 0, 0, 0, NFP, hidden, p_tg1, NIP, NFP, NIP);
    // 8. LN2 -> mod2 half + normed2 fp32
    ln_mod_kernel<<<NTOK, 256>>>(p_hs1, p_scale2, p_mod2_h, p_normed2);
    // 9. router
    tembdot_kernel<<<1, 1024>>>(temb, Wg);
    router_kernel<<<NTOK, 128>>>(Wg);
    topk_kernel<<<BSZ*NE, 512>>>();
    zero_sums_kernel<<<8, 256>>>();
    sum_acc_kernel<<<64, 256>>>();
    gate_norm_kernel<<<64, 256>>>();
    // 10. expert GEMM 1 (gathered A rows, batched over 16 experts)
    mma_gemm<0,true><<<dim3(21, 8, 16), 256, MMSM>>>(p_mod2_h, p_Wein_h, p_hmoe,
        BSZ*CAP, 2*NI, DIMM,
        0, (long long)2*NI*DIMM, (long long)BSZ*CAP*2*NI,
        NFP, NFP, NFP, NIP, NFP, p_rowmap);
    swiglu_kernel<<<MROWS, 256>>>(p_hmoe, p_actmoe_h);
    // 11. shared expert
    mma_gemm<0,false><<<dim3(21, 16, 1), 256, MMSM>>>(p_mod2_h, p_Wsin_h, p_hsh,
        NTOK, 2*NI, DIMM, 0, 0, 0, NFP, NFP, NFP, NIP, NFP, NIP);
    swiglu_kernel<<<NTOK, 256>>>(p_hsh, p_actsh_h);
    mma_gemm<0,false><<<dim3(12, 16, 1), 256, MMSM>>>(p_actsh_h, p_Wsout_h, p_outflat,
        NTOK, DIMM, NI, 0, 0, 0, NFP, NFP, NFP, NIP, NFP, NIP);
    // 12. expert GEMM 2 with atomic scatter onto shared output
    mma_gemm<3,false><<<dim3(12, 8, 16), 256, MMSM>>>(p_actmoe_h, p_Weout_h, p_outflat,
        BSZ*CAP, DIMM, NI,
        (long long)BSZ*CAP*NI, (long long)DIMM*NI, 0,
        NFP, NFP, NFP, p_rowmap, p_rscale, NIP);
    // 13. final gated residual
    final_kernel<<<NTOK, 256>>>(out);
}

// round 13
// speedup vs baseline: 3.8733x; 1.8236x over previous
#include <cuda_runtime.h>
#include <cuda_fp16.h>
#include <math.h>
#include <stdint.h>

#define BSZ 2
#define SEQ 1024
#define TXT 512
#define DIMM 1536
#define NH 12
#define HDD 128
#define NKV 4
#define JD 3584
#define NE 16
#define NI 1344
#define CAP 512
#define LTOT 1536      // SEQ + TXT
#define NTOK 2048      // BSZ*SEQ
#define MROWS 16384    // NE*BSZ*CAP
#define IKV 512        // NKV*HDD
#define REP 3          // NH/NKV
#define EPSL 1e-6f

// ------------------------- fp32 scratch -------------------------------------
__device__ float g_scale1[BSZ*DIMM];
__device__ float g_tg1[BSZ*DIMM];
__device__ float g_scale2[BSZ*DIMM];
__device__ float g_tg2[BSZ*DIMM];
__device__ float g_ctx[BSZ*TXT*DIMM];
__device__ float g_q[NTOK*DIMM];
__device__ float g_kimg[NTOK*IKV];
__device__ float g_vimg[NTOK*IKV];
__device__ float g_ktxt[BSZ*TXT*IKV];
__device__ float g_vtxt[BSZ*TXT*IKV];
__device__ float g_hs1[NTOK*DIMM];
__device__ float g_normed2[NTOK*DIMM];
__device__ float g_tembdot[BSZ*NE];
__device__ float g_aff[BSZ*NE*SEQ];
__device__ int   g_topidx[BSZ*NE*CAP];
__device__ float g_gating[BSZ*NE*CAP];
__device__ float g_sums[NTOK];
__device__ int   g_rowmap[MROWS];
__device__ float g_rscale[MROWS];
__device__ float g_hmoe[(size_t)MROWS*2*NI];
__device__ float g_hsh[NTOK*2*NI];
__device__ float g_outflat[NTOK*DIMM];

// ------------------------- half planes --------------------------------------
__device__ __half g_enc_h[BSZ*TXT*JD];
__device__ __half g_Wenc_h[DIMM*JD];
__device__ __half g_Wq_h[DIMM*DIMM];
__device__ __half g_Wk_h[IKV*DIMM];
__device__ __half g_Wv_h[IKV*DIMM];
__device__ __half g_Wak_h[IKV*DIMM];
__device__ __half g_Wav_h[IKV*DIMM];
__device__ __half g_Wo_h[DIMM*DIMM];
__device__ __half g_Wein_h[(size_t)NE*2*NI*DIMM];
__device__ __half g_Weout_h[(size_t)NE*DIMM*NI];
__device__ __half g_Wsin_h[2*NI*DIMM];
__device__ __half g_Wsout_h[DIMM*NI];
__device__ __half g_ctx_h[BSZ*TXT*DIMM];
__device__ __half g_img_h[NTOK*DIMM];
__device__ __half g_attn_h[NTOK*DIMM];
__device__ __half g_mod2_h[NTOK*DIMM];
__device__ __half g_actsh_h[NTOK*NI];
__device__ __half g_actmoe_h[(size_t)MROWS*NI];
// attention fp16 operands
__device__ __half g_qh[NTOK*DIMM];
__device__ __half g_kh[(size_t)BSZ*NKV*LTOT*HDD];
__device__ __half g_vT[(size_t)BSZ*NKV*HDD*LTOT];

// ======================= helpers ============================================
__device__ __forceinline__ uint32_t s2u(const void* p) {
    uint32_t a;
    asm("{ .reg .u64 t; cvta.to.shared.u64 t, %1; cvt.u32.u64 %0, t; }"
        : "=r"(a) : "l"(p));
    return a;
}
__device__ __forceinline__ void cpa16(uint32_t d, const void* s) {
    asm volatile("cp.async.cg.shared.global [%0], [%1], 16;" :: "r"(d), "l"(s));
}
__device__ __forceinline__ void mma16816(float* c, const uint32_t* a, const uint32_t* b) {
    asm volatile(
        "mma.sync.aligned.m16n8k16.row.col.f32.f16.f16.f32 "
        "{%0,%1,%2,%3}, {%4,%5,%6,%7}, {%8,%9}, {%0,%1,%2,%3};"
        : "+f"(c[0]), "+f"(c[1]), "+f"(c[2]), "+f"(c[3])
        : "r"(a[0]), "r"(a[1]), "r"(a[2]), "r"(a[3]), "r"(b[0]), "r"(b[1]));
}
#define LDSM4(r0, r1, r2, r3, addr) \
    asm volatile("ldmatrix.sync.aligned.m8n8.x4.shared.b16 {%0,%1,%2,%3}, [%4];" \
        : "=r"(r0), "=r"(r1), "=r"(r2), "=r"(r3) : "r"(addr))

// ------------------------- fp32 -> half conversion ---------------------------
__global__ __launch_bounds__(256) void cvt1_kernel(const float* __restrict__ src,
                                                   __half* __restrict__ dh,
                                                   long long n) {
    long long i = ((long long)blockIdx.x * 256 + threadIdx.x) * 4;
    if (i >= n) return;
    float4 v = *(const float4*)(src + i);
    __half2* ph = (__half2*)(dh + i);
    ph[0] = __halves2half2(__float2half(v.x), __float2half(v.y));
    ph[1] = __halves2half2(__float2half(v.z), __float2half(v.w));
}

// ======================= pipelined fp16 GEMM ================================
#define PRS 144
#define PLSZ (128*PRS)
#define BUFSZ (2*PLSZ)
#define MMSM (2*BUFSZ)

template<int EPI, bool AG>
__global__ __launch_bounds__(256, 2) void mma_gemm(
    const __half* __restrict__ Ah, const __half* __restrict__ Bh,
    float* __restrict__ C,
    int M, int N, int K,
    long long sA, long long sB, long long sC,
    const float* __restrict__ bias,
    const float* __restrict__ resid, const float* __restrict__ gate,
    const int* __restrict__ rowmap, const float* __restrict__ rscale,
    const int* __restrict__ agather)
{
    extern __shared__ char smem[];
    const int tid = threadIdx.x;
    const int wid = tid >> 5, lane = tid & 31;
    const int z = blockIdx.z;
    const int m0 = blockIdx.y * 128, n0 = blockIdx.x * 128;
    if (!AG) Ah += (long long)z * sA;
    Bh += (long long)z * sB;

    const int lr = tid >> 1;
    const int lh = tid & 1;
    long long arow = AG ? (long long)agather[(long long)z * M + m0 + lr]
                        : (long long)(m0 + lr);
    const __half* aHp = Ah + arow * (long long)K + lh * 32;
    const __half* bHp = Bh + (long long)(n0 + lr) * K + lh * 32;
    const uint32_t pofs = lr * PRS + lh * 64;

    const uint32_t uA = s2u(smem);
    const uint32_t uB = uA + PLSZ;

    const int wm = (wid >> 2) * 64;
    const int wn = (wid & 3) * 32;
    uint32_t a_off[4];
    #pragma unroll
    for (int mt = 0; mt < 4; mt++) {
        int r = wm + mt * 16 + (lane & 15);
        a_off[mt] = r * PRS + (lane >> 4) * 16;
    }
    uint32_t b_off[2];
    #pragma unroll
    for (int np = 0; np < 2; np++) {
        int r = wn + np * 16 + ((lane >> 4) << 3) + (lane & 7);
        b_off[np] = r * PRS + ((lane >> 3) & 1) * 16;
    }

    float acc[4][4][4];
    #pragma unroll
    for (int mt = 0; mt < 4; mt++)
        #pragma unroll
        for (int nt = 0; nt < 4; nt++)
            #pragma unroll
            for (int i = 0; i < 4; i++) acc[mt][nt][i] = 0.f;

    const int NC = K >> 6;
    auto issue = [&](int c, uint32_t boff) {
        long long ko = (long long)c * 64;
        #pragma unroll
        for (int i = 0; i < 4; i++) {
            cpa16(uA + boff + pofs + 16 * i, aHp + ko + 8 * i);
            cpa16(uB + boff + pofs + 16 * i, bHp + ko + 8 * i);
        }
        asm volatile("cp.async.commit_group;");
    };

    issue(0, 0);
    for (int c = 0; c < NC; c++) {
        const uint32_t boff = (c & 1) * BUFSZ;
        if (c + 1 < NC) {
            issue(c + 1, (~c & 1) * BUFSZ);
            asm volatile("cp.async.wait_group 1;");
        } else {
            asm volatile("cp.async.wait_group 0;");
        }
        __syncthreads();
        #pragma unroll
        for (int ks = 0; ks < 4; ks++) {
            uint32_t bf[4][2];
            #pragma unroll
            for (int np = 0; np < 2; np++)
                LDSM4(bf[np*2][0], bf[np*2][1], bf[np*2+1][0], bf[np*2+1][1],
                      uB + boff + b_off[np] + ks * 32);
            #pragma unroll
            for (int mt = 0; mt < 4; mt++) {
                uint32_t af[4];
                LDSM4(af[0], af[1], af[2], af[3], uA + boff + a_off[mt] + ks * 32);
                #pragma unroll
                for (int nt = 0; nt < 4; nt++) mma16816(acc[mt][nt], af, bf[nt]);
            }
        }
        __syncthreads();
    }

    const int g = lane >> 2;
    const int cp2 = (lane & 3) * 2;
    #pragma unroll
    for (int mt = 0; mt < 4; mt++) {
        #pragma unroll
        for (int hh = 0; hh < 2; hh++) {
            int row = m0 + wm + mt * 16 + g + hh * 8;
            if (EPI == 3) {
                long long gr = (long long)z * M + row;
                int trow = rowmap[gr];
                float s = rscale[gr];
                float* cp = C + (long long)trow * N;
                #pragma unroll
                for (int nt = 0; nt < 4; nt++) {
                    int col = n0 + wn + nt * 8 + cp2;
                    atomicAdd(cp + col,     acc[mt][nt][hh*2]   * s);
                    atomicAdd(cp + col + 1, acc[mt][nt][hh*2+1] * s);
                }
            } else {
                float* Cz = C + (long long)z * sC + (long long)row * N;
                #pragma unroll
                for (int nt = 0; nt < 4; nt++) {
                    int col = n0 + wn + nt * 8 + cp2;
                    float v0 = acc[mt][nt][hh*2], v1 = acc[mt][nt][hh*2+1];
                    if (EPI == 1) { v0 += bias[col]; v1 += bias[col + 1]; }
                    if (EPI == 2) {
                        const float* gp = gate + (row / SEQ) * N + col;
                        const float* rp = resid + (long long)row * N + col;
                        v0 = rp[0] + gp[0] * v0;
                        v1 = rp[1] + gp[1] * v1;
                    }
                    *(float2*)(Cz + col) = make_float2(v0, v1);
                }
            }
        }
    }
}

// ------------------------- modulation ----------------------------------------
__global__ __launch_bounds__(256) void mod_kernel(const float* __restrict__ temb,
                                                  const float* __restrict__ Wm,
                                                  const float* __restrict__ bm) {
    int gw = (blockIdx.x * blockDim.x + threadIdx.x) >> 5;
    int lane = threadIdx.x & 31;
    if (gw >= BSZ * 4 * DIMM) return;
    int b = gw / (4 * DIMM);
    int j = gw - b * 4 * DIMM;
    const float* t = temb + b * DIMM;
    const float* w = Wm + (size_t)j * DIMM;
    float acc = 0.f;
    for (int kk = lane; kk < DIMM; kk += 32) {
        float x = t[kk];
        acc += (x / (1.f + __expf(-x))) * w[kk];
    }
    #pragma unroll
    for (int o = 16; o; o >>= 1) acc += __shfl_xor_sync(0xffffffffu, acc, o);
    if (lane == 0) {
        acc += bm[j];
        int q = j / DIMM, c = j - q * DIMM;
        if (q == 0)      g_scale1[b*DIMM + c] = 1.f + acc;
        else if (q == 1) g_tg1[b*DIMM + c]    = tanhf(fminf(fmaxf(acc, -2.f), 2.f));
        else if (q == 2) g_scale2[b*DIMM + c] = 1.f + acc;
        else             g_tg2[b*DIMM + c]    = tanhf(fminf(fmaxf(acc, -2.f), 2.f));
    }
}

// ------------------------- LayerNorm -> half (+opt fp32 normed) --------------
__global__ __launch_bounds__(256) void ln_mod_kernel(const float* __restrict__ in,
                                                     const float* __restrict__ scale,
                                                     __half* __restrict__ mh,
                                                     float* __restrict__ outnorm) {
    int rowi = blockIdx.x;
    int b = rowi >> 10;
    const float* x = in + (size_t)rowi * DIMM;
    float s = 0.f, sq = 0.f;
    for (int d = threadIdx.x; d < DIMM; d += 256) { float v = x[d]; s += v; sq += v * v; }
    #pragma unroll
    for (int o = 16; o; o >>= 1) {
        s  += __shfl_xor_sync(0xffffffffu, s,  o);
        sq += __shfl_xor_sync(0xffffffffu, sq, o);
    }
    __shared__ float rs[8], rq[8], mv[2];
    int w = threadIdx.x >> 5;
    if ((threadIdx.x & 31) == 0) { rs[w] = s; rq[w] = sq; }
    __syncthreads();
    if (threadIdx.x == 0) {
        float S = 0.f, Q = 0.f;
        for (int i = 0; i < 8; i++) { S += rs[i]; Q += rq[i]; }
        float mean = S / DIMM;
        float var = Q / DIMM - mean * mean;
        mv[0] = mean; mv[1] = rsqrtf(var + EPSL);
    }
    __syncthreads();
    float mean = mv[0], rstd = mv[1];
    const float* sc = scale + (size_t)b * DIMM;
    for (int d = threadIdx.x; d < DIMM; d += 256) {
        float n = (x[d] - mean) * rstd;
        if (outnorm) outnorm[(size_t)rowi * DIMM + d] = n;
        mh[(size_t)rowi * DIMM + d] = __float2half(n * sc[d]);
    }
}

// ------------------------- per-head RMSNorm of Q -> fp16 ---------------------
__global__ __launch_bounds__(256) void rms_q_kernel(const float* __restrict__ w) {
    int gw = (blockIdx.x * blockDim.x + threadIdx.x) >> 5;
    if (gw >= NTOK * NH) return;
    int lane = threadIdx.x & 31;
    const float* p = g_q + (size_t)gw * HDD;
    int d4 = lane << 2;
    float4 v = *(const float4*)(p + d4);
    float ss = v.x*v.x + v.y*v.y + v.z*v.z + v.w*v.w;
    #pragma unroll
    for (int o = 16; o; o >>= 1) ss += __shfl_xor_sync(0xffffffffu, ss, o);
    float r = rsqrtf(ss / HDD + EPSL);
    float4 wv = *(const float4*)(w + d4);
    v.x *= r * wv.x; v.y *= r * wv.y; v.z *= r * wv.z; v.w *= r * wv.w;
    __half2* dst = (__half2*)(g_qh + (size_t)gw * HDD + d4);
    dst[0] = __halves2half2(__float2half(v.x), __float2half(v.y));
    dst[1] = __halves2half2(__float2half(v.z), __float2half(v.w));
}

// ------------------------- K RMS + K/V fp16 repack ---------------------------
// K -> g_kh[b][kv][key][dim] fp16;  V -> g_vT[b][kv][dim][key] fp16 (transposed)
__global__ __launch_bounds__(256) void kv_repack_kernel(const float* __restrict__ nk,
                                                        const float* __restrict__ nak) {
    int gw = (blockIdx.x * blockDim.x + threadIdx.x) >> 5;
    if (gw >= BSZ * NKV * LTOT) return;
    int lane = threadIdx.x & 31;
    int l = gw % LTOT;
    int bk = gw / LTOT;
    int kv = bk % NKV, b = bk / NKV;
    const float *ksrc, *vsrc, *w;
    if (l < SEQ) {
        ksrc = g_kimg + (size_t)(b * SEQ + l) * IKV + kv * HDD;
        vsrc = g_vimg + (size_t)(b * SEQ + l) * IKV + kv * HDD;
        w = nk;
    } else {
        int tt = l - SEQ;
        ksrc = g_ktxt + (size_t)(b * TXT + tt) * IKV + kv * HDD;
        vsrc = g_vtxt + (size_t)(b * TXT + tt) * IKV + kv * HDD;
        w = nak;
    }
    int d4 = lane << 2;
    float4 kvv = *(const float4*)(ksrc + d4);
    float ss = kvv.x*kvv.x + kvv.y*kvv.y + kvv.z*kvv.z + kvv.w*kvv.w;
    #pragma unroll
    for (int o = 16; o; o >>= 1) ss += __shfl_xor_sync(0xffffffffu, ss, o);
    float r = rsqrtf(ss / HDD + EPSL);
    float4 wv = *(const float4*)(w + d4);
    kvv.x *= r * wv.x; kvv.y *= r * wv.y; kvv.z *= r * wv.z; kvv.w *= r * wv.w;
    size_t kb = ((size_t)(b * NKV + kv) * LTOT + l) * HDD + d4;
    __half2* kd = (__half2*)(g_kh + kb);
    kd[0] = __halves2half2(__float2half(kvv.x), __float2half(kvv.y));
    kd[1] = __halves2half2(__float2half(kvv.z), __float2half(kvv.w));
    float4 vv = *(const float4*)(vsrc + d4);
    size_t vb = (size_t)(b * NKV + kv) * HDD;
    g_vT[(vb + d4    ) * LTOT + l] = __float2half(vv.x);
    g_vT[(vb + d4 + 1) * LTOT + l] = __float2half(vv.y);
    g_vT[(vb + d4 + 2) * LTOT + l] = __float2half(vv.z);
    g_vT[(vb + d4 + 3) * LTOT + l] = __float2half(vv.w);
}

// ------------------------- mma flash attention -------------------------------
// 64 queries x 1 head per CTA, 4 warps (16 rows each), key chunks of 64.
#define FQSTR 272
#define FVSTR 144
#define FQSZ (64*FQSTR)          // 17408
#define FKSZ (64*FQSTR)          // 17408
#define FVSZ (128*FVSTR)         // 18432
#define FBUF (FKSZ+FVSZ)         // 35840
#define FSM  (FQSZ + 2*FBUF)     // 89088

__global__ __launch_bounds__(128, 2) void flash_kernel() {
    extern __shared__ char fsm[];
    const int q0 = blockIdx.x * 64;
    const int h = blockIdx.y;
    const int b = blockIdx.z;
    const int kv = h / REP;
    const int t = threadIdx.x;
    const int w = t >> 5, lane = t & 31;
    const uint32_t uQ = s2u(fsm);
    const uint32_t uK0 = uQ + FQSZ;
    const __half* qg = g_qh + (size_t)(b * SEQ + q0) * DIMM + h * HDD;
    const __half* kg = g_kh + (size_t)(b * NKV + kv) * LTOT * HDD;
    const __half* vg = g_vT + (size_t)(b * NKV + kv) * HDD * LTOT;

    {   // Q tile: 64 rows x 256B
        int r = t >> 1, seg = t & 1;
        const __half* src = qg + (size_t)r * DIMM + seg * 64;
        uint32_t dst = uQ + r * FQSTR + seg * 128;
        #pragma unroll
        for (int i = 0; i < 8; i++) cpa16(dst + 16 * i, src + 8 * i);
        asm volatile("cp.async.commit_group;");
    }
    auto issue = [&](int c) {
        uint32_t base = uK0 + (c & 1) * FBUF;
        int k0 = c * 64;
        int r = t >> 1, seg = t & 1;
        const __half* ks = kg + (size_t)(k0 + r) * HDD + seg * 64;
        uint32_t kd = base + r * FQSTR + seg * 128;
        #pragma unroll
        for (int i = 0; i < 8; i++) cpa16(kd + 16 * i, ks + 8 * i);
        const __half* vs = vg + (size_t)t * LTOT + k0;
        uint32_t vd = base + FKSZ + t * FVSTR;
        #pragma unroll
        for (int i = 0; i < 8; i++) cpa16(vd + 16 * i, vs + 8 * i);
        asm volatile("cp.async.commit_group;");
    };

    const uint32_t aq_off = (w * 16 + (lane & 15)) * FQSTR + (lane >> 4) * 16;
    uint32_t bk_off[4];
    #pragma unroll
    for (int np = 0; np < 4; np++)
        bk_off[np] = (np * 16 + ((lane >> 4) << 3) + (lane & 7)) * FQSTR
                   + ((lane >> 3) & 1) * 16;
    uint32_t bv_off[8];
    #pragma unroll
    for (int np = 0; np < 8; np++)
        bv_off[np] = (np * 16 + ((lane >> 4) << 3) + (lane & 7)) * FVSTR
                   + ((lane >> 3) & 1) * 16;

    float o[16][4];
    #pragma unroll
    for (int i = 0; i < 16; i++)
        #pragma unroll
        for (int j = 0; j < 4; j++) o[i][j] = 0.f;
    float m0 = -1e30f, m1 = -1e30f, l0 = 0.f, l1 = 0.f;
    const float sc = 0.08838834764831845f;

    issue(0);
    const int NCH = LTOT / 64;
    for (int c = 0; c < NCH; c++) {
        if (c + 1 < NCH) { issue(c + 1); asm volatile("cp.async.wait_group 1;"); }
        else             { asm volatile("cp.async.wait_group 0;"); }
        __syncthreads();
        const uint32_t base = uK0 + (c & 1) * FBUF;
        float s[8][4];
        #pragma unroll
        for (int nt = 0; nt < 8; nt++)
            #pragma unroll
            for (int j = 0; j < 4; j++) s[nt][j] = 0.f;
        #pragma unroll
        for (int ks = 0; ks < 8; ks++) {
            uint32_t bf[8][2];
            #pragma unroll
            for (int np = 0; np < 4; np++)
                LDSM4(bf[np*2][0], bf[np*2][1], bf[np*2+1][0], bf[np*2+1][1],
                      base + bk_off[np] + ks * 32);
            uint32_t af[4];
            LDSM4(af[0], af[1], af[2], af[3], uQ + aq_off + ks * 32);
            #pragma unroll
            for (int nt = 0; nt < 8; nt++) mma16816(s[nt], af, bf[nt]);
        }
        // ---- online softmax (rows g, g+8; quad lanes share a row) ----
        float mx0 = -1e30f, mx1 = -1e30f;
        #pragma unroll
        for (int nt = 0; nt < 8; nt++) {
            mx0 = fmaxf(mx0, fmaxf(s[nt][0], s[nt][1]));
            mx1 = fmaxf(mx1, fmaxf(s[nt][2], s[nt][3]));
        }
        #pragma unroll
        for (int off = 1; off < 4; off <<= 1) {
            mx0 = fmaxf(mx0, __shfl_xor_sync(0xffffffffu, mx0, off));
            mx1 = fmaxf(mx1, __shfl_xor_sync(0xffffffffu, mx1, off));
        }
        float nm0 = fmaxf(m0, mx0 * sc), nm1 = fmaxf(m1, mx1 * sc);
        float cr0 = __expf(m0 - nm0), cr1 = __expf(m1 - nm1);
        float sum0 = 0.f, sum1 = 0.f;
        uint32_t pr0[8], pr1[8];
        #pragma unroll
        for (int nt = 0; nt < 8; nt++) {
            float p0 = __expf(s[nt][0] * sc - nm0);
            float p1 = __expf(s[nt][1] * sc - nm0);
            float p2 = __expf(s[nt][2] * sc - nm1);
            float p3 = __expf(s[nt][3] * sc - nm1);
            sum0 += p0 + p1; sum1 += p2 + p3;
            __half2 h0 = __halves2half2(__float2half(p0), __float2half(p1));
            __half2 h1 = __halves2half2(__float2half(p2), __float2half(p3));
            pr0[nt] = *(uint32_t*)&h0;
            pr1[nt] = *(uint32_t*)&h1;
        }
        #pragma unroll
        for (int off = 1; off < 4; off <<= 1) {
            sum0 += __shfl_xor_sync(0xffffffffu, sum0, off);
            sum1 += __shfl_xor_sync(0xffffffffu, sum1, off);
        }
        l0 = l0 * cr0 + sum0; l1 = l1 * cr1 + sum1;
        m0 = nm0; m1 = nm1;
        #pragma unroll
        for (int nt2 = 0; nt2 < 16; nt2++) {
            o[nt2][0] *= cr0; o[nt2][1] *= cr0;
            o[nt2][2] *= cr1; o[nt2][3] *= cr1;
        }
        // ---- PV: P fragments direct from S c-fragments ----
        const uint32_t vbase = base + FKSZ;
        #pragma unroll
        for (int ks2 = 0; ks2 < 4; ks2++) {
            uint32_t a[4] = { pr0[2*ks2], pr1[2*ks2], pr0[2*ks2+1], pr1[2*ks2+1] };
            #pragma unroll
            for (int np = 0; np < 8; np++) {
                uint32_t bf2[2][2];
                LDSM4(bf2[0][0], bf2[0][1], bf2[1][0], bf2[1][1],
                      vbase + bv_off[np] + ks2 * 32);
                mma16816(o[np*2],     a, bf2[0]);
                mma16816(o[np*2 + 1], a, bf2[1]);
            }
        }
        __syncthreads();
    }
    float i0 = 1.f / l0, i1 = 1.f / l1;
    const int g = lane >> 2, cp2 = (lane & 3) * 2;
    size_t ob = (size_t)(b * SEQ + q0 + w * 16 + g) * DIMM + h * HDD;
    #pragma unroll
    for (int nt2 = 0; nt2 < 16; nt2++) {
        __half2 v0 = __halves2half2(__float2half(o[nt2][0] * i0),
                                    __float2half(o[nt2][1] * i0));
        __half2 v1 = __halves2half2(__float2half(o[nt2][2] * i1),
                                    __float2half(o[nt2][3] * i1));
        *(__half2*)&g_attn_h[ob + nt2 * 8 + cp2] = v0;
        *(__half2*)&g_attn_h[ob + 8 * DIMM + nt2 * 8 + cp2] = v1;
    }
}

// ------------------------- router ------------------------------------------
__global__ __launch_bounds__(1024) void tembdot_kernel(const float* __restrict__ temb,
                                                       const float* __restrict__ Wg) {
    int wid = threadIdx.x >> 5, lane = threadIdx.x & 31;
    int b = wid / NE, e = wid % NE;
    const float* t = temb + b * DIMM;
    const float* w = Wg + (size_t)e * 2 * DIMM;
    float acc = 0.f;
    for (int d = lane; d < DIMM; d += 32) acc += t[d] * w[d];
    #pragma unroll
    for (int o = 16; o; o >>= 1) acc += __shfl_xor_sync(0xffffffffu, acc, o);
    if (lane == 0) g_tembdot[wid] = acc;
}

__global__ __launch_bounds__(128) void router_kernel(const float* __restrict__ Wg) {
    __shared__ float lg[NE];
    int tokid = blockIdx.x;
    int b = tokid >> 10, s = tokid & 1023;
    int w = threadIdx.x >> 5, lane = threadIdx.x & 31;
    const float* x = g_normed2 + (size_t)tokid * DIMM;
    for (int e = w * 4; e < w * 4 + 4; e++) {
        const float* wg = Wg + (size_t)e * 2 * DIMM + DIMM;
        float acc = 0.f;
        for (int d = lane; d < DIMM; d += 32) acc += x[d] * wg[d];
        #pragma unroll
        for (int o = 16; o; o >>= 1) acc += __shfl_xor_sync(0xffffffffu, acc, o);
        if (lane == 0) lg[e] = acc + g_tembdot[b * NE + e];
    }
    __syncthreads();
    if (threadIdx.x == 0) {
        float mx = -1e30f;
        for (int e = 0; e < NE; e++) mx = fmaxf(mx, lg[e]);
        float ex[NE], sm = 0.f;
        for (int e = 0; e < NE; e++) { ex[e] = __expf(lg[e] - mx); sm += ex[e]; }
        float inv = 1.f / sm;
        for (int e = 0; e < NE; e++)
            g_aff[((size_t)(b * NE + e)) * SEQ + s] = ex[e] * inv;
    }
}

// ------------------------- exact top-k via bitonic sort ---------------------
__global__ __launch_bounds__(512) void topk_kernel() {
    __shared__ float v[1024];
    __shared__ int   id[1024];
    int be = blockIdx.x;
    const float* rowp = g_aff + (size_t)be * SEQ;
    int t = threadIdx.x;
    for (int i = t; i < 1024; i += 512) { v[i] = rowp[i]; id[i] = i; }
    __syncthreads();
    for (int k = 2; k <= 1024; k <<= 1) {
        for (int j = k >> 1; j > 0; j >>= 1) {
            for (int i = t; i < 1024; i += 512) {
                int ixj = i ^ j;
                if (ixj > i) {
                    bool up = ((i & k) == 0);
                    float va = v[i], vb = v[ixj];
                    int ia = id[i], ib = id[ixj];
                    bool a_first = (va > vb) || (va == vb && ia < ib);
                    bool sw = up ? !a_first : a_first;
                    if (sw) { v[i] = vb; v[ixj] = va; id[i] = ib; id[ixj] = ia; }
                }
            }
            __syncthreads();
        }
    }
    if (t < CAP) {
        g_gating[be * CAP + t] = v[t];
        g_topidx[be * CAP + t] = id[t];
    }
}

__global__ void zero_sums_kernel() {
    int i = blockIdx.x * blockDim.x + threadIdx.x;
    if (i < NTOK) g_sums[i] = 0.f;
}

__global__ void sum_acc_kernel() {
    int i = blockIdx.x * blockDim.x + threadIdx.x;
    if (i >= BSZ * NE * CAP) return;
    int be = i / CAP;
    int b = be / NE;
    int tok = b * SEQ + g_topidx[i];
    atomicAdd(&g_sums[tok], g_gating[i]);
}

__global__ void gate_norm_kernel() {
    int i = blockIdx.x * blockDim.x + threadIdx.x;
    if (i >= BSZ * NE * CAP) return;
    int c = i % CAP;
    int be = i / CAP;
    int b = be / NE, e = be % NE;
    int tok = b * SEQ + g_topidx[i];
    float g = g_gating[i] / (g_sums[tok] + 1e-12f) * 2.5f;
    int rowflat = (e * BSZ + b) * CAP + c;
    g_rowmap[rowflat] = tok;
    g_rscale[rowflat] = g;
}

// ------------------------- swiglu -> half ------------------------------------
__global__ __launch_bounds__(256) void swiglu_kernel(const float* __restrict__ h,
                                                     __half* __restrict__ oh) {
    int r = blockIdx.x;
    const float4* a = (const float4*)(h + (size_t)r * 2 * NI);
    const float4* g = (const float4*)(h + (size_t)r * 2 * NI + NI);
    for (int i = threadIdx.x; i < NI / 4; i += 256) {
        float4 av = a[i], gv = g[i];
        float f0 = av.x * (gv.x / (1.f + __expf(-gv.x)));
        float f1 = av.y * (gv.y / (1.f + __expf(-gv.y)));
        float f2 = av.z * (gv.z / (1.f + __expf(-gv.z)));
        float f3 = av.w * (gv.w / (1.f + __expf(-gv.w)));
        __half2* ph = (__half2*)(oh + (size_t)r * NI + i * 4);
        ph[0] = __halves2half2(__float2half(f0), __float2half(f1));
        ph[1] = __halves2half2(__float2half(f2), __float2half(f3));
    }
}

// ------------------------- final residual -----------------------------------
__global__ __launch_bounds__(256) void final_kernel(float* __restrict__ out) {
    int r = blockIdx.x;
    int b = r >> 10;
    const float4* hs = (const float4*)(g_hs1 + (size_t)r * DIMM);
    const float4* mo = (const float4*)(g_outflat + (size_t)r * DIMM);
    const float4* gg = (const float4*)(g_tg2 + (size_t)b * DIMM);
    float4* o = (float4*)(out + (size_t)r * DIMM);
    for (int i = threadIdx.x; i < DIMM / 4; i += 256) {
        float4 h = hs[i], m = mo[i], g = gg[i], v;
        v.x = h.x + g.x * m.x; v.y = h.y + g.y * m.y;
        v.z = h.z + g.z * m.z; v.w = h.w + g.w * m.w;
        o[i] = v;
    }
}

// ------------------------- launcher -----------------------------------------
extern "C" void kernel_launch(void* const* d_in, const int* in_sizes, int n_in,
                              void* d_out, int out_size) {
    const float* hidden = (const float*)d_in[0];
    const float* enc    = (const float*)d_in[1];
    const float* temb   = (const float*)d_in[2];
    const float* W_mod  = (const float*)d_in[3];
    const float* b_mod  = (const float*)d_in[4];
    const float* W_enc  = (const float*)d_in[5];
    const float* b_enc  = (const float*)d_in[6];
    const float* Wq     = (const float*)d_in[7];
    const float* Wk     = (const float*)d_in[8];
    const float* Wv     = (const float*)d_in[9];
    const float* Wak    = (const float*)d_in[10];
    const float* Wav    = (const float*)d_in[11];
    const float* nq_w   = (const float*)d_in[12];
    const float* nk_w   = (const float*)d_in[13];
    const float* nak_w  = (const float*)d_in[14];
    const float* Wo     = (const float*)d_in[15];
    const float* Wg     = (const float*)d_in[16];
    const float* We_in  = (const float*)d_in[17];
    const float* We_out = (const float*)d_in[18];
    const float* Ws_in  = (const float*)d_in[19];
    const float* Ws_out = (const float*)d_in[20];
    float* out = (float*)d_out;

    void* pv;
    #define GF(sym) (cudaGetSymbolAddress(&pv, sym), (float*)pv)
    #define GH(sym) (cudaGetSymbolAddress(&pv, sym), (__half*)pv)
    #define GI(sym) (cudaGetSymbolAddress(&pv, sym), (int*)pv)
    float* p_ctx     = GF(g_ctx);
    float* p_q       = GF(g_q);
    float* p_kimg    = GF(g_kimg);
    float* p_vimg    = GF(g_vimg);
    float* p_ktxt    = GF(g_ktxt);
    float* p_vtxt    = GF(g_vtxt);
    float* p_hs1     = GF(g_hs1);
    float* p_normed2 = GF(g_normed2);
    float* p_hmoe    = GF(g_hmoe);
    float* p_hsh     = GF(g_hsh);
    float* p_outflat = GF(g_outflat);
    float* p_scale1  = GF(g_scale1);
    float* p_scale2  = GF(g_scale2);
    float* p_tg1     = GF(g_tg1);
    int*   p_rowmap  = GI(g_rowmap);
    float* p_rscale  = GF(g_rscale);
    __half *p_enc_h = GH(g_enc_h);
    __half *p_Wenc_h = GH(g_Wenc_h);
    __half *p_Wq_h = GH(g_Wq_h);
    __half *p_Wk_h = GH(g_Wk_h);
    __half *p_Wv_h = GH(g_Wv_h);
    __half *p_Wak_h = GH(g_Wak_h);
    __half *p_Wav_h = GH(g_Wav_h);
    __half *p_Wo_h = GH(g_Wo_h);
    __half *p_Wein_h = GH(g_Wein_h);
    __half *p_Weout_h = GH(g_Weout_h);
    __half *p_Wsin_h = GH(g_Wsin_h);
    __half *p_Wsout_h = GH(g_Wsout_h);
    __half *p_ctx_h = GH(g_ctx_h);
    __half *p_img_h = GH(g_img_h);
    __half *p_attn_h = GH(g_attn_h);
    __half *p_mod2_h = GH(g_mod2_h);
    __half *p_actsh_h = GH(g_actsh_h);
    __half *p_actmoe_h = GH(g_actmoe_h);

    cudaFuncSetAttribute(mma_gemm<0,false>, cudaFuncAttributeMaxDynamicSharedMemorySize, MMSM);
    cudaFuncSetAttribute(mma_gemm<1,false>, cudaFuncAttributeMaxDynamicSharedMemorySize, MMSM);
    cudaFuncSetAttribute(mma_gemm<2,false>, cudaFuncAttributeMaxDynamicSharedMemorySize, MMSM);
    cudaFuncSetAttribute(mma_gemm<3,false>, cudaFuncAttributeMaxDynamicSharedMemorySize, MMSM);
    cudaFuncSetAttribute(mma_gemm<0,true>,  cudaFuncAttributeMaxDynamicSharedMemorySize, MMSM);
    cudaFuncSetAttribute(flash_kernel, cudaFuncAttributeMaxDynamicSharedMemorySize, FSM);

    const float* NFP = nullptr;
    const int*   NIP = nullptr;

    #define CVT1(src, dh, n) \
        cvt1_kernel<<<(int)(((n)/4 + 255)/256), 256>>>(src, dh, (long long)(n))

    // 0. convert weights + enc to fp16
    CVT1(W_enc, p_Wenc_h, (long long)DIMM*JD);
    CVT1(Wq,  p_Wq_h,  (long long)DIMM*DIMM);
    CVT1(Wk,  p_Wk_h,  (long long)IKV*DIMM);
    CVT1(Wv,  p_Wv_h,  (long long)IKV*DIMM);
    CVT1(Wak, p_Wak_h, (long long)IKV*DIMM);
    CVT1(Wav, p_Wav_h, (long long)IKV*DIMM);
    CVT1(Wo,  p_Wo_h,  (long long)DIMM*DIMM);
    CVT1(We_in,  p_Wein_h,  (long long)NE*2*NI*DIMM);
    CVT1(We_out, p_Weout_h, (long long)NE*DIMM*NI);
    CVT1(Ws_in,  p_Wsin_h,  (long long)2*NI*DIMM);
    CVT1(Ws_out, p_Wsout_h, (long long)DIMM*NI);
    CVT1(enc, p_enc_h, (long long)BSZ*TXT*JD);

    // 1. modulation
    mod_kernel<<<1536, 256>>>(temb, W_mod, b_mod);
    // 2. context projection (+bias), then convert ctx
    mma_gemm<1,false><<<dim3(12, 8, 1), 256, MMSM>>>(p_enc_h, p_Wenc_h, p_ctx,
        BSZ*TXT, DIMM, JD, 0, 0, 0, b_enc, NFP, NFP, NIP, NFP, NIP);
    CVT1(p_ctx, p_ctx_h, (long long)BSZ*TXT*DIMM);
    // 3. LN1 * scale1 -> half
    ln_mod_kernel<<<NTOK, 256>>>(hidden, p_scale1, p_img_h, nullptr);
    // 4. projections
    mma_gemm<0,false><<<dim3(12, 16, 1), 256, MMSM>>>(p_img_h, p_Wq_h, p_q,
        NTOK, DIMM, DIMM, 0, 0, 0, NFP, NFP, NFP, NIP, NFP, NIP);
    mma_gemm<0,false><<<dim3(4, 16, 1), 256, MMSM>>>(p_img_h, p_Wk_h, p_kimg,
        NTOK, IKV, DIMM, 0, 0, 0, NFP, NFP, NFP, NIP, NFP, NIP);
    mma_gemm<0,false><<<dim3(4, 16, 1), 256, MMSM>>>(p_img_h, p_Wv_h, p_vimg,
        NTOK, IKV, DIMM, 0, 0, 0, NFP, NFP, NFP, NIP, NFP, NIP);
    mma_gemm<0,false><<<dim3(4, 8, 1), 256, MMSM>>>(p_ctx_h, p_Wak_h, p_ktxt,
        BSZ*TXT, IKV, DIMM, 0, 0, 0, NFP, NFP, NFP, NIP, NFP, NIP);
    mma_gemm<0,false><<<dim3(4, 8, 1), 256, MMSM>>>(p_ctx_h, p_Wav_h, p_vtxt,
        BSZ*TXT, IKV, DIMM, 0, 0, 0, NFP, NFP, NFP, NIP, NFP, NIP);
    // 5. norms + fp16 repack
    rms_q_kernel<<<3072, 256>>>(nq_w);
    kv_repack_kernel<<<1536, 256>>>(nk_w, nak_w);
    // 6. attention (mma, fp16)
    flash_kernel<<<dim3(SEQ/64, NH, BSZ), 128, FSM>>>();
    // 7. output proj + gated residual
    mma_gemm<2,false><<<dim3(12, 16, 1), 256, MMSM>>>(p_attn_h, p_Wo_h, p_hs1,
        NTOK, DIMM, DIMM, 0, 0, 0, NFP, hidden, p_tg1, NIP, NFP, NIP);
    // 8. LN2 -> mod2 half + normed2 fp32
    ln_mod_kernel<<<NTOK, 256>>>(p_hs1, p_scale2, p_mod2_h, p_normed2);
    // 9. router
    tembdot_kernel<<<1, 1024>>>(temb, Wg);
    router_kernel<<<NTOK, 128>>>(Wg);
    topk_kernel<<<BSZ*NE, 512>>>();
    zero_sums_kernel<<<8, 256>>>();
    sum_acc_kernel<<<64, 256>>>();
    gate_norm_kernel<<<64, 256>>>();
    // 10. expert GEMM 1 (gathered A rows, batched over 16 experts)
    mma_gemm<0,true><<<dim3(21, 8, 16), 256, MMSM>>>(p_mod2_h, p_Wein_h, p_hmoe,
        BSZ*CAP, 2*NI, DIMM,
        0, (long long)2*NI*DIMM, (long long)BSZ*CAP*2*NI,
        NFP, NFP, NFP, NIP, NFP, p_rowmap);
    swiglu_kernel<<<MROWS, 256>>>(p_hmoe, p_actmoe_h);
    // 11. shared expert
    mma_gemm<0,false><<<dim3(21, 16, 1), 256, MMSM>>>(p_mod2_h, p_Wsin_h, p_hsh,
        NTOK, 2*NI, DIMM, 0, 0, 0, NFP, NFP, NFP, NIP, NFP, NIP);
    swiglu_kernel<<<NTOK, 256>>>(p_hsh, p_actsh_h);
    mma_gemm<0,false><<<dim3(12, 16, 1), 256, MMSM>>>(p_actsh_h, p_Wsout_h, p_outflat,
        NTOK, DIMM, NI, 0, 0, 0, NFP, NFP, NFP, NIP, NFP, NIP);
    // 12. expert GEMM 2 with atomic scatter onto shared output
    mma_gemm<3,false><<<dim3(12, 8, 16), 256, MMSM>>>(p_actmoe_h, p_Weout_h, p_outflat,
        BSZ*CAP, DIMM, NI,
        (long long)BSZ*CAP*NI, (long long)DIMM*NI, 0,
        NFP, NFP, NFP, p_rowmap, p_rscale, NIP);
    // 13. final gated residual
    final_kernel<<<NTOK, 256>>>(out);
}

// round 14
// speedup vs baseline: 3.9348x; 1.0159x over previous
#include <cuda_runtime.h>
#include <cuda_fp16.h>
#include <math.h>
#include <stdint.h>

#define BSZ 2
#define SEQ 1024
#define TXT 512
#define DIMM 1536
#define NH 12
#define HDD 128
#define NKV 4
#define JD 3584
#define NE 16
#define NI 1344
#define CAP 512
#define LTOT 1536      // SEQ + TXT
#define NTOK 2048      // BSZ*SEQ
#define MROWS 16384    // NE*BSZ*CAP
#define IKV 512        // NKV*HDD
#define REP 3          // NH/NKV
#define EPSL 1e-6f

// ------------------------- fp32 scratch -------------------------------------
__device__ float g_scale1[BSZ*DIMM];
__device__ float g_tg1[BSZ*DIMM];
__device__ float g_scale2[BSZ*DIMM];
__device__ float g_tg2[BSZ*DIMM];
__device__ float g_q[NTOK*DIMM];
__device__ float g_kimg[NTOK*IKV];
__device__ float g_vimg[NTOK*IKV];
__device__ float g_ktxt[BSZ*TXT*IKV];
__device__ float g_vtxt[BSZ*TXT*IKV];
__device__ float g_hs1[NTOK*DIMM];
__device__ float g_normed2[NTOK*DIMM];
__device__ float g_tembdot[BSZ*NE];
__device__ float g_aff[BSZ*NE*SEQ];
__device__ int   g_topidx[BSZ*NE*CAP];
__device__ float g_gating[BSZ*NE*CAP];
__device__ float g_sums[NTOK];
__device__ int   g_rowmap[MROWS];
__device__ float g_rscale[MROWS];
__device__ float g_outflat[NTOK*DIMM];

// ------------------------- half planes --------------------------------------
__device__ __half g_enc_h[BSZ*TXT*JD];
__device__ __half g_Wenc_h[DIMM*JD];
__device__ __half g_Wq_h[DIMM*DIMM];
__device__ __half g_Wk_h[IKV*DIMM];
__device__ __half g_Wv_h[IKV*DIMM];
__device__ __half g_Wak_h[IKV*DIMM];
__device__ __half g_Wav_h[IKV*DIMM];
__device__ __half g_Wo_h[DIMM*DIMM];
__device__ __half g_Wein_h[(size_t)NE*2*NI*DIMM];   // interleaved (a,g) rows
__device__ __half g_Weout_h[(size_t)NE*DIMM*NI];
__device__ __half g_Wsin_h[2*NI*DIMM];              // interleaved (a,g) rows
__device__ __half g_Wsout_h[DIMM*NI];
__device__ __half g_ctx_h[BSZ*TXT*DIMM];
__device__ __half g_img_h[NTOK*DIMM];
__device__ __half g_attn_h[NTOK*DIMM];
__device__ __half g_mod2_h[NTOK*DIMM];
__device__ __half g_actsh_h[NTOK*NI];
__device__ __half g_actmoe_h[(size_t)MROWS*NI];
// attention fp16 operands
__device__ __half g_qh[NTOK*DIMM];
__device__ __half g_kh[(size_t)BSZ*NKV*LTOT*HDD];
__device__ __half g_vT[(size_t)BSZ*NKV*HDD*LTOT];

// ======================= helpers ============================================
__device__ __forceinline__ uint32_t s2u(const void* p) {
    uint32_t a;
    asm("{ .reg .u64 t; cvta.to.shared.u64 t, %1; cvt.u32.u64 %0, t; }"
        : "=r"(a) : "l"(p));
    return a;
}
__device__ __forceinline__ void cpa16(uint32_t d, const void* s) {
    asm volatile("cp.async.cg.shared.global [%0], [%1], 16;" :: "r"(d), "l"(s));
}
__device__ __forceinline__ void mma16816(float* c, const uint32_t* a, const uint32_t* b) {
    asm volatile(
        "mma.sync.aligned.m16n8k16.row.col.f32.f16.f16.f32 "
        "{%0,%1,%2,%3}, {%4,%5,%6,%7}, {%8,%9}, {%0,%1,%2,%3};"
        : "+f"(c[0]), "+f"(c[1]), "+f"(c[2]), "+f"(c[3])
        : "r"(a[0]), "r"(a[1]), "r"(a[2]), "r"(a[3]), "r"(b[0]), "r"(b[1]));
}
#define LDSM4(r0, r1, r2, r3, addr) \
    asm volatile("ldmatrix.sync.aligned.m8n8.x4.shared.b16 {%0,%1,%2,%3}, [%4];" \
        : "=r"(r0), "=r"(r1), "=r"(r2), "=r"(r3) : "r"(addr))

// ------------------------- fp32 -> half conversion ---------------------------
__global__ __launch_bounds__(256) void cvt1_kernel(const float* __restrict__ src,
                                                   __half* __restrict__ dh,
                                                   long long n) {
    long long i = ((long long)blockIdx.x * 256 + threadIdx.x) * 4;
    if (i >= n) return;
    float4 v = *(const float4*)(src + i);
    __half2* ph = (__half2*)(dh + i);
    ph[0] = __halves2half2(__float2half(v.x), __float2half(v.y));
    ph[1] = __halves2half2(__float2half(v.z), __float2half(v.w));
}

// fp32 -> half with (a,g) row interleave: out row 2i <- src row i,
// out row 2i+1 <- src row ni+i  (per matrix of 2*ni rows, batched over z)
__global__ __launch_bounds__(256) void cvt_ilv_kernel(const float* __restrict__ src,
                                                      __half* __restrict__ dst,
                                                      int ni) {
    long long orow = blockIdx.x;
    int rows = 2 * ni;
    long long z = orow / rows;
    int r = (int)(orow % rows);
    long long srow = z * rows + ((r & 1) ? ni + (r >> 1) : (r >> 1));
    const float4* s = (const float4*)(src + srow * DIMM);
    __half2* d = (__half2*)(dst + orow * DIMM);
    for (int i = threadIdx.x; i < DIMM / 4; i += 256) {
        float4 v = s[i];
        d[i*2]   = __halves2half2(__float2half(v.x), __float2half(v.y));
        d[i*2+1] = __halves2half2(__float2half(v.z), __float2half(v.w));
    }
}

// ======================= pipelined fp16 GEMM ================================
// C[M,N] = A[M,K]*B[N,K]^T, fp16 in, fp32 accumulate.
// EPI 0: fp32 store            2: fp32 resid + gate[b][n]*acc
// EPI 3: fp32 atomic scatter   4: swiglu on (even,odd) col pairs -> half N/2
// EPI 5: +bias -> half store
// AG: gather A rows through agather[z*M + m].
#define PRS 144
#define PLSZ (128*PRS)
#define BUFSZ (2*PLSZ)
#define MMSM (2*BUFSZ)

template<int EPI, bool AG>
__global__ __launch_bounds__(256, 2) void mma_gemm(
    const __half* __restrict__ Ah, const __half* __restrict__ Bh,
    void* __restrict__ Cv,
    int M, int N, int K,
    long long sA, long long sB, long long sC,
    const float* __restrict__ bias,
    const float* __restrict__ resid, const float* __restrict__ gate,
    const int* __restrict__ rowmap, const float* __restrict__ rscale,
    const int* __restrict__ agather)
{
    extern __shared__ char smem[];
    const int tid = threadIdx.x;
    const int wid = tid >> 5, lane = tid & 31;
    const int z = blockIdx.z;
    const int m0 = blockIdx.y * 128, n0 = blockIdx.x * 128;
    if (!AG) Ah += (long long)z * sA;
    Bh += (long long)z * sB;

    const int lr = tid >> 1;
    const int lh = tid & 1;
    long long arow = AG ? (long long)agather[(long long)z * M + m0 + lr]
                        : (long long)(m0 + lr);
    const __half* aHp = Ah + arow * (long long)K + lh * 32;
    const __half* bHp = Bh + (long long)(n0 + lr) * K + lh * 32;
    const uint32_t pofs = lr * PRS + lh * 64;

    const uint32_t uA = s2u(smem);
    const uint32_t uB = uA + PLSZ;

    const int wm = (wid >> 2) * 64;
    const int wn = (wid & 3) * 32;
    uint32_t a_off[4];
    #pragma unroll
    for (int mt = 0; mt < 4; mt++) {
        int r = wm + mt * 16 + (lane & 15);
        a_off[mt] = r * PRS + (lane >> 4) * 16;
    }
    uint32_t b_off[2];
    #pragma unroll
    for (int np = 0; np < 2; np++) {
        int r = wn + np * 16 + ((lane >> 4) << 3) + (lane & 7);
        b_off[np] = r * PRS + ((lane >> 3) & 1) * 16;
    }

    float acc[4][4][4];
    #pragma unroll
    for (int mt = 0; mt < 4; mt++)
        #pragma unroll
        for (int nt = 0; nt < 4; nt++)
            #pragma unroll
            for (int i = 0; i < 4; i++) acc[mt][nt][i] = 0.f;

    const int NC = K >> 6;
    auto issue = [&](int c, uint32_t boff) {
        long long ko = (long long)c * 64;
        #pragma unroll
        for (int i = 0; i < 4; i++) {
            cpa16(uA + boff + pofs + 16 * i, aHp + ko + 8 * i);
            cpa16(uB + boff + pofs + 16 * i, bHp + ko + 8 * i);
        }
        asm volatile("cp.async.commit_group;");
    };

    issue(0, 0);
    for (int c = 0; c < NC; c++) {
        const uint32_t boff = (c & 1) * BUFSZ;
        if (c + 1 < NC) {
            issue(c + 1, (~c & 1) * BUFSZ);
            asm volatile("cp.async.wait_group 1;");
        } else {
            asm volatile("cp.async.wait_group 0;");
        }
        __syncthreads();
        #pragma unroll
        for (int ks = 0; ks < 4; ks++) {
            uint32_t bf[4][2];
            #pragma unroll
            for (int np = 0; np < 2; np++)
                LDSM4(bf[np*2][0], bf[np*2][1], bf[np*2+1][0], bf[np*2+1][1],
                      uB + boff + b_off[np] + ks * 32);
            #pragma unroll
            for (int mt = 0; mt < 4; mt++) {
                uint32_t af[4];
                LDSM4(af[0], af[1], af[2], af[3], uA + boff + a_off[mt] + ks * 32);
                #pragma unroll
                for (int nt = 0; nt < 4; nt++) mma16816(acc[mt][nt], af, bf[nt]);
            }
        }
        __syncthreads();
    }

    const int g = lane >> 2;
    const int cp2 = (lane & 3) * 2;
    #pragma unroll
    for (int mt = 0; mt < 4; mt++) {
        #pragma unroll
        for (int hh = 0; hh < 2; hh++) {
            int row = m0 + wm + mt * 16 + g + hh * 8;
            if (EPI == 3) {
                long long gr = (long long)z * M + row;
                int trow = rowmap[gr];
                float s = rscale[gr];
                float* cp = (float*)Cv + (long long)trow * N;
                #pragma unroll
                for (int nt = 0; nt < 4; nt++) {
                    int col = n0 + wn + nt * 8 + cp2;
                    atomicAdd(cp + col,     acc[mt][nt][hh*2]   * s);
                    atomicAdd(cp + col + 1, acc[mt][nt][hh*2+1] * s);
                }
            } else if (EPI == 4) {
                __half* Ch = (__half*)Cv + (long long)z * sC
                           + (long long)row * (N >> 1);
                #pragma unroll
                for (int nt = 0; nt < 4; nt++) {
                    int col = n0 + wn + nt * 8 + cp2;     // even
                    float a = acc[mt][nt][hh*2];
                    float gg = acc[mt][nt][hh*2+1];
                    float act = a * (gg / (1.f + __expf(-gg)));
                    Ch[col >> 1] = __float2half(act);
                }
            } else if (EPI == 5) {
                __half* Ch = (__half*)Cv + (long long)z * sC + (long long)row * N;
                #pragma unroll
                for (int nt = 0; nt < 4; nt++) {
                    int col = n0 + wn + nt * 8 + cp2;
                    __half2 v = __halves2half2(
                        __float2half(acc[mt][nt][hh*2]   + bias[col]),
                        __float2half(acc[mt][nt][hh*2+1] + bias[col + 1]));
                    *(__half2*)&Ch[col] = v;
                }
            } else {
                float* Cz = (float*)Cv + (long long)z * sC + (long long)row * N;
                #pragma unroll
                for (int nt = 0; nt < 4; nt++) {
                    int col = n0 + wn + nt * 8 + cp2;
                    float v0 = acc[mt][nt][hh*2], v1 = acc[mt][nt][hh*2+1];
                    if (EPI == 2) {
                        const float* gp = gate + (row / SEQ) * N + col;
                        const float* rp = resid + (long long)row * N + col;
                        v0 = rp[0] + gp[0] * v0;
                        v1 = rp[1] + gp[1] * v1;
                    }
                    *(float2*)(Cz + col) = make_float2(v0, v1);
                }
            }
        }
    }
}

// ------------------------- modulation ----------------------------------------
__global__ __launch_bounds__(256) void mod_kernel(const float* __restrict__ temb,
                                                  const float* __restrict__ Wm,
                                                  const float* __restrict__ bm) {
    int gw = (blockIdx.x * blockDim.x + threadIdx.x) >> 5;
    int lane = threadIdx.x & 31;
    if (gw >= BSZ * 4 * DIMM) return;
    int b = gw / (4 * DIMM);
    int j = gw - b * 4 * DIMM;
    const float* t = temb + b * DIMM;
    const float* w = Wm + (size_t)j * DIMM;
    float acc = 0.f;
    for (int kk = lane; kk < DIMM; kk += 32) {
        float x = t[kk];
        acc += (x / (1.f + __expf(-x))) * w[kk];
    }
    #pragma unroll
    for (int o = 16; o; o >>= 1) acc += __shfl_xor_sync(0xffffffffu, acc, o);
    if (lane == 0) {
        acc += bm[j];
        int q = j / DIMM, c = j - q * DIMM;
        if (q == 0)      g_scale1[b*DIMM + c] = 1.f + acc;
        else if (q == 1) g_tg1[b*DIMM + c]    = tanhf(fminf(fmaxf(acc, -2.f), 2.f));
        else if (q == 2) g_scale2[b*DIMM + c] = 1.f + acc;
        else             g_tg2[b*DIMM + c]    = tanhf(fminf(fmaxf(acc, -2.f), 2.f));
    }
}

// ------------------------- LayerNorm -> half (+opt fp32 normed) --------------
__global__ __launch_bounds__(256) void ln_mod_kernel(const float* __restrict__ in,
                                                     const float* __restrict__ scale,
                                                     __half* __restrict__ mh,
                                                     float* __restrict__ outnorm) {
    int rowi = blockIdx.x;
    int b = rowi >> 10;
    const float* x = in + (size_t)rowi * DIMM;
    float s = 0.f, sq = 0.f;
    for (int d = threadIdx.x; d < DIMM; d += 256) { float v = x[d]; s += v; sq += v * v; }
    #pragma unroll
    for (int o = 16; o; o >>= 1) {
        s  += __shfl_xor_sync(0xffffffffu, s,  o);
        sq += __shfl_xor_sync(0xffffffffu, sq, o);
    }
    __shared__ float rs[8], rq[8], mv[2];
    int w = threadIdx.x >> 5;
    if ((threadIdx.x & 31) == 0) { rs[w] = s; rq[w] = sq; }
    __syncthreads();
    if (threadIdx.x == 0) {
        float S = 0.f, Q = 0.f;
        for (int i = 0; i < 8; i++) { S += rs[i]; Q += rq[i]; }
        float mean = S / DIMM;
        float var = Q / DIMM - mean * mean;
        mv[0] = mean; mv[1] = rsqrtf(var + EPSL);
    }
    __syncthreads();
    float mean = mv[0], rstd = mv[1];
    const float* sc = scale + (size_t)b * DIMM;
    for (int d = threadIdx.x; d < DIMM; d += 256) {
        float n = (x[d] - mean) * rstd;
        if (outnorm) outnorm[(size_t)rowi * DIMM + d] = n;
        mh[(size_t)rowi * DIMM + d] = __float2half(n * sc[d]);
    }
}

// ------------------------- per-head RMSNorm of Q -> fp16 ---------------------
__global__ __launch_bounds__(256) void rms_q_kernel(const float* __restrict__ w) {
    int gw = (blockIdx.x * blockDim.x + threadIdx.x) >> 5;
    if (gw >= NTOK * NH) return;
    int lane = threadIdx.x & 31;
    const float* p = g_q + (size_t)gw * HDD;
    int d4 = lane << 2;
    float4 v = *(const float4*)(p + d4);
    float ss = v.x*v.x + v.y*v.y + v.z*v.z + v.w*v.w;
    #pragma unroll
    for (int o = 16; o; o >>= 1) ss += __shfl_xor_sync(0xffffffffu, ss, o);
    float r = rsqrtf(ss / HDD + EPSL);
    float4 wv = *(const float4*)(w + d4);
    v.x *= r * wv.x; v.y *= r * wv.y; v.z *= r * wv.z; v.w *= r * wv.w;
    __half2* dst = (__half2*)(g_qh + (size_t)gw * HDD + d4);
    dst[0] = __halves2half2(__float2half(v.x), __float2half(v.y));
    dst[1] = __halves2half2(__float2half(v.z), __float2half(v.w));
}

// ------------------------- K RMS + K/V fp16 repack ---------------------------
__global__ __launch_bounds__(256) void kv_repack_kernel(const float* __restrict__ nk,
                                                        const float* __restrict__ nak) {
    int gw = (blockIdx.x * blockDim.x + threadIdx.x) >> 5;
    if (gw >= BSZ * NKV * LTOT) return;
    int lane = threadIdx.x & 31;
    int l = gw % LTOT;
    int bk = gw / LTOT;
    int kv = bk % NKV, b = bk / NKV;
    const float *ksrc, *vsrc, *w;
    if (l < SEQ) {
        ksrc = g_kimg + (size_t)(b * SEQ + l) * IKV + kv * HDD;
        vsrc = g_vimg + (size_t)(b * SEQ + l) * IKV + kv * HDD;
        w = nk;
    } else {
        int tt = l - SEQ;
        ksrc = g_ktxt + (size_t)(b * TXT + tt) * IKV + kv * HDD;
        vsrc = g_vtxt + (size_t)(b * TXT + tt) * IKV + kv * HDD;
        w = nak;
    }
    int d4 = lane << 2;
    float4 kvv = *(const float4*)(ksrc + d4);
    float ss = kvv.x*kvv.x + kvv.y*kvv.y + kvv.z*kvv.z + kvv.w*kvv.w;
    #pragma unroll
    for (int o = 16; o; o >>= 1) ss += __shfl_xor_sync(0xffffffffu, ss, o);
    float r = rsqrtf(ss / HDD + EPSL);
    float4 wv = *(const float4*)(w + d4);
    kvv.x *= r * wv.x; kvv.y *= r * wv.y; kvv.z *= r * wv.z; kvv.w *= r * wv.w;
    size_t kb = ((size_t)(b * NKV + kv) * LTOT + l) * HDD + d4;
    __half2* kd = (__half2*)(g_kh + kb);
    kd[0] = __halves2half2(__float2half(kvv.x), __float2half(kvv.y));
    kd[1] = __halves2half2(__float2half(kvv.z), __float2half(kvv.w));
    float4 vv = *(const float4*)(vsrc + d4);
    size_t vb = (size_t)(b * NKV + kv) * HDD;
    g_vT[(vb + d4    ) * LTOT + l] = __float2half(vv.x);
    g_vT[(vb + d4 + 1) * LTOT + l] = __float2half(vv.y);
    g_vT[(vb + d4 + 2) * LTOT + l] = __float2half(vv.z);
    g_vT[(vb + d4 + 3) * LTOT + l] = __float2half(vv.w);
}

// ------------------------- mma flash attention -------------------------------
#define FQSTR 272
#define FVSTR 144
#define FQSZ (64*FQSTR)
#define FKSZ (64*FQSTR)
#define FVSZ (128*FVSTR)
#define FBUF (FKSZ+FVSZ)
#define FSM  (FQSZ + 2*FBUF)

__global__ __launch_bounds__(128, 2) void flash_kernel() {
    extern __shared__ char fsm[];
    const int q0 = blockIdx.x * 64;
    const int h = blockIdx.y;
    const int b = blockIdx.z;
    const int kv = h / REP;
    const int t = threadIdx.x;
    const int w = t >> 5, lane = t & 31;
    const uint32_t uQ = s2u(fsm);
    const uint32_t uK0 = uQ + FQSZ;
    const __half* qg = g_qh + (size_t)(b * SEQ + q0) * DIMM + h * HDD;
    const __half* kg = g_kh + (size_t)(b * NKV + kv) * LTOT * HDD;
    const __half* vg = g_vT + (size_t)(b * NKV + kv) * HDD * LTOT;

    {
        int r = t >> 1, seg = t & 1;
        const __half* src = qg + (size_t)r * DIMM + seg * 64;
        uint32_t dst = uQ + r * FQSTR + seg * 128;
        #pragma unroll
        for (int i = 0; i < 8; i++) cpa16(dst + 16 * i, src + 8 * i);
        asm volatile("cp.async.commit_group;");
    }
    auto issue = [&](int c) {
        uint32_t base = uK0 + (c & 1) * FBUF;
        int k0 = c * 64;
        int r = t >> 1, seg = t & 1;
        const __half* ks = kg + (size_t)(k0 + r) * HDD + seg * 64;
        uint32_t kd = base + r * FQSTR + seg * 128;
        #pragma unroll
        for (int i = 0; i < 8; i++) cpa16(kd + 16 * i, ks + 8 * i);
        const __half* vs = vg + (size_t)t * LTOT + k0;
        uint32_t vd = base + FKSZ + t * FVSTR;
        #pragma unroll
        for (int i = 0; i < 8; i++) cpa16(vd + 16 * i, vs + 8 * i);
        asm volatile("cp.async.commit_group;");
    };

    const uint32_t aq_off = (w * 16 + (lane & 15)) * FQSTR + (lane >> 4) * 16;
    uint32_t bk_off[4];
    #pragma unroll
    for (int np = 0; np < 4; np++)
        bk_off[np] = (np * 16 + ((lane >> 4) << 3) + (lane & 7)) * FQSTR
                   + ((lane >> 3) & 1) * 16;
    uint32_t bv_off[8];
    #pragma unroll
    for (int np = 0; np < 8; np++)
        bv_off[np] = (np * 16 + ((lane >> 4) << 3) + (lane & 7)) * FVSTR
                   + ((lane >> 3) & 1) * 16;

    float o[16][4];
    #pragma unroll
    for (int i = 0; i < 16; i++)
        #pragma unroll
        for (int j = 0; j < 4; j++) o[i][j] = 0.f;
    float m0 = -1e30f, m1 = -1e30f, l0 = 0.f, l1 = 0.f;
    const float sc = 0.08838834764831845f;

    issue(0);
    const int NCH = LTOT / 64;
    for (int c = 0; c < NCH; c++) {
        if (c + 1 < NCH) { issue(c + 1); asm volatile("cp.async.wait_group 1;"); }
        else             { asm volatile("cp.async.wait_group 0;"); }
        __syncthreads();
        const uint32_t base = uK0 + (c & 1) * FBUF;
        float s[8][4];
        #pragma unroll
        for (int nt = 0; nt < 8; nt++)
            #pragma unroll
            for (int j = 0; j < 4; j++) s[nt][j] = 0.f;
        #pragma unroll
        for (int ks = 0; ks < 8; ks++) {
            uint32_t bf[8][2];
            #pragma unroll
            for (int np = 0; np < 4; np++)
                LDSM4(bf[np*2][0], bf[np*2][1], bf[np*2+1][0], bf[np*2+1][1],
                      base + bk_off[np] + ks * 32);
            uint32_t af[4];
            LDSM4(af[0], af[1], af[2], af[3], uQ + aq_off + ks * 32);
            #pragma unroll
            for (int nt = 0; nt < 8; nt++) mma16816(s[nt], af, bf[nt]);
        }
        float mx0 = -1e30f, mx1 = -1e30f;
        #pragma unroll
        for (int nt = 0; nt < 8; nt++) {
            mx0 = fmaxf(mx0, fmaxf(s[nt][0], s[nt][1]));
            mx1 = fmaxf(mx1, fmaxf(s[nt][2], s[nt][3]));
        }
        #pragma unroll
        for (int off = 1; off < 4; off <<= 1) {
            mx0 = fmaxf(mx0, __shfl_xor_sync(0xffffffffu, mx0, off));
            mx1 = fmaxf(mx1, __shfl_xor_sync(0xffffffffu, mx1, off));
        }
        float nm0 = fmaxf(m0, mx0 * sc), nm1 = fmaxf(m1, mx1 * sc);
        float cr0 = __expf(m0 - nm0), cr1 = __expf(m1 - nm1);
        float sum0 = 0.f, sum1 = 0.f;
        uint32_t pr0[8], pr1[8];
        #pragma unroll
        for (int nt = 0; nt < 8; nt++) {
            float p0 = __expf(s[nt][0] * sc - nm0);
            float p1 = __expf(s[nt][1] * sc - nm0);
            float p2 = __expf(s[nt][2] * sc - nm1);
            float p3 = __expf(s[nt][3] * sc - nm1);
            sum0 += p0 + p1; sum1 += p2 + p3;
            __half2 h0 = __halves2half2(__float2half(p0), __float2half(p1));
            __half2 h1 = __halves2half2(__float2half(p2), __float2half(p3));
            pr0[nt] = *(uint32_t*)&h0;
            pr1[nt] = *(uint32_t*)&h1;
        }
        #pragma unroll
        for (int off = 1; off < 4; off <<= 1) {
            sum0 += __shfl_xor_sync(0xffffffffu, sum0, off);
            sum1 += __shfl_xor_sync(0xffffffffu, sum1, off);
        }
        l0 = l0 * cr0 + sum0; l1 = l1 * cr1 + sum1;
        m0 = nm0; m1 = nm1;
        #pragma unroll
        for (int nt2 = 0; nt2 < 16; nt2++) {
            o[nt2][0] *= cr0; o[nt2][1] *= cr0;
            o[nt2][2] *= cr1; o[nt2][3] *= cr1;
        }
        const uint32_t vbase = base + FKSZ;
        #pragma unroll
        for (int ks2 = 0; ks2 < 4; ks2++) {
            uint32_t a[4] = { pr0[2*ks2], pr1[2*ks2], pr0[2*ks2+1], pr1[2*ks2+1] };
            #pragma unroll
            for (int np = 0; np < 8; np++) {
                uint32_t bf2[2][2];
                LDSM4(bf2[0][0], bf2[0][1], bf2[1][0], bf2[1][1],
                      vbase + bv_off[np] + ks2 * 32);
                mma16816(o[np*2],     a, bf2[0]);
                mma16816(o[np*2 + 1], a, bf2[1]);
            }
        }
        __syncthreads();
    }
    float i0 = 1.f / l0, i1 = 1.f / l1;
    const int g = lane >> 2, cp2 = (lane & 3) * 2;
    size_t ob = (size_t)(b * SEQ + q0 + w * 16 + g) * DIMM + h * HDD;
    #pragma unroll
    for (int nt2 = 0; nt2 < 16; nt2++) {
        __half2 v0 = __halves2half2(__float2half(o[nt2][0] * i0),
                                    __float2half(o[nt2][1] * i0));
        __half2 v1 = __halves2half2(__float2half(o[nt2][2] * i1),
                                    __float2half(o[nt2][3] * i1));
        *(__half2*)&g_attn_h[ob + nt2 * 8 + cp2] = v0;
        *(__half2*)&g_attn_h[ob + 8 * DIMM + nt2 * 8 + cp2] = v1;
    }
}

// ------------------------- router ------------------------------------------
__global__ __launch_bounds__(1024) void tembdot_kernel(const float* __restrict__ temb,
                                                       const float* __restrict__ Wg) {
    int wid = threadIdx.x >> 5, lane = threadIdx.x & 31;
    int b = wid / NE, e = wid % NE;
    const float* t = temb + b * DIMM;
    const float* w = Wg + (size_t)e * 2 * DIMM;
    float acc = 0.f;
    for (int d = lane; d < DIMM; d += 32) acc += t[d] * w[d];
    #pragma unroll
    for (int o = 16; o; o >>= 1) acc += __shfl_xor_sync(0xffffffffu, acc, o);
    if (lane == 0) g_tembdot[wid] = acc;
}

__global__ __launch_bounds__(128) void router_kernel(const float* __restrict__ Wg) {
    __shared__ float lg[NE];
    int tokid = blockIdx.x;
    int b = tokid >> 10, s = tokid & 1023;
    int w = threadIdx.x >> 5, lane = threadIdx.x & 31;
    const float* x = g_normed2 + (size_t)tokid * DIMM;
    for (int e = w * 4; e < w * 4 + 4; e++) {
        const float* wg = Wg + (size_t)e * 2 * DIMM + DIMM;
        float acc = 0.f;
        for (int d = lane; d < DIMM; d += 32) acc += x[d] * wg[d];
        #pragma unroll
        for (int o = 16; o; o >>= 1) acc += __shfl_xor_sync(0xffffffffu, acc, o);
        if (lane == 0) lg[e] = acc + g_tembdot[b * NE + e];
    }
    __syncthreads();
    if (threadIdx.x == 0) {
        float mx = -1e30f;
        for (int e = 0; e < NE; e++) mx = fmaxf(mx, lg[e]);
        float ex[NE], sm = 0.f;
        for (int e = 0; e < NE; e++) { ex[e] = __expf(lg[e] - mx); sm += ex[e]; }
        float inv = 1.f / sm;
        for (int e = 0; e < NE; e++)
            g_aff[((size_t)(b * NE + e)) * SEQ + s] = ex[e] * inv;
    }
}

// ------------------------- exact top-k via bitonic sort ---------------------
__global__ __launch_bounds__(512) void topk_kernel() {
    __shared__ float v[1024];
    __shared__ int   id[1024];
    int be = blockIdx.x;
    const float* rowp = g_aff + (size_t)be * SEQ;
    int t = threadIdx.x;
    for (int i = t; i < 1024; i += 512) { v[i] = rowp[i]; id[i] = i; }
    __syncthreads();
    for (int k = 2; k <= 1024; k <<= 1) {
        for (int j = k >> 1; j > 0; j >>= 1) {
            for (int i = t; i < 1024; i += 512) {
                int ixj = i ^ j;
                if (ixj > i) {
                    bool up = ((i & k) == 0);
                    float va = v[i], vb = v[ixj];
                    int ia = id[i], ib = id[ixj];
                    bool a_first = (va > vb) || (va == vb && ia < ib);
                    bool sw = up ? !a_first : a_first;
                    if (sw) { v[i] = vb; v[ixj] = va; id[i] = ib; id[ixj] = ia; }
                }
            }
            __syncthreads();
        }
    }
    if (t < CAP) {
        g_gating[be * CAP + t] = v[t];
        g_topidx[be * CAP + t] = id[t];
    }
}

__global__ void zero_sums_kernel() {
    int i = blockIdx.x * blockDim.x + threadIdx.x;
    if (i < NTOK) g_sums[i] = 0.f;
}

__global__ void sum_acc_kernel() {
    int i = blockIdx.x * blockDim.x + threadIdx.x;
    if (i >= BSZ * NE * CAP) return;
    int be = i / CAP;
    int b = be / NE;
    int tok = b * SEQ + g_topidx[i];
    atomicAdd(&g_sums[tok], g_gating[i]);
}

__global__ void gate_norm_kernel() {
    int i = blockIdx.x * blockDim.x + threadIdx.x;
    if (i >= BSZ * NE * CAP) return;
    int c = i % CAP;
    int be = i / CAP;
    int b = be / NE, e = be % NE;
    int tok = b * SEQ + g_topidx[i];
    float g = g_gating[i] / (g_sums[tok] + 1e-12f) * 2.5f;
    int rowflat = (e * BSZ + b) * CAP + c;
    g_rowmap[rowflat] = tok;
    g_rscale[rowflat] = g;
}

// ------------------------- final residual -----------------------------------
__global__ __launch_bounds__(256) void final_kernel(float* __restrict__ out) {
    int r = blockIdx.x;
    int b = r >> 10;
    const float4* hs = (const float4*)(g_hs1 + (size_t)r * DIMM);
    const float4* mo = (const float4*)(g_outflat + (size_t)r * DIMM);
    const float4* gg = (const float4*)(g_tg2 + (size_t)b * DIMM);
    float4* o = (float4*)(out + (size_t)r * DIMM);
    for (int i = threadIdx.x; i < DIMM / 4; i += 256) {
        float4 h = hs[i], m = mo[i], g = gg[i], v;
        v.x = h.x + g.x * m.x; v.y = h.y + g.y * m.y;
        v.z = h.z + g.z * m.z; v.w = h.w + g.w * m.w;
        o[i] = v;
    }
}

// ------------------------- launcher -----------------------------------------
extern "C" void kernel_launch(void* const* d_in, const int* in_sizes, int n_in,
                              void* d_out, int out_size) {
    const float* hidden = (const float*)d_in[0];
    const float* enc    = (const float*)d_in[1];
    const float* temb   = (const float*)d_in[2];
    const float* W_mod  = (const float*)d_in[3];
    const float* b_mod  = (const float*)d_in[4];
    const float* W_enc  = (const float*)d_in[5];
    const float* b_enc  = (const float*)d_in[6];
    const float* Wq     = (const float*)d_in[7];
    const float* Wk     = (const float*)d_in[8];
    const float* Wv     = (const float*)d_in[9];
    const float* Wak    = (const float*)d_in[10];
    const float* Wav    = (const float*)d_in[11];
    const float* nq_w   = (const float*)d_in[12];
    const float* nk_w   = (const float*)d_in[13];
    const float* nak_w  = (const float*)d_in[14];
    const float* Wo     = (const float*)d_in[15];
    const float* Wg     = (const float*)d_in[16];
    const float* We_in  = (const float*)d_in[17];
    const float* We_out = (const float*)d_in[18];
    const float* Ws_in  = (const float*)d_in[19];
    const float* Ws_out = (const float*)d_in[20];
    float* out = (float*)d_out;

    void* pv;
    #define GF(sym) (cudaGetSymbolAddress(&pv, sym), (float*)pv)
    #define GH(sym) (cudaGetSymbolAddress(&pv, sym), (__half*)pv)
    #define GI(sym) (cudaGetSymbolAddress(&pv, sym), (int*)pv)
    float* p_q       = GF(g_q);
    float* p_kimg    = GF(g_kimg);
    float* p_vimg    = GF(g_vimg);
    float* p_ktxt    = GF(g_ktxt);
    float* p_vtxt    = GF(g_vtxt);
    float* p_hs1     = GF(g_hs1);
    float* p_normed2 = GF(g_normed2);
    float* p_outflat = GF(g_outflat);
    float* p_scale1  = GF(g_scale1);
    float* p_scale2  = GF(g_scale2);
    float* p_tg1     = GF(g_tg1);
    int*   p_rowmap  = GI(g_rowmap);
    float* p_rscale  = GF(g_rscale);
    __half *p_enc_h = GH(g_enc_h);
    __half *p_Wenc_h = GH(g_Wenc_h);
    __half *p_Wq_h = GH(g_Wq_h);
    __half *p_Wk_h = GH(g_Wk_h);
    __half *p_Wv_h = GH(g_Wv_h);
    __half *p_Wak_h = GH(g_Wak_h);
    __half *p_Wav_h = GH(g_Wav_h);
    __half *p_Wo_h = GH(g_Wo_h);
    __half *p_Wein_h = GH(g_Wein_h);
    __half *p_Weout_h = GH(g_Weout_h);
    __half *p_Wsin_h = GH(g_Wsin_h);
    __half *p_Wsout_h = GH(g_Wsout_h);
    __half *p_ctx_h = GH(g_ctx_h);
    __half *p_img_h = GH(g_img_h);
    __half *p_attn_h = GH(g_attn_h);
    __half *p_mod2_h = GH(g_mod2_h);
    __half *p_actsh_h = GH(g_actsh_h);
    __half *p_actmoe_h = GH(g_actmoe_h);

    cudaFuncSetAttribute(mma_gemm<0,false>, cudaFuncAttributeMaxDynamicSharedMemorySize, MMSM);
    cudaFuncSetAttribute(mma_gemm<2,false>, cudaFuncAttributeMaxDynamicSharedMemorySize, MMSM);
    cudaFuncSetAttribute(mma_gemm<3,false>, cudaFuncAttributeMaxDynamicSharedMemorySize, MMSM);
    cudaFuncSetAttribute(mma_gemm<4,false>, cudaFuncAttributeMaxDynamicSharedMemorySize, MMSM);
    cudaFuncSetAttribute(mma_gemm<4,true>,  cudaFuncAttributeMaxDynamicSharedMemorySize, MMSM);
    cudaFuncSetAttribute(mma_gemm<5,false>, cudaFuncAttributeMaxDynamicSharedMemorySize, MMSM);
    cudaFuncSetAttribute(flash_kernel, cudaFuncAttributeMaxDynamicSharedMemorySize, FSM);

    const float* NFP = nullptr;
    const int*   NIP = nullptr;

    #define CVT1(src, dh, n) \
        cvt1_kernel<<<(int)(((n)/4 + 255)/256), 256>>>(src, dh, (long long)(n))

    // 0. convert weights + enc to fp16 (expert/shared in-weights interleaved)
    CVT1(W_enc, p_Wenc_h, (long long)DIMM*JD);
    CVT1(Wq,  p_Wq_h,  (long long)DIMM*DIMM);
    CVT1(Wk,  p_Wk_h,  (long long)IKV*DIMM);
    CVT1(Wv,  p_Wv_h,  (long long)IKV*DIMM);
    CVT1(Wak, p_Wak_h, (long long)IKV*DIMM);
    CVT1(Wav, p_Wav_h, (long long)IKV*DIMM);
    CVT1(Wo,  p_Wo_h,  (long long)DIMM*DIMM);
    cvt_ilv_kernel<<<NE*2*NI, 256>>>(We_in, p_Wein_h, NI);
    CVT1(We_out, p_Weout_h, (long long)NE*DIMM*NI);
    cvt_ilv_kernel<<<2*NI, 256>>>(Ws_in, p_Wsin_h, NI);
    CVT1(Ws_out, p_Wsout_h, (long long)DIMM*NI);
    CVT1(enc, p_enc_h, (long long)BSZ*TXT*JD);

    // 1. modulation
    mod_kernel<<<1536, 256>>>(temb, W_mod, b_mod);
    // 2. context projection (+bias) -> half directly
    mma_gemm<5,false><<<dim3(12, 8, 1), 256, MMSM>>>(p_enc_h, p_Wenc_h, p_ctx_h,
        BSZ*TXT, DIMM, JD, 0, 0, 0, b_enc, NFP, NFP, NIP, NFP, NIP);
    // 3. LN1 * scale1 -> half
    ln_mod_kernel<<<NTOK, 256>>>(hidden, p_scale1, p_img_h, nullptr);
    // 4. projections
    mma_gemm<0,false><<<dim3(12, 16, 1), 256, MMSM>>>(p_img_h, p_Wq_h, p_q,
        NTOK, DIMM, DIMM, 0, 0, 0, NFP, NFP, NFP, NIP, NFP, NIP);
    mma_gemm<0,false><<<dim3(4, 16, 1), 256, MMSM>>>(p_img_h, p_Wk_h, p_kimg,
        NTOK, IKV, DIMM, 0, 0, 0, NFP, NFP, NFP, NIP, NFP, NIP);
    mma_gemm<0,false><<<dim3(4, 16, 1), 256, MMSM>>>(p_img_h, p_Wv_h, p_vimg,
        NTOK, IKV, DIMM, 0, 0, 0, NFP, NFP, NFP, NIP, NFP, NIP);
    mma_gemm<0,false><<<dim3(4, 8, 1), 256, MMSM>>>(p_ctx_h, p_Wak_h, p_ktxt,
        BSZ*TXT, IKV, DIMM, 0, 0, 0, NFP, NFP, NFP, NIP, NFP, NIP);
    mma_gemm<0,false><<<dim3(4, 8, 1), 256, MMSM>>>(p_ctx_h, p_Wav_h, p_vtxt,
        BSZ*TXT, IKV, DIMM, 0, 0, 0, NFP, NFP, NFP, NIP, NFP, NIP);
    // 5. norms + fp16 repack
    rms_q_kernel<<<3072, 256>>>(nq_w);
    kv_repack_kernel<<<1536, 256>>>(nk_w, nak_w);
    // 6. attention (mma, fp16)
    flash_kernel<<<dim3(SEQ/64, NH, BSZ), 128, FSM>>>();
    // 7. output proj + gated residual
    mma_gemm<2,false><<<dim3(12, 16, 1), 256, MMSM>>>(p_attn_h, p_Wo_h, p_hs1,
        NTOK, DIMM, DIMM, 0, 0, 0, NFP, hidden, p_tg1, NIP, NFP, NIP);
    // 8. LN2 -> mod2 half + normed2 fp32
    ln_mod_kernel<<<NTOK, 256>>>(p_hs1, p_scale2, p_mod2_h, p_normed2);
    // 9. router
    tembdot_kernel<<<1, 1024>>>(temb, Wg);
    router_kernel<<<NTOK, 128>>>(Wg);
    topk_kernel<<<BSZ*NE, 512>>>();
    zero_sums_kernel<<<8, 256>>>();
    sum_acc_kernel<<<64, 256>>>();
    gate_norm_kernel<<<64, 256>>>();
    // 10. expert GEMM 1 (gathered A, interleaved weights, fused swiglu -> half)
    mma_gemm<4,true><<<dim3(21, 8, 16), 256, MMSM>>>(p_mod2_h, p_Wein_h, p_actmoe_h,
        BSZ*CAP, 2*NI, DIMM,
        0, (long long)2*NI*DIMM, (long long)BSZ*CAP*NI,
        NFP, NFP, NFP, NIP, NFP, p_rowmap);
    // 11. shared expert (fused swiglu -> half), then out-proj
    mma_gemm<4,false><<<dim3(21, 16, 1), 256, MMSM>>>(p_mod2_h, p_Wsin_h, p_actsh_h,
        NTOK, 2*NI, DIMM, 0, 0, 0, NFP, NFP, NFP, NIP, NFP, NIP);
    mma_gemm<0,false><<<dim3(12, 16, 1), 256, MMSM>>>(p_actsh_h, p_Wsout_h, p_outflat,
        NTOK, DIMM, NI, 0, 0, 0, NFP, NFP, NFP, NIP, NFP, NIP);
    // 12. expert GEMM 2 with atomic scatter onto shared output
    mma_gemm<3,false><<<dim3(12, 8, 16), 256, MMSM>>>(p_actmoe_h, p_Weout_h, p_outflat,
        BSZ*CAP, DIMM, NI,
        (long long)BSZ*CAP*NI, (long long)DIMM*NI, 0,
        NFP, NFP, NFP, p_rowmap, p_rscale, NIP);
    // 13. final gated residual
    final_kernel<<<NTOK, 256>>>(out);
}

// round 15
// speedup vs baseline: 4.1203x; 1.0472x over previous
#include <cuda_runtime.h>
#include <cuda_fp16.h>
#include <math.h>
#include <stdint.h>

#define BSZ 2
#define SEQ 1024
#define TXT 512
#define DIMM 1536
#define NH 12
#define HDD 128
#define NKV 4
#define JD 3584
#define NE 16
#define NI 1344
#define CAP 512
#define LTOT 1536      // SEQ + TXT
#define NTOK 2048      // BSZ*SEQ
#define MROWS 16384    // NE*BSZ*CAP
#define IKV 512        // NKV*HDD
#define REP 3          // NH/NKV
#define QKVN 2560      // DIMM + 2*IKV
#define AKVN 1024      // 2*IKV
#define EPSL 1e-6f

// ------------------------- fp32 scratch -------------------------------------
__device__ float g_scale1[BSZ*DIMM];
__device__ float g_tg1[BSZ*DIMM];
__device__ float g_scale2[BSZ*DIMM];
__device__ float g_tg2[BSZ*DIMM];
__device__ float g_hs1[NTOK*DIMM];
__device__ float g_normed2[NTOK*DIMM];
__device__ float g_tembdot[BSZ*NE];
__device__ float g_aff[BSZ*NE*SEQ];
__device__ int   g_topidx[BSZ*NE*CAP];
__device__ float g_gating[BSZ*NE*CAP];
__device__ float g_sums[NTOK];
__device__ int   g_rowmap[MROWS];
__device__ float g_rscale[MROWS];
__device__ float g_outflat[NTOK*DIMM];

// ------------------------- half planes --------------------------------------
__device__ __half g_enc_h[BSZ*TXT*JD];
__device__ __half g_Wenc_h[DIMM*JD];
__device__ __half g_Wqkv_h[(size_t)QKVN*DIMM];      // [Wq ; Wk ; Wv] rows
__device__ __half g_Wakv_h[(size_t)AKVN*DIMM];      // [Wak ; Wav] rows
__device__ __half g_Wo_h[DIMM*DIMM];
__device__ __half g_Wein_h[(size_t)NE*2*NI*DIMM];   // interleaved (a,g) rows
__device__ __half g_Weout_h[(size_t)NE*DIMM*NI];
__device__ __half g_Wsin_h[2*NI*DIMM];              // interleaved (a,g) rows
__device__ __half g_Wsout_h[DIMM*NI];
__device__ __half g_ctx_h[BSZ*TXT*DIMM];
__device__ __half g_img_h[NTOK*DIMM];
__device__ __half g_attn_h[NTOK*DIMM];
__device__ __half g_mod2_h[NTOK*DIMM];
__device__ __half g_actsh_h[NTOK*NI];
__device__ __half g_actmoe_h[(size_t)MROWS*NI];
// attention operands / merged projection outputs
__device__ __half g_qkv_h[(size_t)NTOK*QKVN];
__device__ __half g_akv_h[(size_t)BSZ*TXT*AKVN];
__device__ __half g_qh[NTOK*DIMM];
__device__ __half g_kh[(size_t)BSZ*NKV*LTOT*HDD];
__device__ __half g_vT[(size_t)BSZ*NKV*HDD*LTOT];

// ======================= helpers ============================================
__device__ __forceinline__ uint32_t s2u(const void* p) {
    uint32_t a;
    asm("{ .reg .u64 t; cvta.to.shared.u64 t, %1; cvt.u32.u64 %0, t; }"
        : "=r"(a) : "l"(p));
    return a;
}
__device__ __forceinline__ void cpa16(uint32_t d, const void* s) {
    asm volatile("cp.async.cg.shared.global [%0], [%1], 16;" :: "r"(d), "l"(s));
}
__device__ __forceinline__ void mma16816(float* c, const uint32_t* a, const uint32_t* b) {
    asm volatile(
        "mma.sync.aligned.m16n8k16.row.col.f32.f16.f16.f32 "
        "{%0,%1,%2,%3}, {%4,%5,%6,%7}, {%8,%9}, {%0,%1,%2,%3};"
        : "+f"(c[0]), "+f"(c[1]), "+f"(c[2]), "+f"(c[3])
        : "r"(a[0]), "r"(a[1]), "r"(a[2]), "r"(a[3]), "r"(b[0]), "r"(b[1]));
}
#define LDSM4(r0, r1, r2, r3, addr) \
    asm volatile("ldmatrix.sync.aligned.m8n8.x4.shared.b16 {%0,%1,%2,%3}, [%4];" \
        : "=r"(r0), "=r"(r1), "=r"(r2), "=r"(r3) : "r"(addr))

// ------------------------- fp32 -> half conversion (MLP 4) -------------------
__global__ __launch_bounds__(256) void cvt1_kernel(const float* __restrict__ src,
                                                   __half* __restrict__ dh,
                                                   long long n) {
    long long base = (long long)blockIdx.x * 4096 + threadIdx.x * 4;
    #pragma unroll
    for (int j = 0; j < 4; j++) {
        long long i = base + j * 1024;
        if (i < n) {
            float4 v = *(const float4*)(src + i);
            __half2* ph = (__half2*)(dh + i);
            ph[0] = __halves2half2(__float2half(v.x), __float2half(v.y));
            ph[1] = __halves2half2(__float2half(v.z), __float2half(v.w));
        }
    }
}

// fp32 -> half with (a,g) row interleave per matrix of 2*ni rows (batched z)
__global__ __launch_bounds__(256) void cvt_ilv_kernel(const float* __restrict__ src,
                                                      __half* __restrict__ dst,
                                                      int ni) {
    long long orow = blockIdx.x;
    int rows = 2 * ni;
    long long z = orow / rows;
    int r = (int)(orow % rows);
    long long srow = z * rows + ((r & 1) ? ni + (r >> 1) : (r >> 1));
    const float4* s = (const float4*)(src + srow * DIMM);
    __half2* d = (__half2*)(dst + orow * DIMM);
    for (int i = threadIdx.x; i < DIMM / 4; i += 256) {
        float4 v = s[i];
        d[i*2]   = __halves2half2(__float2half(v.x), __float2half(v.y));
        d[i*2+1] = __halves2half2(__float2half(v.z), __float2half(v.w));
    }
}

// ======================= pipelined fp16 GEMM ================================
// C[M,N] = A[M,K]*B[N,K]^T, fp16 in, fp32 accumulate.
// EPI 0: fp32 store            2: fp32 resid + gate[b][n]*acc
// EPI 3: fp32 atomic scatter   4: swiglu on (even,odd) col pairs -> half N/2
// EPI 5: +bias -> half store   6: plain half store
// AG: gather A rows through agather[z*M + m].
#define PRS 144
#define PLSZ (128*PRS)
#define BUFSZ (2*PLSZ)
#define MMSM (2*BUFSZ)

template<int EPI, bool AG>
__global__ __launch_bounds__(256, 2) void mma_gemm(
    const __half* __restrict__ Ah, const __half* __restrict__ Bh,
    void* __restrict__ Cv,
    int M, int N, int K,
    long long sA, long long sB, long long sC,
    const float* __restrict__ bias,
    const float* __restrict__ resid, const float* __restrict__ gate,
    const int* __restrict__ rowmap, const float* __restrict__ rscale,
    const int* __restrict__ agather)
{
    extern __shared__ char smem[];
    const int tid = threadIdx.x;
    const int wid = tid >> 5, lane = tid & 31;
    const int z = blockIdx.z;
    const int m0 = blockIdx.y * 128, n0 = blockIdx.x * 128;
    if (!AG) Ah += (long long)z * sA;
    Bh += (long long)z * sB;

    const int lr = tid >> 1;
    const int lh = tid & 1;
    long long arow = AG ? (long long)agather[(long long)z * M + m0 + lr]
                        : (long long)(m0 + lr);
    const __half* aHp = Ah + arow * (long long)K + lh * 32;
    const __half* bHp = Bh + (long long)(n0 + lr) * K + lh * 32;
    const uint32_t pofs = lr * PRS + lh * 64;

    const uint32_t uA = s2u(smem);
    const uint32_t uB = uA + PLSZ;

    const int wm = (wid >> 2) * 64;
    const int wn = (wid & 3) * 32;
    uint32_t a_off[4];
    #pragma unroll
    for (int mt = 0; mt < 4; mt++) {
        int r = wm + mt * 16 + (lane & 15);
        a_off[mt] = r * PRS + (lane >> 4) * 16;
    }
    uint32_t b_off[2];
    #pragma unroll
    for (int np = 0; np < 2; np++) {
        int r = wn + np * 16 + ((lane >> 4) << 3) + (lane & 7);
        b_off[np] = r * PRS + ((lane >> 3) & 1) * 16;
    }

    float acc[4][4][4];
    #pragma unroll
    for (int mt = 0; mt < 4; mt++)
        #pragma unroll
        for (int nt = 0; nt < 4; nt++)
            #pragma unroll
            for (int i = 0; i < 4; i++) acc[mt][nt][i] = 0.f;

    const int NC = K >> 6;
    auto issue = [&](int c, uint32_t boff) {
        long long ko = (long long)c * 64;
        #pragma unroll
        for (int i = 0; i < 4; i++) {
            cpa16(uA + boff + pofs + 16 * i, aHp + ko + 8 * i);
            cpa16(uB + boff + pofs + 16 * i, bHp + ko + 8 * i);
        }
        asm volatile("cp.async.commit_group;");
    };

    issue(0, 0);
    for (int c = 0; c < NC; c++) {
        const uint32_t boff = (c & 1) * BUFSZ;
        if (c + 1 < NC) {
            issue(c + 1, (~c & 1) * BUFSZ);
            asm volatile("cp.async.wait_group 1;");
        } else {
            asm volatile("cp.async.wait_group 0;");
        }
        __syncthreads();
        #pragma unroll
        for (int ks = 0; ks < 4; ks++) {
            uint32_t bf[4][2];
            #pragma unroll
            for (int np = 0; np < 2; np++)
                LDSM4(bf[np*2][0], bf[np*2][1], bf[np*2+1][0], bf[np*2+1][1],
                      uB + boff + b_off[np] + ks * 32);
            #pragma unroll
            for (int mt = 0; mt < 4; mt++) {
                uint32_t af[4];
                LDSM4(af[0], af[1], af[2], af[3], uA + boff + a_off[mt] + ks * 32);
                #pragma unroll
                for (int nt = 0; nt < 4; nt++) mma16816(acc[mt][nt], af, bf[nt]);
            }
        }
        __syncthreads();
    }

    const int g = lane >> 2;
    const int cp2 = (lane & 3) * 2;
    #pragma unroll
    for (int mt = 0; mt < 4; mt++) {
        #pragma unroll
        for (int hh = 0; hh < 2; hh++) {
            int row = m0 + wm + mt * 16 + g + hh * 8;
            if (EPI == 3) {
                long long gr = (long long)z * M + row;
                int trow = rowmap[gr];
                float s = rscale[gr];
                float* cp = (float*)Cv + (long long)trow * N;
                #pragma unroll
                for (int nt = 0; nt < 4; nt++) {
                    int col = n0 + wn + nt * 8 + cp2;
                    atomicAdd(cp + col,     acc[mt][nt][hh*2]   * s);
                    atomicAdd(cp + col + 1, acc[mt][nt][hh*2+1] * s);
                }
            } else if (EPI == 4) {
                __half* Ch = (__half*)Cv + (long long)z * sC
                           + (long long)row * (N >> 1);
                #pragma unroll
                for (int nt = 0; nt < 4; nt++) {
                    int col = n0 + wn + nt * 8 + cp2;     // even
                    float a = acc[mt][nt][hh*2];
                    float gg = acc[mt][nt][hh*2+1];
                    float act = a * (gg / (1.f + __expf(-gg)));
                    Ch[col >> 1] = __float2half(act);
                }
            } else if (EPI == 5 || EPI == 6) {
                __half* Ch = (__half*)Cv + (long long)z * sC + (long long)row * N;
                #pragma unroll
                for (int nt = 0; nt < 4; nt++) {
                    int col = n0 + wn + nt * 8 + cp2;
                    float v0 = acc[mt][nt][hh*2], v1 = acc[mt][nt][hh*2+1];
                    if (EPI == 5) { v0 += bias[col]; v1 += bias[col + 1]; }
                    __half2 v = __halves2half2(__float2half(v0), __float2half(v1));
                    *(__half2*)&Ch[col] = v;
                }
            } else {
                float* Cz = (float*)Cv + (long long)z * sC + (long long)row * N;
                #pragma unroll
                for (int nt = 0; nt < 4; nt++) {
                    int col = n0 + wn + nt * 8 + cp2;
                    float v0 = acc[mt][nt][hh*2], v1 = acc[mt][nt][hh*2+1];
                    if (EPI == 2) {
                        const float* gp = gate + (row / SEQ) * N + col;
                        const float* rp = resid + (long long)row * N + col;
                        v0 = rp[0] + gp[0] * v0;
                        v1 = rp[1] + gp[1] * v1;
                    }
                    *(float2*)(Cz + col) = make_float2(v0, v1);
                }
            }
        }
    }
}

// ------------------------- modulation ----------------------------------------
__global__ __launch_bounds__(256) void mod_kernel(const float* __restrict__ temb,
                                                  const float* __restrict__ Wm,
                                                  const float* __restrict__ bm) {
    int gw = (blockIdx.x * blockDim.x + threadIdx.x) >> 5;
    int lane = threadIdx.x & 31;
    if (gw >= BSZ * 4 * DIMM) return;
    int b = gw / (4 * DIMM);
    int j = gw - b * 4 * DIMM;
    const float* t = temb + b * DIMM;
    const float* w = Wm + (size_t)j * DIMM;
    float acc = 0.f;
    for (int kk = lane; kk < DIMM; kk += 32) {
        float x = t[kk];
        acc += (x / (1.f + __expf(-x))) * w[kk];
    }
    #pragma unroll
    for (int o = 16; o; o >>= 1) acc += __shfl_xor_sync(0xffffffffu, acc, o);
    if (lane == 0) {
        acc += bm[j];
        int q = j / DIMM, c = j - q * DIMM;
        if (q == 0)      g_scale1[b*DIMM + c] = 1.f + acc;
        else if (q == 1) g_tg1[b*DIMM + c]    = tanhf(fminf(fmaxf(acc, -2.f), 2.f));
        else if (q == 2) g_scale2[b*DIMM + c] = 1.f + acc;
        else             g_tg2[b*DIMM + c]    = tanhf(fminf(fmaxf(acc, -2.f), 2.f));
    }
}

// ------------------------- LayerNorm -> half (+opt fp32 normed) --------------
__global__ __launch_bounds__(256) void ln_mod_kernel(const float* __restrict__ in,
                                                     const float* __restrict__ scale,
                                                     __half* __restrict__ mh,
                                                     float* __restrict__ outnorm) {
    int rowi = blockIdx.x;
    int b = rowi >> 10;
    const float* x = in + (size_t)rowi * DIMM;
    float s = 0.f, sq = 0.f;
    for (int d = threadIdx.x; d < DIMM; d += 256) { float v = x[d]; s += v; sq += v * v; }
    #pragma unroll
    for (int o = 16; o; o >>= 1) {
        s  += __shfl_xor_sync(0xffffffffu, s,  o);
        sq += __shfl_xor_sync(0xffffffffu, sq, o);
    }
    __shared__ float rs[8], rq[8], mv[2];
    int w = threadIdx.x >> 5;
    if ((threadIdx.x & 31) == 0) { rs[w] = s; rq[w] = sq; }
    __syncthreads();
    if (threadIdx.x == 0) {
        float S = 0.f, Q = 0.f;
        for (int i = 0; i < 8; i++) { S += rs[i]; Q += rq[i]; }
        float mean = S / DIMM;
        float var = Q / DIMM - mean * mean;
        mv[0] = mean; mv[1] = rsqrtf(var + EPSL);
    }
    __syncthreads();
    float mean = mv[0], rstd = mv[1];
    const float* sc = scale + (size_t)b * DIMM;
    for (int d = threadIdx.x; d < DIMM; d += 256) {
        float n = (x[d] - mean) * rstd;
        if (outnorm) outnorm[(size_t)rowi * DIMM + d] = n;
        mh[(size_t)rowi * DIMM + d] = __float2half(n * sc[d]);
    }
}

// ------------------------- per-head RMSNorm of Q (half in/out) ---------------
__global__ __launch_bounds__(256) void rms_q_kernel(const float* __restrict__ w) {
    int gw = (blockIdx.x * blockDim.x + threadIdx.x) >> 5;
    if (gw >= NTOK * NH) return;
    int lane = threadIdx.x & 31;
    int tok = gw / NH, h = gw % NH;
    const __half* p = g_qkv_h + (size_t)tok * QKVN + h * HDD;
    int d4 = lane << 2;
    __half2 a = *(const __half2*)(p + d4);
    __half2 b2 = *(const __half2*)(p + d4 + 2);
    float v0 = __half2float(__low2half(a)),  v1 = __half2float(__high2half(a));
    float v2 = __half2float(__low2half(b2)), v3 = __half2float(__high2half(b2));
    float ss = v0*v0 + v1*v1 + v2*v2 + v3*v3;
    #pragma unroll
    for (int o = 16; o; o >>= 1) ss += __shfl_xor_sync(0xffffffffu, ss, o);
    float r = rsqrtf(ss / HDD + EPSL);
    float4 wv = *(const float4*)(w + d4);
    __half2* dst = (__half2*)(g_qh + (size_t)tok * DIMM + h * HDD + d4);
    dst[0] = __halves2half2(__float2half(v0 * r * wv.x), __float2half(v1 * r * wv.y));
    dst[1] = __halves2half2(__float2half(v2 * r * wv.z), __float2half(v3 * r * wv.w));
}

// ------------------------- K RMS + K/V fp16 repack (half in) ----------------
__global__ __launch_bounds__(256) void kv_repack_kernel(const float* __restrict__ nk,
                                                        const float* __restrict__ nak) {
    int gw = (blockIdx.x * blockDim.x + threadIdx.x) >> 5;
    if (gw >= BSZ * NKV * LTOT) return;
    int lane = threadIdx.x & 31;
    int l = gw % LTOT;
    int bk = gw / LTOT;
    int kv = bk % NKV, b = bk / NKV;
    const __half *ksrc, *vsrc;
    const float* w;
    if (l < SEQ) {
        const __half* base = g_qkv_h + (size_t)(b * SEQ + l) * QKVN;
        ksrc = base + DIMM + kv * HDD;
        vsrc = base + DIMM + IKV + kv * HDD;
        w = nk;
    } else {
        int tt = l - SEQ;
        const __half* base = g_akv_h + (size_t)(b * TXT + tt) * AKVN;
        ksrc = base + kv * HDD;
        vsrc = base + IKV + kv * HDD;
        w = nak;
    }
    int d4 = lane << 2;
    __half2 ka = *(const __half2*)(ksrc + d4);
    __half2 kb2 = *(const __half2*)(ksrc + d4 + 2);
    float k0 = __half2float(__low2half(ka)),  k1 = __half2float(__high2half(ka));
    float k2 = __half2float(__low2half(kb2)), k3 = __half2float(__high2half(kb2));
    float ss = k0*k0 + k1*k1 + k2*k2 + k3*k3;
    #pragma unroll
    for (int o = 16; o; o >>= 1) ss += __shfl_xor_sync(0xffffffffu, ss, o);
    float r = rsqrtf(ss / HDD + EPSL);
    float4 wv = *(const float4*)(w + d4);
    size_t kbase = ((size_t)(b * NKV + kv) * LTOT + l) * HDD + d4;
    __half2* kd = (__half2*)(g_kh + kbase);
    kd[0] = __halves2half2(__float2half(k0 * r * wv.x), __float2half(k1 * r * wv.y));
    kd[1] = __halves2half2(__float2half(k2 * r * wv.z), __float2half(k3 * r * wv.w));
    __half2 va = *(const __half2*)(vsrc + d4);
    __half2 vb2 = *(const __half2*)(vsrc + d4 + 2);
    size_t vb = (size_t)(b * NKV + kv) * HDD;
    g_vT[(vb + d4    ) * LTOT + l] = __low2half(va);
    g_vT[(vb + d4 + 1) * LTOT + l] = __high2half(va);
    g_vT[(vb + d4 + 2) * LTOT + l] = __low2half(vb2);
    g_vT[(vb + d4 + 3) * LTOT + l] = __high2half(vb2);
}

// ------------------------- mma flash attention -------------------------------
#define FQSTR 272
#define FVSTR 144
#define FQSZ (64*FQSTR)
#define FKSZ (64*FQSTR)
#define FVSZ (128*FVSTR)
#define FBUF (FKSZ+FVSZ)
#define FSM  (FQSZ + 2*FBUF)

__global__ __launch_bounds__(128, 2) void flash_kernel() {
    extern __shared__ char fsm[];
    const int q0 = blockIdx.x * 64;
    const int h = blockIdx.y;
    const int b = blockIdx.z;
    const int kv = h / REP;
    const int t = threadIdx.x;
    const int w = t >> 5, lane = t & 31;
    const uint32_t uQ = s2u(fsm);
    const uint32_t uK0 = uQ + FQSZ;
    const __half* qg = g_qh + (size_t)(b * SEQ + q0) * DIMM + h * HDD;
    const __half* kg = g_kh + (size_t)(b * NKV + kv) * LTOT * HDD;
    const __half* vg = g_vT + (size_t)(b * NKV + kv) * HDD * LTOT;

    {
        int r = t >> 1, seg = t & 1;
        const __half* src = qg + (size_t)r * DIMM + seg * 64;
        uint32_t dst = uQ + r * FQSTR + seg * 128;
        #pragma unroll
        for (int i = 0; i < 8; i++) cpa16(dst + 16 * i, src + 8 * i);
        asm volatile("cp.async.commit_group;");
    }
    auto issue = [&](int c) {
        uint32_t base = uK0 + (c & 1) * FBUF;
        int k0 = c * 64;
        int r = t >> 1, seg = t & 1;
        const __half* ks = kg + (size_t)(k0 + r) * HDD + seg * 64;
        uint32_t kd = base + r * FQSTR + seg * 128;
        #pragma unroll
        for (int i = 0; i < 8; i++) cpa16(kd + 16 * i, ks + 8 * i);
        const __half* vs = vg + (size_t)t * LTOT + k0;
        uint32_t vd = base + FKSZ + t * FVSTR;
        #pragma unroll
        for (int i = 0; i < 8; i++) cpa16(vd + 16 * i, vs + 8 * i);
        asm volatile("cp.async.commit_group;");
    };

    const uint32_t aq_off = (w * 16 + (lane & 15)) * FQSTR + (lane >> 4) * 16;
    uint32_t bk_off[4];
    #pragma unroll
    for (int np = 0; np < 4; np++)
        bk_off[np] = (np * 16 + ((lane >> 4) << 3) + (lane & 7)) * FQSTR
                   + ((lane >> 3) & 1) * 16;
    uint32_t bv_off[8];
    #pragma unroll
    for (int np = 0; np < 8; np++)
        bv_off[np] = (np * 16 + ((lane >> 4) << 3) + (lane & 7)) * FVSTR
                   + ((lane >> 3) & 1) * 16;

    float o[16][4];
    #pragma unroll
    for (int i = 0; i < 16; i++)
        #pragma unroll
        for (int j = 0; j < 4; j++) o[i][j] = 0.f;
    float m0 = -1e30f, m1 = -1e30f, l0 = 0.f, l1 = 0.f;
    const float sc = 0.08838834764831845f;

    issue(0);
    const int NCH = LTOT / 64;
    for (int c = 0; c < NCH; c++) {
        if (c + 1 < NCH) { issue(c + 1); asm volatile("cp.async.wait_group 1;"); }
        else             { asm volatile("cp.async.wait_group 0;"); }
        __syncthreads();
        const uint32_t base = uK0 + (c & 1) * FBUF;
        float s[8][4];
        #pragma unroll
        for (int nt = 0; nt < 8; nt++)
            #pragma unroll
            for (int j = 0; j < 4; j++) s[nt][j] = 0.f;
        #pragma unroll
        for (int ks = 0; ks < 8; ks++) {
            uint32_t bf[8][2];
            #pragma unroll
            for (int np = 0; np < 4; np++)
                LDSM4(bf[np*2][0], bf[np*2][1], bf[np*2+1][0], bf[np*2+1][1],
                      base + bk_off[np] + ks * 32);
            uint32_t af[4];
            LDSM4(af[0], af[1], af[2], af[3], uQ + aq_off + ks * 32);
            #pragma unroll
            for (int nt = 0; nt < 8; nt++) mma16816(s[nt], af, bf[nt]);
        }
        float mx0 = -1e30f, mx1 = -1e30f;
        #pragma unroll
        for (int nt = 0; nt < 8; nt++) {
            mx0 = fmaxf(mx0, fmaxf(s[nt][0], s[nt][1]));
            mx1 = fmaxf(mx1, fmaxf(s[nt][2], s[nt][3]));
        }
        #pragma unroll
        for (int off = 1; off < 4; off <<= 1) {
            mx0 = fmaxf(mx0, __shfl_xor_sync(0xffffffffu, mx0, off));
            mx1 = fmaxf(mx1, __shfl_xor_sync(0xffffffffu, mx1, off));
        }
        float nm0 = fmaxf(m0, mx0 * sc), nm1 = fmaxf(m1, mx1 * sc);
        float cr0 = __expf(m0 - nm0), cr1 = __expf(m1 - nm1);
        float sum0 = 0.f, sum1 = 0.f;
        uint32_t pr0[8], pr1[8];
        #pragma unroll
        for (int nt = 0; nt < 8; nt++) {
            float p0 = __expf(s[nt][0] * sc - nm0);
            float p1 = __expf(s[nt][1] * sc - nm0);
            float p2 = __expf(s[nt][2] * sc - nm1);
            float p3 = __expf(s[nt][3] * sc - nm1);
            sum0 += p0 + p1; sum1 += p2 + p3;
            __half2 h0 = __halves2half2(__float2half(p0), __float2half(p1));
            __half2 h1 = __halves2half2(__float2half(p2), __float2half(p3));
            pr0[nt] = *(uint32_t*)&h0;
            pr1[nt] = *(uint32_t*)&h1;
        }
        #pragma unroll
        for (int off = 1; off < 4; off <<= 1) {
            sum0 += __shfl_xor_sync(0xffffffffu, sum0, off);
            sum1 += __shfl_xor_sync(0xffffffffu, sum1, off);
        }
        l0 = l0 * cr0 + sum0; l1 = l1 * cr1 + sum1;
        m0 = nm0; m1 = nm1;
        #pragma unroll
        for (int nt2 = 0; nt2 < 16; nt2++) {
            o[nt2][0] *= cr0; o[nt2][1] *= cr0;
            o[nt2][2] *= cr1; o[nt2][3] *= cr1;
        }
        const uint32_t vbase = base + FKSZ;
        #pragma unroll
        for (int ks2 = 0; ks2 < 4; ks2++) {
            uint32_t a[4] = { pr0[2*ks2], pr1[2*ks2], pr0[2*ks2+1], pr1[2*ks2+1] };
            #pragma unroll
            for (int np = 0; np < 8; np++) {
                uint32_t bf2[2][2];
                LDSM4(bf2[0][0], bf2[0][1], bf2[1][0], bf2[1][1],
                      vbase + bv_off[np] + ks2 * 32);
                mma16816(o[np*2],     a, bf2[0]);
                mma16816(o[np*2 + 1], a, bf2[1]);
            }
        }
        __syncthreads();
    }
    float i0 = 1.f / l0, i1 = 1.f / l1;
    const int g = lane >> 2, cp2 = (lane & 3) * 2;
    size_t ob = (size_t)(b * SEQ + q0 + w * 16 + g) * DIMM + h * HDD;
    #pragma unroll
    for (int nt2 = 0; nt2 < 16; nt2++) {
        __half2 v0 = __halves2half2(__float2half(o[nt2][0] * i0),
                                    __float2half(o[nt2][1] * i0));
        __half2 v1 = __halves2half2(__float2half(o[nt2][2] * i1),
                                    __float2half(o[nt2][3] * i1));
        *(__half2*)&g_attn_h[ob + nt2 * 8 + cp2] = v0;
        *(__half2*)&g_attn_h[ob + 8 * DIMM + nt2 * 8 + cp2] = v1;
    }
}

// ------------------------- router ------------------------------------------
__global__ __launch_bounds__(1024) void tembdot_kernel(const float* __restrict__ temb,
                                                       const float* __restrict__ Wg) {
    int wid = threadIdx.x >> 5, lane = threadIdx.x & 31;
    int b = wid / NE, e = wid % NE;
    const float* t = temb + b * DIMM;
    const float* w = Wg + (size_t)e * 2 * DIMM;
    float acc = 0.f;
    for (int d = lane; d < DIMM; d += 32) acc += t[d] * w[d];
    #pragma unroll
    for (int o = 16; o; o >>= 1) acc += __shfl_xor_sync(0xffffffffu, acc, o);
    if (lane == 0) g_tembdot[wid] = acc;
}

__global__ __launch_bounds__(128) void router_kernel(const float* __restrict__ Wg) {
    __shared__ float lg[NE];
    int tokid = blockIdx.x;
    int b = tokid >> 10, s = tokid & 1023;
    int w = threadIdx.x >> 5, lane = threadIdx.x & 31;
    const float* x = g_normed2 + (size_t)tokid * DIMM;
    for (int e = w * 4; e < w * 4 + 4; e++) {
        const float* wg = Wg + (size_t)e * 2 * DIMM + DIMM;
        float acc = 0.f;
        for (int d = lane; d < DIMM; d += 32) acc += x[d] * wg[d];
        #pragma unroll
        for (int o = 16; o; o >>= 1) acc += __shfl_xor_sync(0xffffffffu, acc, o);
        if (lane == 0) lg[e] = acc + g_tembdot[b * NE + e];
    }
    __syncthreads();
    if (threadIdx.x == 0) {
        float mx = -1e30f;
        for (int e = 0; e < NE; e++) mx = fmaxf(mx, lg[e]);
        float ex[NE], sm = 0.f;
        for (int e = 0; e < NE; e++) { ex[e] = __expf(lg[e] - mx); sm += ex[e]; }
        float inv = 1.f / sm;
        for (int e = 0; e < NE; e++)
            g_aff[((size_t)(b * NE + e)) * SEQ + s] = ex[e] * inv;
    }
}

// ------------------------- exact top-k via bitonic sort ---------------------
__global__ __launch_bounds__(512) void topk_kernel() {
    __shared__ float v[1024];
    __shared__ int   id[1024];
    int be = blockIdx.x;
    const float* rowp = g_aff + (size_t)be * SEQ;
    int t = threadIdx.x;
    for (int i = t; i < 1024; i += 512) { v[i] = rowp[i]; id[i] = i; }
    __syncthreads();
    for (int k = 2; k <= 1024; k <<= 1) {
        for (int j = k >> 1; j > 0; j >>= 1) {
            for (int i = t; i < 1024; i += 512) {
                int ixj = i ^ j;
                if (ixj > i) {
                    bool up = ((i & k) == 0);
                    float va = v[i], vb = v[ixj];
                    int ia = id[i], ib = id[ixj];
                    bool a_first = (va > vb) || (va == vb && ia < ib);
                    bool sw = up ? !a_first : a_first;
                    if (sw) { v[i] = vb; v[ixj] = va; id[i] = ib; id[ixj] = ia; }
                }
            }
            __syncthreads();
        }
    }
    if (t < CAP) {
        g_gating[be * CAP + t] = v[t];
        g_topidx[be * CAP + t] = id[t];
    }
}

__global__ void zero_sums_kernel() {
    int i = blockIdx.x * blockDim.x + threadIdx.x;
    if (i < NTOK) g_sums[i] = 0.f;
}

__global__ void sum_acc_kernel() {
    int i = blockIdx.x * blockDim.x + threadIdx.x;
    if (i >= BSZ * NE * CAP) return;
    int be = i / CAP;
    int b = be / NE;
    int tok = b * SEQ + g_topidx[i];
    atomicAdd(&g_sums[tok], g_gating[i]);
}

__global__ void gate_norm_kernel() {
    int i = blockIdx.x * blockDim.x + threadIdx.x;
    if (i >= BSZ * NE * CAP) return;
    int c = i % CAP;
    int be = i / CAP;
    int b = be / NE, e = be % NE;
    int tok = b * SEQ + g_topidx[i];
    float g = g_gating[i] / (g_sums[tok] + 1e-12f) * 2.5f;
    int rowflat = (e * BSZ + b) * CAP + c;
    g_rowmap[rowflat] = tok;
    g_rscale[rowflat] = g;
}

// ------------------------- final residual -----------------------------------
__global__ __launch_bounds__(256) void final_kernel(float* __restrict__ out) {
    int r = blockIdx.x;
    int b = r >> 10;
    const float4* hs = (const float4*)(g_hs1 + (size_t)r * DIMM);
    const float4* mo = (const float4*)(g_outflat + (size_t)r * DIMM);
    const float4* gg = (const float4*)(g_tg2 + (size_t)b * DIMM);
    float4* o = (float4*)(out + (size_t)r * DIMM);
    for (int i = threadIdx.x; i < DIMM / 4; i += 256) {
        float4 h = hs[i], m = mo[i], g = gg[i], v;
        v.x = h.x + g.x * m.x; v.y = h.y + g.y * m.y;
        v.z = h.z + g.z * m.z; v.w = h.w + g.w * m.w;
        o[i] = v;
    }
}

// ------------------------- launcher -----------------------------------------
extern "C" void kernel_launch(void* const* d_in, const int* in_sizes, int n_in,
                              void* d_out, int out_size) {
    const float* hidden = (const float*)d_in[0];
    const float* enc    = (const float*)d_in[1];
    const float* temb   = (const float*)d_in[2];
    const float* W_mod  = (const float*)d_in[3];
    const float* b_mod  = (const float*)d_in[4];
    const float* W_enc  = (const float*)d_in[5];
    const float* b_enc  = (const float*)d_in[6];
    const float* Wq     = (const float*)d_in[7];
    const float* Wk     = (const float*)d_in[8];
    const float* Wv     = (const float*)d_in[9];
    const float* Wak    = (const float*)d_in[10];
    const float* Wav    = (const float*)d_in[11];
    const float* nq_w   = (const float*)d_in[12];
    const float* nk_w   = (const float*)d_in[13];
    const float* nak_w  = (const float*)d_in[14];
    const float* Wo     = (const float*)d_in[15];
    const float* Wg     = (const float*)d_in[16];
    const float* We_in  = (const float*)d_in[17];
    const float* We_out = (const float*)d_in[18];
    const float* Ws_in  = (const float*)d_in[19];
    const float* Ws_out = (const float*)d_in[20];
    float* out = (float*)d_out;

    void* pv;
    #define GF(sym) (cudaGetSymbolAddress(&pv, sym), (float*)pv)
    #define GH(sym) (cudaGetSymbolAddress(&pv, sym), (__half*)pv)
    #define GI(sym) (cudaGetSymbolAddress(&pv, sym), (int*)pv)
    float* p_hs1     = GF(g_hs1);
    float* p_normed2 = GF(g_normed2);
    float* p_outflat = GF(g_outflat);
    float* p_scale1  = GF(g_scale1);
    float* p_scale2  = GF(g_scale2);
    float* p_tg1     = GF(g_tg1);
    int*   p_rowmap  = GI(g_rowmap);
    float* p_rscale  = GF(g_rscale);
    __half *p_enc_h = GH(g_enc_h);
    __half *p_Wenc_h = GH(g_Wenc_h);
    __half *p_Wqkv_h = GH(g_Wqkv_h);
    __half *p_Wakv_h = GH(g_Wakv_h);
    __half *p_Wo_h = GH(g_Wo_h);
    __half *p_Wein_h = GH(g_Wein_h);
    __half *p_Weout_h = GH(g_Weout_h);
    __half *p_Wsin_h = GH(g_Wsin_h);
    __half *p_Wsout_h = GH(g_Wsout_h);
    __half *p_ctx_h = GH(g_ctx_h);
    __half *p_img_h = GH(g_img_h);
    __half *p_attn_h = GH(g_attn_h);
    __half *p_mod2_h = GH(g_mod2_h);
    __half *p_actsh_h = GH(g_actsh_h);
    __half *p_actmoe_h = GH(g_actmoe_h);
    __half *p_qkv_h = GH(g_qkv_h);
    __half *p_akv_h = GH(g_akv_h);

    cudaFuncSetAttribute(mma_gemm<0,false>, cudaFuncAttributeMaxDynamicSharedMemorySize, MMSM);
    cudaFuncSetAttribute(mma_gemm<2,false>, cudaFuncAttributeMaxDynamicSharedMemorySize, MMSM);
    cudaFuncSetAttribute(mma_gemm<3,false>, cudaFuncAttributeMaxDynamicSharedMemorySize, MMSM);
    cudaFuncSetAttribute(mma_gemm<4,false>, cudaFuncAttributeMaxDynamicSharedMemorySize, MMSM);
    cudaFuncSetAttribute(mma_gemm<4,true>,  cudaFuncAttributeMaxDynamicSharedMemorySize, MMSM);
    cudaFuncSetAttribute(mma_gemm<5,false>, cudaFuncAttributeMaxDynamicSharedMemorySize, MMSM);
    cudaFuncSetAttribute(mma_gemm<6,false>, cudaFuncAttributeMaxDynamicSharedMemorySize, MMSM);
    cudaFuncSetAttribute(flash_kernel, cudaFuncAttributeMaxDynamicSharedMemorySize, FSM);

    const float* NFP = nullptr;
    const int*   NIP = nullptr;

    #define CVT1(src, dh, n) \
        cvt1_kernel<<<(int)(((n) + 4095) / 4096), 256>>>(src, dh, (long long)(n))

    // 0. convert weights + enc to fp16 (QKV / AKV concatenated along N)
    CVT1(W_enc, p_Wenc_h, (long long)DIMM*JD);
    CVT1(Wq,  p_Wqkv_h,                          (long long)DIMM*DIMM);
    CVT1(Wk,  p_Wqkv_h + (size_t)DIMM*DIMM,      (long long)IKV*DIMM);
    CVT1(Wv,  p_Wqkv_h + (size_t)(DIMM+IKV)*DIMM,(long long)IKV*DIMM);
    CVT1(Wak, p_Wakv_h,                          (long long)IKV*DIMM);
    CVT1(Wav, p_Wakv_h + (size_t)IKV*DIMM,       (long long)IKV*DIMM);
    CVT1(Wo,  p_Wo_h,  (long long)DIMM*DIMM);
    cvt_ilv_kernel<<<NE*2*NI, 256>>>(We_in, p_Wein_h, NI);
    CVT1(We_out, p_Weout_h, (long long)NE*DIMM*NI);
    cvt_ilv_kernel<<<2*NI, 256>>>(Ws_in, p_Wsin_h, NI);
    CVT1(Ws_out, p_Wsout_h, (long long)DIMM*NI);
    CVT1(enc, p_enc_h, (long long)BSZ*TXT*JD);

    // 1. modulation
    mod_kernel<<<1536, 256>>>(temb, W_mod, b_mod);
    // 2. context projection (+bias) -> half directly
    mma_gemm<5,false><<<dim3(12, 8, 1), 256, MMSM>>>(p_enc_h, p_Wenc_h, p_ctx_h,
        BSZ*TXT, DIMM, JD, 0, 0, 0, b_enc, NFP, NFP, NIP, NFP, NIP);
    // 3. LN1 * scale1 -> half
    ln_mod_kernel<<<NTOK, 256>>>(hidden, p_scale1, p_img_h, nullptr);
    // 4. merged projections (QKV for image; AK/AV for text) -> half
    mma_gemm<6,false><<<dim3(20, 16, 1), 256, MMSM>>>(p_img_h, p_Wqkv_h, p_qkv_h,
        NTOK, QKVN, DIMM, 0, 0, 0, NFP, NFP, NFP, NIP, NFP, NIP);
    mma_gemm<6,false><<<dim3(8, 8, 1), 256, MMSM>>>(p_ctx_h, p_Wakv_h, p_akv_h,
        BSZ*TXT, AKVN, DIMM, 0, 0, 0, NFP, NFP, NFP, NIP, NFP, NIP);
    // 5. norms + fp16 repack
    rms_q_kernel<<<3072, 256>>>(nq_w);
    kv_repack_kernel<<<1536, 256>>>(nk_w, nak_w);
    // 6. attention (mma, fp16)
    flash_kernel<<<dim3(SEQ/64, NH, BSZ), 128, FSM>>>();
    // 7. output proj + gated residual
    mma_gemm<2,false><<<dim3(12, 16, 1), 256, MMSM>>>(p_attn_h, p_Wo_h, p_hs1,
        NTOK, DIMM, DIMM, 0, 0, 0, NFP, hidden, p_tg1, NIP, NFP, NIP);
    // 8. LN2 -> mod2 half + normed2 fp32
    ln_mod_kernel<<<NTOK, 256>>>(p_hs1, p_scale2, p_mod2_h, p_normed2);
    // 9. router
    tembdot_kernel<<<1, 1024>>>(temb, Wg);
    router_kernel<<<NTOK, 128>>>(Wg);
    topk_kernel<<<BSZ*NE, 512>>>();
    zero_sums_kernel<<<8, 256>>>();
    sum_acc_kernel<<<64, 256>>>();
    gate_norm_kernel<<<64, 256>>>();
    // 10. expert GEMM 1 (gathered A, interleaved weights, fused swiglu -> half)
    mma_gemm<4,true><<<dim3(21, 8, 16), 256, MMSM>>>(p_mod2_h, p_Wein_h, p_actmoe_h,
        BSZ*CAP, 2*NI, DIMM,
        0, (long long)2*NI*DIMM, (long long)BSZ*CAP*NI,
        NFP, NFP, NFP, NIP, NFP, p_rowmap);
    // 11. shared expert (fused swiglu -> half), then out-proj
    mma_gemm<4,false><<<dim3(21, 16, 1), 256, MMSM>>>(p_mod2_h, p_Wsin_h, p_actsh_h,
        NTOK, 2*NI, DIMM, 0, 0, 0, NFP, NFP, NFP, NIP, NFP, NIP);
    mma_gemm<0,false><<<dim3(12, 16, 1), 256, MMSM>>>(p_actsh_h, p_Wsout_h, p_outflat,
        NTOK, DIMM, NI, 0, 0, 0, NFP, NFP, NFP, NIP, NFP, NIP);
    // 12. expert GEMM 2 with atomic scatter onto shared output
    mma_gemm<3,false><<<dim3(12, 8, 16), 256, MMSM>>>(p_actmoe_h, p_Weout_h, p_outflat,
        BSZ*CAP, DIMM, NI,
        (long long)BSZ*CAP*NI, (long long)DIMM*NI, 0,
        NFP, NFP, NFP, p_rowmap, p_rscale, NIP);
    // 13. final gated residual
    final_kernel<<<NTOK, 256>>>(out);
}

// round 16
// speedup vs baseline: 4.4691x; 1.0847x over previous
#include <cuda_runtime.h>
#include <cuda_fp16.h>
#include <math.h>
#include <stdint.h>

#define BSZ 2
#define SEQ 1024
#define TXT 512
#define DIMM 1536
#define NH 12
#define HDD 128
#define NKV 4
#define JD 3584
#define NE 16
#define NI 1344
#define CAP 512
#define LTOT 1536      // SEQ + TXT
#define NTOK 2048      // BSZ*SEQ
#define MROWS 16384    // NE*BSZ*CAP
#define IKV 512        // NKV*HDD
#define REP 3          // NH/NKV
#define QKVN 2560      // DIMM + 2*IKV
#define AKVN 1024      // 2*IKV
#define EPSL 1e-6f

// ------------------------- fp32 scratch -------------------------------------
__device__ float g_scale1[BSZ*DIMM];
__device__ float g_tg1[BSZ*DIMM];
__device__ float g_scale2[BSZ*DIMM];
__device__ float g_tg2[BSZ*DIMM];
__device__ float g_hs1[NTOK*DIMM];
__device__ float g_normed2[NTOK*DIMM];
__device__ float g_tembdot[BSZ*NE];
__device__ float g_aff[BSZ*NE*SEQ];
__device__ int   g_topidx[BSZ*NE*CAP];
__device__ float g_gating[BSZ*NE*CAP];
__device__ float g_sums[NTOK];
__device__ int   g_rowmap[MROWS];
__device__ float g_rscale[MROWS];

// ------------------------- half planes --------------------------------------
__device__ __half g_enc_h[BSZ*TXT*JD];
__device__ __half g_Wenc_h[DIMM*JD];
__device__ __half g_Wqkv_h[(size_t)QKVN*DIMM];      // [Wq ; Wk ; Wv] rows
__device__ __half g_Wakv_h[(size_t)AKVN*DIMM];      // [Wak ; Wav] rows
__device__ __half g_Wo_h[DIMM*DIMM];
__device__ __half g_Wein_h[(size_t)NE*2*NI*DIMM];   // interleaved (a,g) rows
__device__ __half g_Weout_h[(size_t)NE*DIMM*NI];
__device__ __half g_Wsin_h[2*NI*DIMM];              // interleaved (a,g) rows
__device__ __half g_Wsout_h[DIMM*NI];
__device__ __half g_ctx_h[BSZ*TXT*DIMM];
__device__ __half g_img_h[NTOK*DIMM];
__device__ __half g_attn_h[NTOK*DIMM];
__device__ __half g_mod2_h[NTOK*DIMM];
__device__ __half g_actsh_h[NTOK*NI];
__device__ __half g_actmoe_h[(size_t)MROWS*NI];
// attention operands / merged projection outputs
__device__ __half g_qkv_h[(size_t)NTOK*QKVN];
__device__ __half g_akv_h[(size_t)BSZ*TXT*AKVN];
__device__ __half g_qh[NTOK*DIMM];
__device__ __half g_kh[(size_t)BSZ*NKV*LTOT*HDD];
__device__ __half g_vT[(size_t)BSZ*NKV*HDD*LTOT];

// ======================= helpers ============================================
__device__ __forceinline__ uint32_t s2u(const void* p) {
    uint32_t a;
    asm("{ .reg .u64 t; cvta.to.shared.u64 t, %1; cvt.u32.u64 %0, t; }"
        : "=r"(a) : "l"(p));
    return a;
}
__device__ __forceinline__ void cpa16(uint32_t d, const void* s) {
    asm volatile("cp.async.cg.shared.global [%0], [%1], 16;" :: "r"(d), "l"(s));
}
__device__ __forceinline__ void mma16816(float* c, const uint32_t* a, const uint32_t* b) {
    asm volatile(
        "mma.sync.aligned.m16n8k16.row.col.f32.f16.f16.f32 "
        "{%0,%1,%2,%3}, {%4,%5,%6,%7}, {%8,%9}, {%0,%1,%2,%3};"
        : "+f"(c[0]), "+f"(c[1]), "+f"(c[2]), "+f"(c[3])
        : "r"(a[0]), "r"(a[1]), "r"(a[2]), "r"(a[3]), "r"(b[0]), "r"(b[1]));
}
#define LDSM4(r0, r1, r2, r3, addr) \
    asm volatile("ldmatrix.sync.aligned.m8n8.x4.shared.b16 {%0,%1,%2,%3}, [%4];" \
        : "=r"(r0), "=r"(r1), "=r"(r2), "=r"(r3) : "r"(addr))

// ------------------------- fp32 -> half conversion (MLP 4) -------------------
__global__ __launch_bounds__(256) void cvt1_kernel(const float* __restrict__ src,
                                                   __half* __restrict__ dh,
                                                   long long n) {
    long long base = (long long)blockIdx.x * 4096 + threadIdx.x * 4;
    #pragma unroll
    for (int j = 0; j < 4; j++) {
        long long i = base + j * 1024;
        if (i < n) {
            float4 v = *(const float4*)(src + i);
            __half2* ph = (__half2*)(dh + i);
            ph[0] = __halves2half2(__float2half(v.x), __float2half(v.y));
            ph[1] = __halves2half2(__float2half(v.z), __float2half(v.w));
        }
    }
}

// fp32 -> half with (a,g) row interleave per matrix of 2*ni rows (batched z)
__global__ __launch_bounds__(256) void cvt_ilv_kernel(const float* __restrict__ src,
                                                      __half* __restrict__ dst,
                                                      int ni) {
    long long orow = blockIdx.x;
    int rows = 2 * ni;
    long long z = orow / rows;
    int r = (int)(orow % rows);
    long long srow = z * rows + ((r & 1) ? ni + (r >> 1) : (r >> 1));
    const float4* s = (const float4*)(src + srow * DIMM);
    __half2* d = (__half2*)(dst + orow * DIMM);
    for (int i = threadIdx.x; i < DIMM / 4; i += 256) {
        float4 v = s[i];
        d[i*2]   = __halves2half2(__float2half(v.x), __float2half(v.y));
        d[i*2+1] = __halves2half2(__float2half(v.z), __float2half(v.w));
    }
}

// ======================= pipelined fp16 GEMM (3-stage, 1 barrier) ===========
// C[M,N] = A[M,K]*B[N,K]^T, fp16 in, fp32 accumulate.
// EPI 0: fp32 store            2: fp32 resid + gate[b][n]*acc
// EPI 3: fp32 atomic scatter (acc * rscale * gate[b][n])
// EPI 4: swiglu on (even,odd) col pairs -> half N/2
// EPI 5: +bias -> half store   6: plain half store
// AG: gather A rows through agather[z*M + m].
#define PRS 144
#define PLSZ (128*PRS)
#define BUFSZ (2*PLSZ)          // 36864
#define NSTG 3
#define MMSM (NSTG*BUFSZ)       // 110592

template<int EPI, bool AG>
__global__ __launch_bounds__(256, 2) void mma_gemm(
    const __half* __restrict__ Ah, const __half* __restrict__ Bh,
    void* __restrict__ Cv,
    int M, int N, int K,
    long long sA, long long sB, long long sC,
    const float* __restrict__ bias,
    const float* __restrict__ resid, const float* __restrict__ gate,
    const int* __restrict__ rowmap, const float* __restrict__ rscale,
    const int* __restrict__ agather)
{
    extern __shared__ char smem[];
    const int tid = threadIdx.x;
    const int wid = tid >> 5, lane = tid & 31;
    const int z = blockIdx.z;
    const int m0 = blockIdx.y * 128, n0 = blockIdx.x * 128;
    if (!AG) Ah += (long long)z * sA;
    Bh += (long long)z * sB;

    const int lr = tid >> 1;
    const int lh = tid & 1;
    long long arow = AG ? (long long)agather[(long long)z * M + m0 + lr]
                        : (long long)(m0 + lr);
    const __half* aHp = Ah + arow * (long long)K + lh * 32;
    const __half* bHp = Bh + (long long)(n0 + lr) * K + lh * 32;
    const uint32_t pofs = lr * PRS + lh * 64;

    const uint32_t uA = s2u(smem);
    const uint32_t uB = uA + PLSZ;

    const int wm = (wid >> 2) * 64;
    const int wn = (wid & 3) * 32;
    uint32_t a_off[4];
    #pragma unroll
    for (int mt = 0; mt < 4; mt++) {
        int r = wm + mt * 16 + (lane & 15);
        a_off[mt] = r * PRS + (lane >> 4) * 16;
    }
    uint32_t b_off[2];
    #pragma unroll
    for (int np = 0; np < 2; np++) {
        int r = wn + np * 16 + ((lane >> 4) << 3) + (lane & 7);
        b_off[np] = r * PRS + ((lane >> 3) & 1) * 16;
    }

    float acc[4][4][4];
    #pragma unroll
    for (int mt = 0; mt < 4; mt++)
        #pragma unroll
        for (int nt = 0; nt < 4; nt++)
            #pragma unroll
            for (int i = 0; i < 4; i++) acc[mt][nt][i] = 0.f;

    const int NC = K >> 6;
    auto issue = [&](int c, uint32_t boff) {
        long long ko = (long long)c * 64;
        #pragma unroll
        for (int i = 0; i < 4; i++) {
            cpa16(uA + boff + pofs + 16 * i, aHp + ko + 8 * i);
            cpa16(uB + boff + pofs + 16 * i, bHp + ko + 8 * i);
        }
        asm volatile("cp.async.commit_group;");
    };

    issue(0, 0);
    if (NC > 1) issue(1, BUFSZ);
    int buf = 0, nbuf = (2 < NC) ? 2 : (2 - NC >= 0 ? 2 % NC : 2);
    nbuf = 2 % NSTG;
    for (int c = 0; c < NC; c++) {
        asm volatile("cp.async.wait_group 1;");
        __syncthreads();
        const uint32_t boff = buf * BUFSZ;
        #pragma unroll
        for (int ks = 0; ks < 4; ks++) {
            uint32_t bf[4][2];
            #pragma unroll
            for (int np = 0; np < 2; np++)
                LDSM4(bf[np*2][0], bf[np*2][1], bf[np*2+1][0], bf[np*2+1][1],
                      uB + boff + b_off[np] + ks * 32);
            #pragma unroll
            for (int mt = 0; mt < 4; mt++) {
                uint32_t af[4];
                LDSM4(af[0], af[1], af[2], af[3], uA + boff + a_off[mt] + ks * 32);
                #pragma unroll
                for (int nt = 0; nt < 4; nt++) mma16816(acc[mt][nt], af, bf[nt]);
            }
        }
        if (c + 2 < NC) issue(c + 2, nbuf * BUFSZ);
        else asm volatile("cp.async.commit_group;");   // keep group count in step
        buf = (buf + 1) % NSTG;
        nbuf = (nbuf + 1) % NSTG;
    }

    const int g = lane >> 2;
    const int cp2 = (lane & 3) * 2;
    #pragma unroll
    for (int mt = 0; mt < 4; mt++) {
        #pragma unroll
        for (int hh = 0; hh < 2; hh++) {
            int row = m0 + wm + mt * 16 + g + hh * 8;
            if (EPI == 3) {
                long long gr = (long long)z * M + row;
                int trow = rowmap[gr];
                float s = rscale[gr];
                const float* gp = gate + (trow / SEQ) * N;
                float* cp = (float*)Cv + (long long)trow * N;
                #pragma unroll
                for (int nt = 0; nt < 4; nt++) {
                    int col = n0 + wn + nt * 8 + cp2;
                    atomicAdd(cp + col,     acc[mt][nt][hh*2]   * s * gp[col]);
                    atomicAdd(cp + col + 1, acc[mt][nt][hh*2+1] * s * gp[col+1]);
                }
            } else if (EPI == 4) {
                __half* Ch = (__half*)Cv + (long long)z * sC
                           + (long long)row * (N >> 1);
                #pragma unroll
                for (int nt = 0; nt < 4; nt++) {
                    int col = n0 + wn + nt * 8 + cp2;     // even
                    float a = acc[mt][nt][hh*2];
                    float gg = acc[mt][nt][hh*2+1];
                    float act = a * (gg / (1.f + __expf(-gg)));
                    Ch[col >> 1] = __float2half(act);
                }
            } else if (EPI == 5 || EPI == 6) {
                __half* Ch = (__half*)Cv + (long long)z * sC + (long long)row * N;
                #pragma unroll
                for (int nt = 0; nt < 4; nt++) {
                    int col = n0 + wn + nt * 8 + cp2;
                    float v0 = acc[mt][nt][hh*2], v1 = acc[mt][nt][hh*2+1];
                    if (EPI == 5) { v0 += bias[col]; v1 += bias[col + 1]; }
                    __half2 v = __halves2half2(__float2half(v0), __float2half(v1));
                    *(__half2*)&Ch[col] = v;
                }
            } else {
                float* Cz = (float*)Cv + (long long)z * sC + (long long)row * N;
                #pragma unroll
                for (int nt = 0; nt < 4; nt++) {
                    int col = n0 + wn + nt * 8 + cp2;
                    float v0 = acc[mt][nt][hh*2], v1 = acc[mt][nt][hh*2+1];
                    if (EPI == 2) {
                        const float* gp = gate + (row / SEQ) * N + col;
                        const float* rp = resid + (long long)row * N + col;
                        v0 = rp[0] + gp[0] * v0;
                        v1 = rp[1] + gp[1] * v1;
                    }
                    *(float2*)(Cz + col) = make_float2(v0, v1);
                }
            }
        }
    }
}

// ------------------------- modulation ----------------------------------------
__global__ __launch_bounds__(256) void mod_kernel(const float* __restrict__ temb,
                                                  const float* __restrict__ Wm,
                                                  const float* __restrict__ bm) {
    int gw = (blockIdx.x * blockDim.x + threadIdx.x) >> 5;
    int lane = threadIdx.x & 31;
    if (gw >= BSZ * 4 * DIMM) return;
    int b = gw / (4 * DIMM);
    int j = gw - b * 4 * DIMM;
    const float* t = temb + b * DIMM;
    const float* w = Wm + (size_t)j * DIMM;
    float acc = 0.f;
    for (int kk = lane; kk < DIMM; kk += 32) {
        float x = t[kk];
        acc += (x / (1.f + __expf(-x))) * w[kk];
    }
    #pragma unroll
    for (int o = 16; o; o >>= 1) acc += __shfl_xor_sync(0xffffffffu, acc, o);
    if (lane == 0) {
        acc += bm[j];
        int q = j / DIMM, c = j - q * DIMM;
        if (q == 0)      g_scale1[b*DIMM + c] = 1.f + acc;
        else if (q == 1) g_tg1[b*DIMM + c]    = tanhf(fminf(fmaxf(acc, -2.f), 2.f));
        else if (q == 2) g_scale2[b*DIMM + c] = 1.f + acc;
        else             g_tg2[b*DIMM + c]    = tanhf(fminf(fmaxf(acc, -2.f), 2.f));
    }
}

// ------------------------- LayerNorm -> half (+opt fp32 normed) --------------
__global__ __launch_bounds__(256) void ln_mod_kernel(const float* __restrict__ in,
                                                     const float* __restrict__ scale,
                                                     __half* __restrict__ mh,
                                                     float* __restrict__ outnorm) {
    int rowi = blockIdx.x;
    int b = rowi >> 10;
    const float* x = in + (size_t)rowi * DIMM;
    float s = 0.f, sq = 0.f;
    for (int d = threadIdx.x; d < DIMM; d += 256) { float v = x[d]; s += v; sq += v * v; }
    #pragma unroll
    for (int o = 16; o; o >>= 1) {
        s  += __shfl_xor_sync(0xffffffffu, s,  o);
        sq += __shfl_xor_sync(0xffffffffu, sq, o);
    }
    __shared__ float rs[8], rq[8], mv[2];
    int w = threadIdx.x >> 5;
    if ((threadIdx.x & 31) == 0) { rs[w] = s; rq[w] = sq; }
    __syncthreads();
    if (threadIdx.x == 0) {
        float S = 0.f, Q = 0.f;
        for (int i = 0; i < 8; i++) { S += rs[i]; Q += rq[i]; }
        float mean = S / DIMM;
        float var = Q / DIMM - mean * mean;
        mv[0] = mean; mv[1] = rsqrtf(var + EPSL);
    }
    __syncthreads();
    float mean = mv[0], rstd = mv[1];
    const float* sc = scale + (size_t)b * DIMM;
    for (int d = threadIdx.x; d < DIMM; d += 256) {
        float n = (x[d] - mean) * rstd;
        if (outnorm) outnorm[(size_t)rowi * DIMM + d] = n;
        mh[(size_t)rowi * DIMM + d] = __float2half(n * sc[d]);
    }
}

// ------------------------- per-head RMSNorm of Q (half in/out) ---------------
__global__ __launch_bounds__(256) void rms_q_kernel(const float* __restrict__ w) {
    int gw = (blockIdx.x * blockDim.x + threadIdx.x) >> 5;
    if (gw >= NTOK * NH) return;
    int lane = threadIdx.x & 31;
    int tok = gw / NH, h = gw % NH;
    const __half* p = g_qkv_h + (size_t)tok * QKVN + h * HDD;
    int d4 = lane << 2;
    __half2 a = *(const __half2*)(p + d4);
    __half2 b2 = *(const __half2*)(p + d4 + 2);
    float v0 = __half2float(__low2half(a)),  v1 = __half2float(__high2half(a));
    float v2 = __half2float(__low2half(b2)), v3 = __half2float(__high2half(b2));
    float ss = v0*v0 + v1*v1 + v2*v2 + v3*v3;
    #pragma unroll
    for (int o = 16; o; o >>= 1) ss += __shfl_xor_sync(0xffffffffu, ss, o);
    float r = rsqrtf(ss / HDD + EPSL);
    float4 wv = *(const float4*)(w + d4);
    __half2* dst = (__half2*)(g_qh + (size_t)tok * DIMM + h * HDD + d4);
    dst[0] = __halves2half2(__float2half(v0 * r * wv.x), __float2half(v1 * r * wv.y));
    dst[1] = __halves2half2(__float2half(v2 * r * wv.z), __float2half(v3 * r * wv.w));
}

// ------------------------- K RMS + K/V fp16 repack (half in) ----------------
__global__ __launch_bounds__(256) void kv_repack_kernel(const float* __restrict__ nk,
                                                        const float* __restrict__ nak) {
    int gw = (blockIdx.x * blockDim.x + threadIdx.x) >> 5;
    if (gw >= BSZ * NKV * LTOT) return;
    int lane = threadIdx.x & 31;
    int l = gw % LTOT;
    int bk = gw / LTOT;
    int kv = bk % NKV, b = bk / NKV;
    const __half *ksrc, *vsrc;
    const float* w;
    if (l < SEQ) {
        const __half* base = g_qkv_h + (size_t)(b * SEQ + l) * QKVN;
        ksrc = base + DIMM + kv * HDD;
        vsrc = base + DIMM + IKV + kv * HDD;
        w = nk;
    } else {
        int tt = l - SEQ;
        const __half* base = g_akv_h + (size_t)(b * TXT + tt) * AKVN;
        ksrc = base + kv * HDD;
        vsrc = base + IKV + kv * HDD;
        w = nak;
    }
    int d4 = lane << 2;
    __half2 ka = *(const __half2*)(ksrc + d4);
    __half2 kb2 = *(const __half2*)(ksrc + d4 + 2);
    float k0 = __half2float(__low2half(ka)),  k1 = __half2float(__high2half(ka));
    float k2 = __half2float(__low2half(kb2)), k3 = __half2float(__high2half(kb2));
    float ss = k0*k0 + k1*k1 + k2*k2 + k3*k3;
    #pragma unroll
    for (int o = 16; o; o >>= 1) ss += __shfl_xor_sync(0xffffffffu, ss, o);
    float r = rsqrtf(ss / HDD + EPSL);
    float4 wv = *(const float4*)(w + d4);
    size_t kbase = ((size_t)(b * NKV + kv) * LTOT + l) * HDD + d4;
    __half2* kd = (__half2*)(g_kh + kbase);
    kd[0] = __halves2half2(__float2half(k0 * r * wv.x), __float2half(k1 * r * wv.y));
    kd[1] = __halves2half2(__float2half(k2 * r * wv.z), __float2half(k3 * r * wv.w));
    __half2 va = *(const __half2*)(vsrc + d4);
    __half2 vb2 = *(const __half2*)(vsrc + d4 + 2);
    size_t vb = (size_t)(b * NKV + kv) * HDD;
    g_vT[(vb + d4    ) * LTOT + l] = __low2half(va);
    g_vT[(vb + d4 + 1) * LTOT + l] = __high2half(va);
    g_vT[(vb + d4 + 2) * LTOT + l] = __low2half(vb2);
    g_vT[(vb + d4 + 3) * LTOT + l] = __high2half(vb2);
}

// ------------------------- mma flash attention -------------------------------
#define FQSTR 272
#define FVSTR 144
#define FQSZ (64*FQSTR)
#define FKSZ (64*FQSTR)
#define FVSZ (128*FVSTR)
#define FBUF (FKSZ+FVSZ)
#define FSM  (FQSZ + 2*FBUF)

__global__ __launch_bounds__(128, 2) void flash_kernel() {
    extern __shared__ char fsm[];
    const int q0 = blockIdx.x * 64;
    const int h = blockIdx.y;
    const int b = blockIdx.z;
    const int kv = h / REP;
    const int t = threadIdx.x;
    const int w = t >> 5, lane = t & 31;
    const uint32_t uQ = s2u(fsm);
    const uint32_t uK0 = uQ + FQSZ;
    const __half* qg = g_qh + (size_t)(b * SEQ + q0) * DIMM + h * HDD;
    const __half* kg = g_kh + (size_t)(b * NKV + kv) * LTOT * HDD;
    const __half* vg = g_vT + (size_t)(b * NKV + kv) * HDD * LTOT;

    {
        int r = t >> 1, seg = t & 1;
        const __half* src = qg + (size_t)r * DIMM + seg * 64;
        uint32_t dst = uQ + r * FQSTR + seg * 128;
        #pragma unroll
        for (int i = 0; i < 8; i++) cpa16(dst + 16 * i, src + 8 * i);
        asm volatile("cp.async.commit_group;");
    }
    auto issue = [&](int c) {
        uint32_t base = uK0 + (c & 1) * FBUF;
        int k0 = c * 64;
        int r = t >> 1, seg = t & 1;
        const __half* ks = kg + (size_t)(k0 + r) * HDD + seg * 64;
        uint32_t kd = base + r * FQSTR + seg * 128;
        #pragma unroll
        for (int i = 0; i < 8; i++) cpa16(kd + 16 * i, ks + 8 * i);
        const __half* vs = vg + (size_t)t * LTOT + k0;
        uint32_t vd = base + FKSZ + t * FVSTR;
        #pragma unroll
        for (int i = 0; i < 8; i++) cpa16(vd + 16 * i, vs + 8 * i);
        asm volatile("cp.async.commit_group;");
    };

    const uint32_t aq_off = (w * 16 + (lane & 15)) * FQSTR + (lane >> 4) * 16;
    uint32_t bk_off[4];
    #pragma unroll
    for (int np = 0; np < 4; np++)
        bk_off[np] = (np * 16 + ((lane >> 4) << 3) + (lane & 7)) * FQSTR
                   + ((lane >> 3) & 1) * 16;
    uint32_t bv_off[8];
    #pragma unroll
    for (int np = 0; np < 8; np++)
        bv_off[np] = (np * 16 + ((lane >> 4) << 3) + (lane & 7)) * FVSTR
                   + ((lane >> 3) & 1) * 16;

    float o[16][4];
    #pragma unroll
    for (int i = 0; i < 16; i++)
        #pragma unroll
        for (int j = 0; j < 4; j++) o[i][j] = 0.f;
    float m0 = -1e30f, m1 = -1e30f, l0 = 0.f, l1 = 0.f;
    const float sc = 0.08838834764831845f;

    issue(0);
    const int NCH = LTOT / 64;
    for (int c = 0; c < NCH; c++) {
        if (c + 1 < NCH) { issue(c + 1); asm volatile("cp.async.wait_group 1;"); }
        else             { asm volatile("cp.async.wait_group 0;"); }
        __syncthreads();
        const uint32_t base = uK0 + (c & 1) * FBUF;
        float s[8][4];
        #pragma unroll
        for (int nt = 0; nt < 8; nt++)
            #pragma unroll
            for (int j = 0; j < 4; j++) s[nt][j] = 0.f;
        #pragma unroll
        for (int ks = 0; ks < 8; ks++) {
            uint32_t bf[8][2];
            #pragma unroll
            for (int np = 0; np < 4; np++)
                LDSM4(bf[np*2][0], bf[np*2][1], bf[np*2+1][0], bf[np*2+1][1],
                      base + bk_off[np] + ks * 32);
            uint32_t af[4];
            LDSM4(af[0], af[1], af[2], af[3], uQ + aq_off + ks * 32);
            #pragma unroll
            for (int nt = 0; nt < 8; nt++) mma16816(s[nt], af, bf[nt]);
        }
        float mx0 = -1e30f, mx1 = -1e30f;
        #pragma unroll
        for (int nt = 0; nt < 8; nt++) {
            mx0 = fmaxf(mx0, fmaxf(s[nt][0], s[nt][1]));
            mx1 = fmaxf(mx1, fmaxf(s[nt][2], s[nt][3]));
        }
        #pragma unroll
        for (int off = 1; off < 4; off <<= 1) {
            mx0 = fmaxf(mx0, __shfl_xor_sync(0xffffffffu, mx0, off));
            mx1 = fmaxf(mx1, __shfl_xor_sync(0xffffffffu, mx1, off));
        }
        float nm0 = fmaxf(m0, mx0 * sc), nm1 = fmaxf(m1, mx1 * sc);
        float cr0 = __expf(m0 - nm0), cr1 = __expf(m1 - nm1);
        float sum0 = 0.f, sum1 = 0.f;
        uint32_t pr0[8], pr1[8];
        #pragma unroll
        for (int nt = 0; nt < 8; nt++) {
            float p0 = __expf(s[nt][0] * sc - nm0);
            float p1 = __expf(s[nt][1] * sc - nm0);
            float p2 = __expf(s[nt][2] * sc - nm1);
            float p3 = __expf(s[nt][3] * sc - nm1);
            sum0 += p0 + p1; sum1 += p2 + p3;
            __half2 h0 = __halves2half2(__float2half(p0), __float2half(p1));
            __half2 h1 = __halves2half2(__float2half(p2), __float2half(p3));
            pr0[nt] = *(uint32_t*)&h0;
            pr1[nt] = *(uint32_t*)&h1;
        }
        #pragma unroll
        for (int off = 1; off < 4; off <<= 1) {
            sum0 += __shfl_xor_sync(0xffffffffu, sum0, off);
            sum1 += __shfl_xor_sync(0xffffffffu, sum1, off);
        }
        l0 = l0 * cr0 + sum0; l1 = l1 * cr1 + sum1;
        m0 = nm0; m1 = nm1;
        #pragma unroll
        for (int nt2 = 0; nt2 < 16; nt2++) {
            o[nt2][0] *= cr0; o[nt2][1] *= cr0;
            o[nt2][2] *= cr1; o[nt2][3] *= cr1;
        }
        const uint32_t vbase = base + FKSZ;
        #pragma unroll
        for (int ks2 = 0; ks2 < 4; ks2++) {
            uint32_t a[4] = { pr0[2*ks2], pr1[2*ks2], pr0[2*ks2+1], pr1[2*ks2+1] };
            #pragma unroll
            for (int np = 0; np < 8; np++) {
                uint32_t bf2[2][2];
                LDSM4(bf2[0][0], bf2[0][1], bf2[1][0], bf2[1][1],
                      vbase + bv_off[np] + ks2 * 32);
                mma16816(o[np*2],     a, bf2[0]);
                mma16816(o[np*2 + 1], a, bf2[1]);
            }
        }
        __syncthreads();
    }
    float i0 = 1.f / l0, i1 = 1.f / l1;
    const int g = lane >> 2, cp2 = (lane & 3) * 2;
    size_t ob = (size_t)(b * SEQ + q0 + w * 16 + g) * DIMM + h * HDD;
    #pragma unroll
    for (int nt2 = 0; nt2 < 16; nt2++) {
        __half2 v0 = __halves2half2(__float2half(o[nt2][0] * i0),
                                    __float2half(o[nt2][1] * i0));
        __half2 v1 = __halves2half2(__float2half(o[nt2][2] * i1),
                                    __float2half(o[nt2][3] * i1));
        *(__half2*)&g_attn_h[ob + nt2 * 8 + cp2] = v0;
        *(__half2*)&g_attn_h[ob + 8 * DIMM + nt2 * 8 + cp2] = v1;
    }
}

// ------------------------- router ------------------------------------------
__global__ __launch_bounds__(1024) void tembdot_kernel(const float* __restrict__ temb,
                                                       const float* __restrict__ Wg) {
    int wid = threadIdx.x >> 5, lane = threadIdx.x & 31;
    int b = wid / NE, e = wid % NE;
    const float* t = temb + b * DIMM;
    const float* w = Wg + (size_t)e * 2 * DIMM;
    float acc = 0.f;
    for (int d = lane; d < DIMM; d += 32) acc += t[d] * w[d];
    #pragma unroll
    for (int o = 16; o; o >>= 1) acc += __shfl_xor_sync(0xffffffffu, acc, o);
    if (lane == 0) g_tembdot[wid] = acc;
}

__global__ __launch_bounds__(128) void router_kernel(const float* __restrict__ Wg) {
    __shared__ float lg[NE];
    int tokid = blockIdx.x;
    int b = tokid >> 10, s = tokid & 1023;
    int w = threadIdx.x >> 5, lane = threadIdx.x & 31;
    const float* x = g_normed2 + (size_t)tokid * DIMM;
    for (int e = w * 4; e < w * 4 + 4; e++) {
        const float* wg = Wg + (size_t)e * 2 * DIMM + DIMM;
        float acc = 0.f;
        for (int d = lane; d < DIMM; d += 32) acc += x[d] * wg[d];
        #pragma unroll
        for (int o = 16; o; o >>= 1) acc += __shfl_xor_sync(0xffffffffu, acc, o);
        if (lane == 0) lg[e] = acc + g_tembdot[b * NE + e];
    }
    __syncthreads();
    if (threadIdx.x == 0) {
        float mx = -1e30f;
        for (int e = 0; e < NE; e++) mx = fmaxf(mx, lg[e]);
        float ex[NE], sm = 0.f;
        for (int e = 0; e < NE; e++) { ex[e] = __expf(lg[e] - mx); sm += ex[e]; }
        float inv = 1.f / sm;
        for (int e = 0; e < NE; e++)
            g_aff[((size_t)(b * NE + e)) * SEQ + s] = ex[e] * inv;
    }
}

// ------------------------- exact top-k via bitonic sort ---------------------
__global__ __launch_bounds__(512) void topk_kernel() {
    __shared__ float v[1024];
    __shared__ int   id[1024];
    int be = blockIdx.x;
    const float* rowp = g_aff + (size_t)be * SEQ;
    int t = threadIdx.x;
    for (int i = t; i < 1024; i += 512) { v[i] = rowp[i]; id[i] = i; }
    __syncthreads();
    for (int k = 2; k <= 1024; k <<= 1) {
        for (int j = k >> 1; j > 0; j >>= 1) {
            for (int i = t; i < 1024; i += 512) {
                int ixj = i ^ j;
                if (ixj > i) {
                    bool up = ((i & k) == 0);
                    float va = v[i], vb = v[ixj];
                    int ia = id[i], ib = id[ixj];
                    bool a_first = (va > vb) || (va == vb && ia < ib);
                    bool sw = up ? !a_first : a_first;
                    if (sw) { v[i] = vb; v[ixj] = va; id[i] = ib; id[ixj] = ia; }
                }
            }
            __syncthreads();
        }
    }
    if (t < CAP) {
        g_gating[be * CAP + t] = v[t];
        g_topidx[be * CAP + t] = id[t];
    }
}

__global__ void zero_sums_kernel() {
    int i = blockIdx.x * blockDim.x + threadIdx.x;
    if (i < NTOK) g_sums[i] = 0.f;
}

__global__ void sum_acc_kernel() {
    int i = blockIdx.x * blockDim.x + threadIdx.x;
    if (i >= BSZ * NE * CAP) return;
    int be = i / CAP;
    int b = be / NE;
    int tok = b * SEQ + g_topidx[i];
    atomicAdd(&g_sums[tok], g_gating[i]);
}

__global__ void gate_norm_kernel() {
    int i = blockIdx.x * blockDim.x + threadIdx.x;
    if (i >= BSZ * NE * CAP) return;
    int c = i % CAP;
    int be = i / CAP;
    int b = be / NE, e = be % NE;
    int tok = b * SEQ + g_topidx[i];
    float g = g_gating[i] / (g_sums[tok] + 1e-12f) * 2.5f;
    int rowflat = (e * BSZ + b) * CAP + c;
    g_rowmap[rowflat] = tok;
    g_rscale[rowflat] = g;
}

// ------------------------- launcher -----------------------------------------
extern "C" void kernel_launch(void* const* d_in, const int* in_sizes, int n_in,
                              void* d_out, int out_size) {
    const float* hidden = (const float*)d_in[0];
    const float* enc    = (const float*)d_in[1];
    const float* temb   = (const float*)d_in[2];
    const float* W_mod  = (const float*)d_in[3];
    const float* b_mod  = (const float*)d_in[4];
    const float* W_enc  = (const float*)d_in[5];
    const float* b_enc  = (const float*)d_in[6];
    const float* Wq     = (const float*)d_in[7];
    const float* Wk     = (const float*)d_in[8];
    const float* Wv     = (const float*)d_in[9];
    const float* Wak    = (const float*)d_in[10];
    const float* Wav    = (const float*)d_in[11];
    const float* nq_w   = (const float*)d_in[12];
    const float* nk_w   = (const float*)d_in[13];
    const float* nak_w  = (const float*)d_in[14];
    const float* Wo     = (const float*)d_in[15];
    const float* Wg     = (const float*)d_in[16];
    const float* We_in  = (const float*)d_in[17];
    const float* We_out = (const float*)d_in[18];
    const float* Ws_in  = (const float*)d_in[19];
    const float* Ws_out = (const float*)d_in[20];
    float* out = (float*)d_out;

    void* pv;
    #define GF(sym) (cudaGetSymbolAddress(&pv, sym), (float*)pv)
    #define GH(sym) (cudaGetSymbolAddress(&pv, sym), (__half*)pv)
    #define GI(sym) (cudaGetSymbolAddress(&pv, sym), (int*)pv)
    float* p_hs1     = GF(g_hs1);
    float* p_normed2 = GF(g_normed2);
    float* p_scale1  = GF(g_scale1);
    float* p_scale2  = GF(g_scale2);
    float* p_tg1     = GF(g_tg1);
    float* p_tg2     = GF(g_tg2);
    int*   p_rowmap  = GI(g_rowmap);
    float* p_rscale  = GF(g_rscale);
    __half *p_enc_h = GH(g_enc_h);
    __half *p_Wenc_h = GH(g_Wenc_h);
    __half *p_Wqkv_h = GH(g_Wqkv_h);
    __half *p_Wakv_h = GH(g_Wakv_h);
    __half *p_Wo_h = GH(g_Wo_h);
    __half *p_Wein_h = GH(g_Wein_h);
    __half *p_Weout_h = GH(g_Weout_h);
    __half *p_Wsin_h = GH(g_Wsin_h);
    __half *p_Wsout_h = GH(g_Wsout_h);
    __half *p_ctx_h = GH(g_ctx_h);
    __half *p_img_h = GH(g_img_h);
    __half *p_attn_h = GH(g_attn_h);
    __half *p_mod2_h = GH(g_mod2_h);
    __half *p_actsh_h = GH(g_actsh_h);
    __half *p_actmoe_h = GH(g_actmoe_h);
    __half *p_qkv_h = GH(g_qkv_h);
    __half *p_akv_h = GH(g_akv_h);

    cudaFuncSetAttribute(mma_gemm<2,false>, cudaFuncAttributeMaxDynamicSharedMemorySize, MMSM);
    cudaFuncSetAttribute(mma_gemm<3,false>, cudaFuncAttributeMaxDynamicSharedMemorySize, MMSM);
    cudaFuncSetAttribute(mma_gemm<4,false>, cudaFuncAttributeMaxDynamicSharedMemorySize, MMSM);
    cudaFuncSetAttribute(mma_gemm<4,true>,  cudaFuncAttributeMaxDynamicSharedMemorySize, MMSM);
    cudaFuncSetAttribute(mma_gemm<5,false>, cudaFuncAttributeMaxDynamicSharedMemorySize, MMSM);
    cudaFuncSetAttribute(mma_gemm<6,false>, cudaFuncAttributeMaxDynamicSharedMemorySize, MMSM);
    cudaFuncSetAttribute(flash_kernel, cudaFuncAttributeMaxDynamicSharedMemorySize, FSM);

    const float* NFP = nullptr;
    const int*   NIP = nullptr;

    #define CVT1(src, dh, n) \
        cvt1_kernel<<<(int)(((n) + 4095) / 4096), 256>>>(src, dh, (long long)(n))

    // 0. convert weights + enc to fp16 (QKV / AKV concatenated along N)
    CVT1(W_enc, p_Wenc_h, (long long)DIMM*JD);
    CVT1(Wq,  p_Wqkv_h,                          (long long)DIMM*DIMM);
    CVT1(Wk,  p_Wqkv_h + (size_t)DIMM*DIMM,      (long long)IKV*DIMM);
    CVT1(Wv,  p_Wqkv_h + (size_t)(DIMM+IKV)*DIMM,(long long)IKV*DIMM);
    CVT1(Wak, p_Wakv_h,                          (long long)IKV*DIMM);
    CVT1(Wav, p_Wakv_h + (size_t)IKV*DIMM,       (long long)IKV*DIMM);
    CVT1(Wo,  p_Wo_h,  (long long)DIMM*DIMM);
    cvt_ilv_kernel<<<NE*2*NI, 256>>>(We_in, p_Wein_h, NI);
    CVT1(We_out, p_Weout_h, (long long)NE*DIMM*NI);
    cvt_ilv_kernel<<<2*NI, 256>>>(Ws_in, p_Wsin_h, NI);
    CVT1(Ws_out, p_Wsout_h, (long long)DIMM*NI);
    CVT1(enc, p_enc_h, (long long)BSZ*TXT*JD);

    // 1. modulation
    mod_kernel<<<1536, 256>>>(temb, W_mod, b_mod);
    // 2. context projection (+bias) -> half directly
    mma_gemm<5,false><<<dim3(12, 8, 1), 256, MMSM>>>(p_enc_h, p_Wenc_h, p_ctx_h,
        BSZ*TXT, DIMM, JD, 0, 0, 0, b_enc, NFP, NFP, NIP, NFP, NIP);
    // 3. LN1 * scale1 -> half
    ln_mod_kernel<<<NTOK, 256>>>(hidden, p_scale1, p_img_h, nullptr);
    // 4. merged projections (QKV for image; AK/AV for text) -> half
    mma_gemm<6,false><<<dim3(20, 16, 1), 256, MMSM>>>(p_img_h, p_Wqkv_h, p_qkv_h,
        NTOK, QKVN, DIMM, 0, 0, 0, NFP, NFP, NFP, NIP, NFP, NIP);
    mma_gemm<6,false><<<dim3(8, 8, 1), 256, MMSM>>>(p_ctx_h, p_Wakv_h, p_akv_h,
        BSZ*TXT, AKVN, DIMM, 0, 0, 0, NFP, NFP, NFP, NIP, NFP, NIP);
    // 5. norms + fp16 repack
    rms_q_kernel<<<3072, 256>>>(nq_w);
    kv_repack_kernel<<<1536, 256>>>(nk_w, nak_w);
    // 6. attention (mma, fp16)
    flash_kernel<<<dim3(SEQ/64, NH, BSZ), 128, FSM>>>();
    // 7. output proj + gated residual
    mma_gemm<2,false><<<dim3(12, 16, 1), 256, MMSM>>>(p_attn_h, p_Wo_h, p_hs1,
        NTOK, DIMM, DIMM, 0, 0, 0, NFP, hidden, p_tg1, NIP, NFP, NIP);
    // 8. LN2 -> mod2 half + normed2 fp32
    ln_mod_kernel<<<NTOK, 256>>>(p_hs1, p_scale2, p_mod2_h, p_normed2);
    // 9. router
    tembdot_kernel<<<1, 1024>>>(temb, Wg);
    router_kernel<<<NTOK, 128>>>(Wg);
    topk_kernel<<<BSZ*NE, 512>>>();
    zero_sums_kernel<<<8, 256>>>();
    sum_acc_kernel<<<64, 256>>>();
    gate_norm_kernel<<<64, 256>>>();
    // 10. expert GEMM 1 (gathered A, interleaved weights, fused swiglu -> half)
    mma_gemm<4,true><<<dim3(21, 8, 16), 256, MMSM>>>(p_mod2_h, p_Wein_h, p_actmoe_h,
        BSZ*CAP, 2*NI, DIMM,
        0, (long long)2*NI*DIMM, (long long)BSZ*CAP*NI,
        NFP, NFP, NFP, NIP, NFP, p_rowmap);
    // 11. shared expert (fused swiglu -> half), then out-proj fused with
    //     hs1 residual + tg2 gate -> writes d_out directly
    mma_gemm<4,false><<<dim3(21, 16, 1), 256, MMSM>>>(p_mod2_h, p_Wsin_h, p_actsh_h,
        NTOK, 2*NI, DIMM, 0, 0, 0, NFP, NFP, NFP, NIP, NFP, NIP);
    mma_gemm<2,false><<<dim3(12, 16, 1), 256, MMSM>>>(p_actsh_h, p_Wsout_h, out,
        NTOK, DIMM, NI, 0, 0, 0, NFP, p_hs1, p_tg2, NIP, NFP, NIP);
    // 12. expert GEMM 2: gated atomic scatter (acc * rscale * tg2) onto d_out
    mma_gemm<3,false><<<dim3(12, 8, 16), 256, MMSM>>>(p_actmoe_h, p_Weout_h, out,
        BSZ*CAP, DIMM, NI,
        (long long)BSZ*CAP*NI, (long long)DIMM*NI, 0,
        NFP, NFP, p_tg2, p_rowmap, p_rscale, NIP);
}

// round 17
// speedup vs baseline: 4.5515x; 1.0184x over previous
#include <cuda_runtime.h>
#include <cuda_fp16.h>
#include <math.h>
#include <stdint.h>

#define BSZ 2
#define SEQ 1024
#define TXT 512
#define DIMM 1536
#define NH 12
#define HDD 128
#define NKV 4
#define JD 3584
#define NE 16
#define NI 1344
#define CAP 512
#define LTOT 1536      // SEQ + TXT
#define NTOK 2048      // BSZ*SEQ
#define MROWS 16384    // NE*BSZ*CAP
#define IKV 512        // NKV*HDD
#define REP 3          // NH/NKV
#define QKVN 2560      // DIMM + 2*IKV
#define AKVN 1024      // 2*IKV
#define EPSL 1e-6f

// ------------------------- fp32 scratch -------------------------------------
__device__ float g_scale1[BSZ*DIMM];
__device__ float g_tg1[BSZ*DIMM];
__device__ float g_scale2[BSZ*DIMM];
__device__ float g_tg2[BSZ*DIMM];
__device__ float g_hs1[NTOK*DIMM];
__device__ float g_normed2[NTOK*DIMM];
__device__ float g_tembdot[BSZ*NE];
__device__ float g_aff[BSZ*NE*SEQ];
__device__ int   g_topidx[BSZ*NE*CAP];
__device__ float g_gating[BSZ*NE*CAP];
__device__ float g_sums[NTOK];
__device__ int   g_rowmap[MROWS];
__device__ float g_rscale[MROWS];

// ------------------------- half planes --------------------------------------
__device__ __half g_enc_h[BSZ*TXT*JD];
__device__ __half g_Wenc_h[DIMM*JD];
__device__ __half g_Wqkv_h[(size_t)QKVN*DIMM];      // [Wq ; Wk ; Wv] rows
__device__ __half g_Wakv_h[(size_t)AKVN*DIMM];      // [Wak ; Wav] rows
__device__ __half g_Wo_h[DIMM*DIMM];
__device__ __half g_Wein_h[(size_t)NE*2*NI*DIMM];   // interleaved (a,g) rows
__device__ __half g_Weout_h[(size_t)NE*DIMM*NI];
__device__ __half g_Wsin_h[2*NI*DIMM];              // interleaved (a,g) rows
__device__ __half g_Wsout_h[DIMM*NI];
__device__ __half g_ctx_h[BSZ*TXT*DIMM];
__device__ __half g_img_h[NTOK*DIMM];
__device__ __half g_attn_h[NTOK*DIMM];
__device__ __half g_mod2_h[NTOK*DIMM];
__device__ __half g_actsh_h[NTOK*NI];
__device__ __half g_actmoe_h[(size_t)MROWS*NI];
// attention operands / merged projection outputs
__device__ __half g_qkv_h[(size_t)NTOK*QKVN];
__device__ __half g_akv_h[(size_t)BSZ*TXT*AKVN];
__device__ __half g_qh[NTOK*DIMM];
__device__ __half g_kh[(size_t)BSZ*NKV*LTOT*HDD];
__device__ __half g_vT[(size_t)BSZ*NKV*HDD*LTOT];

// ======================= helpers ============================================
__device__ __forceinline__ uint32_t s2u(const void* p) {
    uint32_t a;
    asm("{ .reg .u64 t; cvta.to.shared.u64 t, %1; cvt.u32.u64 %0, t; }"
        : "=r"(a) : "l"(p));
    return a;
}
__device__ __forceinline__ void cpa16(uint32_t d, const void* s) {
    asm volatile("cp.async.cg.shared.global [%0], [%1], 16;" :: "r"(d), "l"(s));
}
__device__ __forceinline__ void mma16816(float* c, const uint32_t* a, const uint32_t* b) {
    asm volatile(
        "mma.sync.aligned.m16n8k16.row.col.f32.f16.f16.f32 "
        "{%0,%1,%2,%3}, {%4,%5,%6,%7}, {%8,%9}, {%0,%1,%2,%3};"
        : "+f"(c[0]), "+f"(c[1]), "+f"(c[2]), "+f"(c[3])
        : "r"(a[0]), "r"(a[1]), "r"(a[2]), "r"(a[3]), "r"(b[0]), "r"(b[1]));
}
#define LDSM4(r0, r1, r2, r3, addr) \
    asm volatile("ldmatrix.sync.aligned.m8n8.x4.shared.b16 {%0,%1,%2,%3}, [%4];" \
        : "=r"(r0), "=r"(r1), "=r"(r2), "=r"(r3) : "r"(addr))

// ------------------------- merged fp32 -> half conversion --------------------
#define MAXSEG 12
struct CvtTab {
    const float* src[MAXSEG];
    __half* dst[MAXSEG];
    long long nelem[MAXSEG];
    int blkStart[MAXSEG + 1];
    int nseg;
};

__global__ __launch_bounds__(256) void cvt_multi_kernel(CvtTab tab) {
    int blk = blockIdx.x;
    int s = 0;
    #pragma unroll 4
    for (int i = 1; i <= MAXSEG; i++)
        if (i <= tab.nseg && blk >= tab.blkStart[i]) s = i;
    if (s >= tab.nseg) return;
    int lb = blk - tab.blkStart[s];
    const float* src = tab.src[s];
    __half* dh = tab.dst[s];
    long long n = tab.nelem[s];
    long long base = (long long)lb * 4096 + threadIdx.x * 4;
    #pragma unroll
    for (int j = 0; j < 4; j++) {
        long long i = base + j * 1024;
        if (i < n) {
            float4 v = *(const float4*)(src + i);
            __half2* ph = (__half2*)(dh + i);
            ph[0] = __halves2half2(__float2half(v.x), __float2half(v.y));
            ph[1] = __halves2half2(__float2half(v.z), __float2half(v.w));
        }
    }
}

// fp32 -> half with (a,g) row interleave per matrix of 2*ni rows (batched z)
__global__ __launch_bounds__(256) void cvt_ilv_kernel(const float* __restrict__ src,
                                                      __half* __restrict__ dst,
                                                      int ni) {
    long long orow = blockIdx.x;
    int rows = 2 * ni;
    long long z = orow / rows;
    int r = (int)(orow % rows);
    long long srow = z * rows + ((r & 1) ? ni + (r >> 1) : (r >> 1));
    const float4* s = (const float4*)(src + srow * DIMM);
    __half2* d = (__half2*)(dst + orow * DIMM);
    for (int i = threadIdx.x; i < DIMM / 4; i += 256) {
        float4 v = s[i];
        d[i*2]   = __halves2half2(__float2half(v.x), __float2half(v.y));
        d[i*2+1] = __halves2half2(__float2half(v.z), __float2half(v.w));
    }
}

// ======================= pipelined fp16 GEMM (3-stage, 1 barrier) ===========
// C[M,N] = A[M,K]*B[N,K]^T, fp16 in, fp32 accumulate.
// EPI 0: fp32 store            2: fp32 resid + gate[b][n]*acc
// EPI 3: fp32 atomic scatter (acc * rscale * gate[b][n])
// EPI 4: swiglu on (even,odd) col pairs -> half N/2
// EPI 5: +bias -> half store   6: plain half store
// AG: gather A rows through agather[z*M + m].
#define PRS 144
#define PLSZ (128*PRS)
#define BUFSZ (2*PLSZ)          // 36864
#define NSTG 3
#define MMSM (NSTG*BUFSZ)       // 110592

template<int EPI, bool AG>
__global__ __launch_bounds__(256, 2) void mma_gemm(
    const __half* __restrict__ Ah, const __half* __restrict__ Bh,
    void* __restrict__ Cv,
    int M, int N, int K,
    long long sA, long long sB, long long sC,
    const float* __restrict__ bias,
    const float* __restrict__ resid, const float* __restrict__ gate,
    const int* __restrict__ rowmap, const float* __restrict__ rscale,
    const int* __restrict__ agather)
{
    extern __shared__ char smem[];
    const int tid = threadIdx.x;
    const int wid = tid >> 5, lane = tid & 31;
    const int z = blockIdx.z;
    const int m0 = blockIdx.y * 128, n0 = blockIdx.x * 128;
    if (!AG) Ah += (long long)z * sA;
    Bh += (long long)z * sB;

    const int lr = tid >> 1;
    const int lh = tid & 1;
    long long arow = AG ? (long long)agather[(long long)z * M + m0 + lr]
                        : (long long)(m0 + lr);
    const __half* aHp = Ah + arow * (long long)K + lh * 32;
    const __half* bHp = Bh + (long long)(n0 + lr) * K + lh * 32;
    const uint32_t pofs = lr * PRS + lh * 64;

    const uint32_t uA = s2u(smem);
    const uint32_t uB = uA + PLSZ;

    const int wm = (wid >> 2) * 64;
    const int wn = (wid & 3) * 32;
    uint32_t a_off[4];
    #pragma unroll
    for (int mt = 0; mt < 4; mt++) {
        int r = wm + mt * 16 + (lane & 15);
        a_off[mt] = r * PRS + (lane >> 4) * 16;
    }
    uint32_t b_off[2];
    #pragma unroll
    for (int np = 0; np < 2; np++) {
        int r = wn + np * 16 + ((lane >> 4) << 3) + (lane & 7);
        b_off[np] = r * PRS + ((lane >> 3) & 1) * 16;
    }

    float acc[4][4][4];
    #pragma unroll
    for (int mt = 0; mt < 4; mt++)
        #pragma unroll
        for (int nt = 0; nt < 4; nt++)
            #pragma unroll
            for (int i = 0; i < 4; i++) acc[mt][nt][i] = 0.f;

    const int NC = K >> 6;
    auto issue = [&](int c, uint32_t boff) {
        long long ko = (long long)c * 64;
        #pragma unroll
        for (int i = 0; i < 4; i++) {
            cpa16(uA + boff + pofs + 16 * i, aHp + ko + 8 * i);
            cpa16(uB + boff + pofs + 16 * i, bHp + ko + 8 * i);
        }
        asm volatile("cp.async.commit_group;");
    };

    issue(0, 0);
    if (NC > 1) issue(1, BUFSZ);
    int buf = 0, nbuf = 2 % NSTG;
    for (int c = 0; c < NC; c++) {
        asm volatile("cp.async.wait_group 1;");
        __syncthreads();
        const uint32_t boff = buf * BUFSZ;
        #pragma unroll
        for (int ks = 0; ks < 4; ks++) {
            uint32_t bf[4][2];
            #pragma unroll
            for (int np = 0; np < 2; np++)
                LDSM4(bf[np*2][0], bf[np*2][1], bf[np*2+1][0], bf[np*2+1][1],
                      uB + boff + b_off[np] + ks * 32);
            #pragma unroll
            for (int mt = 0; mt < 4; mt++) {
                uint32_t af[4];
                LDSM4(af[0], af[1], af[2], af[3], uA + boff + a_off[mt] + ks * 32);
                #pragma unroll
                for (int nt = 0; nt < 4; nt++) mma16816(acc[mt][nt], af, bf[nt]);
            }
        }
        if (c + 2 < NC) issue(c + 2, nbuf * BUFSZ);
        else asm volatile("cp.async.commit_group;");   // keep group count in step
        buf = (buf + 1) % NSTG;
        nbuf = (nbuf + 1) % NSTG;
    }

    const int g = lane >> 2;
    const int cp2 = (lane & 3) * 2;
    #pragma unroll
    for (int mt = 0; mt < 4; mt++) {
        #pragma unroll
        for (int hh = 0; hh < 2; hh++) {
            int row = m0 + wm + mt * 16 + g + hh * 8;
            if (EPI == 3) {
                long long gr = (long long)z * M + row;
                int trow = rowmap[gr];
                float s = rscale[gr];
                const float* gp = gate + (trow / SEQ) * N;
                float* cp = (float*)Cv + (long long)trow * N;
                #pragma unroll
                for (int nt = 0; nt < 4; nt++) {
                    int col = n0 + wn + nt * 8 + cp2;
                    atomicAdd(cp + col,     acc[mt][nt][hh*2]   * s * gp[col]);
                    atomicAdd(cp + col + 1, acc[mt][nt][hh*2+1] * s * gp[col+1]);
                }
            } else if (EPI == 4) {
                __half* Ch = (__half*)Cv + (long long)z * sC
                           + (long long)row * (N >> 1);
                #pragma unroll
                for (int nt = 0; nt < 4; nt++) {
                    int col = n0 + wn + nt * 8 + cp2;     // even
                    float a = acc[mt][nt][hh*2];
                    float gg = acc[mt][nt][hh*2+1];
                    float act = a * (gg / (1.f + __expf(-gg)));
                    Ch[col >> 1] = __float2half(act);
                }
            } else if (EPI == 5 || EPI == 6) {
                __half* Ch = (__half*)Cv + (long long)z * sC + (long long)row * N;
                #pragma unroll
                for (int nt = 0; nt < 4; nt++) {
                    int col = n0 + wn + nt * 8 + cp2;
                    float v0 = acc[mt][nt][hh*2], v1 = acc[mt][nt][hh*2+1];
                    if (EPI == 5) { v0 += bias[col]; v1 += bias[col + 1]; }
                    __half2 v = __halves2half2(__float2half(v0), __float2half(v1));
                    *(__half2*)&Ch[col] = v;
                }
            } else {
                float* Cz = (float*)Cv + (long long)z * sC + (long long)row * N;
                #pragma unroll
                for (int nt = 0; nt < 4; nt++) {
                    int col = n0 + wn + nt * 8 + cp2;
                    float v0 = acc[mt][nt][hh*2], v1 = acc[mt][nt][hh*2+1];
                    if (EPI == 2) {
                        const float* gp = gate + (row / SEQ) * N + col;
                        const float* rp = resid + (long long)row * N + col;
                        v0 = rp[0] + gp[0] * v0;
                        v1 = rp[1] + gp[1] * v1;
                    }
                    *(float2*)(Cz + col) = make_float2(v0, v1);
                }
            }
        }
    }
}

// ------------------------- modulation ----------------------------------------
__global__ __launch_bounds__(256) void mod_kernel(const float* __restrict__ temb,
                                                  const float* __restrict__ Wm,
                                                  const float* __restrict__ bm) {
    int gw = (blockIdx.x * blockDim.x + threadIdx.x) >> 5;
    int lane = threadIdx.x & 31;
    if (gw >= BSZ * 4 * DIMM) return;
    int b = gw / (4 * DIMM);
    int j = gw - b * 4 * DIMM;
    const float* t = temb + b * DIMM;
    const float* w = Wm + (size_t)j * DIMM;
    float acc = 0.f;
    for (int kk = lane; kk < DIMM; kk += 32) {
        float x = t[kk];
        acc += (x / (1.f + __expf(-x))) * w[kk];
    }
    #pragma unroll
    for (int o = 16; o; o >>= 1) acc += __shfl_xor_sync(0xffffffffu, acc, o);
    if (lane == 0) {
        acc += bm[j];
        int q = j / DIMM, c = j - q * DIMM;
        if (q == 0)      g_scale1[b*DIMM + c] = 1.f + acc;
        else if (q == 1) g_tg1[b*DIMM + c]    = tanhf(fminf(fmaxf(acc, -2.f), 2.f));
        else if (q == 2) g_scale2[b*DIMM + c] = 1.f + acc;
        else             g_tg2[b*DIMM + c]    = tanhf(fminf(fmaxf(acc, -2.f), 2.f));
    }
}

// ------------------------- LayerNorm -> half (+opt fp32 normed) --------------
__global__ __launch_bounds__(256) void ln_mod_kernel(const float* __restrict__ in,
                                                     const float* __restrict__ scale,
                                                     __half* __restrict__ mh,
                                                     float* __restrict__ outnorm) {
    int rowi = blockIdx.x;
    int b = rowi >> 10;
    const float* x = in + (size_t)rowi * DIMM;
    float s = 0.f, sq = 0.f;
    for (int d = threadIdx.x; d < DIMM; d += 256) { float v = x[d]; s += v; sq += v * v; }
    #pragma unroll
    for (int o = 16; o; o >>= 1) {
        s  += __shfl_xor_sync(0xffffffffu, s,  o);
        sq += __shfl_xor_sync(0xffffffffu, sq, o);
    }
    __shared__ float rs[8], rq[8], mv[2];
    int w = threadIdx.x >> 5;
    if ((threadIdx.x & 31) == 0) { rs[w] = s; rq[w] = sq; }
    __syncthreads();
    if (threadIdx.x == 0) {
        float S = 0.f, Q = 0.f;
        for (int i = 0; i < 8; i++) { S += rs[i]; Q += rq[i]; }
        float mean = S / DIMM;
        float var = Q / DIMM - mean * mean;
        mv[0] = mean; mv[1] = rsqrtf(var + EPSL);
    }
    __syncthreads();
    float mean = mv[0], rstd = mv[1];
    const float* sc = scale + (size_t)b * DIMM;
    for (int d = threadIdx.x; d < DIMM; d += 256) {
        float n = (x[d] - mean) * rstd;
        if (outnorm) outnorm[(size_t)rowi * DIMM + d] = n;
        mh[(size_t)rowi * DIMM + d] = __float2half(n * sc[d]);
    }
}

// ------------------------- merged Q RMS + K/V repack (half in/out) ----------
__global__ __launch_bounds__(256) void qknorm_kernel(const float* __restrict__ nq,
                                                     const float* __restrict__ nk,
                                                     const float* __restrict__ nak) {
    int gw = (blockIdx.x * blockDim.x + threadIdx.x) >> 5;
    int lane = threadIdx.x & 31;
    int d4 = lane << 2;
    if (gw < NTOK * NH) {
        // ---- Q per-head RMS ----
        int tok = gw / NH, h = gw % NH;
        const __half* p = g_qkv_h + (size_t)tok * QKVN + h * HDD;
        __half2 a = *(const __half2*)(p + d4);
        __half2 b2 = *(const __half2*)(p + d4 + 2);
        float v0 = __half2float(__low2half(a)),  v1 = __half2float(__high2half(a));
        float v2 = __half2float(__low2half(b2)), v3 = __half2float(__high2half(b2));
        float ss = v0*v0 + v1*v1 + v2*v2 + v3*v3;
        #pragma unroll
        for (int o = 16; o; o >>= 1) ss += __shfl_xor_sync(0xffffffffu, ss, o);
        float r = rsqrtf(ss / HDD + EPSL);
        float4 wv = *(const float4*)(nq + d4);
        __half2* dst = (__half2*)(g_qh + (size_t)tok * DIMM + h * HDD + d4);
        dst[0] = __halves2half2(__float2half(v0 * r * wv.x), __float2half(v1 * r * wv.y));
        dst[1] = __halves2half2(__float2half(v2 * r * wv.z), __float2half(v3 * r * wv.w));
        return;
    }
    gw -= NTOK * NH;
    if (gw >= BSZ * NKV * LTOT) return;
    // ---- K RMS + K/V repack ----
    int l = gw % LTOT;
    int bk = gw / LTOT;
    int kv = bk % NKV, b = bk / NKV;
    const __half *ksrc, *vsrc;
    const float* w;
    if (l < SEQ) {
        const __half* base = g_qkv_h + (size_t)(b * SEQ + l) * QKVN;
        ksrc = base + DIMM + kv * HDD;
        vsrc = base + DIMM + IKV + kv * HDD;
        w = nk;
    } else {
        int tt = l - SEQ;
        const __half* base = g_akv_h + (size_t)(b * TXT + tt) * AKVN;
        ksrc = base + kv * HDD;
        vsrc = base + IKV + kv * HDD;
        w = nak;
    }
    __half2 ka = *(const __half2*)(ksrc + d4);
    __half2 kb2 = *(const __half2*)(ksrc + d4 + 2);
    float k0 = __half2float(__low2half(ka)),  k1 = __half2float(__high2half(ka));
    float k2 = __half2float(__low2half(kb2)), k3 = __half2float(__high2half(kb2));
    float ss = k0*k0 + k1*k1 + k2*k2 + k3*k3;
    #pragma unroll
    for (int o = 16; o; o >>= 1) ss += __shfl_xor_sync(0xffffffffu, ss, o);
    float r = rsqrtf(ss / HDD + EPSL);
    float4 wv = *(const float4*)(w + d4);
    size_t kbase = ((size_t)(b * NKV + kv) * LTOT + l) * HDD + d4;
    __half2* kd = (__half2*)(g_kh + kbase);
    kd[0] = __halves2half2(__float2half(k0 * r * wv.x), __float2half(k1 * r * wv.y));
    kd[1] = __halves2half2(__float2half(k2 * r * wv.z), __float2half(k3 * r * wv.w));
    __half2 va = *(const __half2*)(vsrc + d4);
    __half2 vb2 = *(const __half2*)(vsrc + d4 + 2);
    size_t vb = (size_t)(b * NKV + kv) * HDD;
    g_vT[(vb + d4    ) * LTOT + l] = __low2half(va);
    g_vT[(vb + d4 + 1) * LTOT + l] = __high2half(va);
    g_vT[(vb + d4 + 2) * LTOT + l] = __low2half(vb2);
    g_vT[(vb + d4 + 3) * LTOT + l] = __high2half(vb2);
}

// ------------------------- mma flash attention -------------------------------
#define FQSTR 272
#define FVSTR 144
#define FQSZ (64*FQSTR)
#define FKSZ (64*FQSTR)
#define FVSZ (128*FVSTR)
#define FBUF (FKSZ+FVSZ)
#define FSM  (FQSZ + 2*FBUF)

__global__ __launch_bounds__(128, 2) void flash_kernel() {
    extern __shared__ char fsm[];
    const int q0 = blockIdx.x * 64;
    const int h = blockIdx.y;
    const int b = blockIdx.z;
    const int kv = h / REP;
    const int t = threadIdx.x;
    const int w = t >> 5, lane = t & 31;
    const uint32_t uQ = s2u(fsm);
    const uint32_t uK0 = uQ + FQSZ;
    const __half* qg = g_qh + (size_t)(b * SEQ + q0) * DIMM + h * HDD;
    const __half* kg = g_kh + (size_t)(b * NKV + kv) * LTOT * HDD;
    const __half* vg = g_vT + (size_t)(b * NKV + kv) * HDD * LTOT;

    {
        int r = t >> 1, seg = t & 1;
        const __half* src = qg + (size_t)r * DIMM + seg * 64;
        uint32_t dst = uQ + r * FQSTR + seg * 128;
        #pragma unroll
        for (int i = 0; i < 8; i++) cpa16(dst + 16 * i, src + 8 * i);
        asm volatile("cp.async.commit_group;");
    }
    auto issue = [&](int c) {
        uint32_t base = uK0 + (c & 1) * FBUF;
        int k0 = c * 64;
        int r = t >> 1, seg = t & 1;
        const __half* ks = kg + (size_t)(k0 + r) * HDD + seg * 64;
        uint32_t kd = base + r * FQSTR + seg * 128;
        #pragma unroll
        for (int i = 0; i < 8; i++) cpa16(kd + 16 * i, ks + 8 * i);
        const __half* vs = vg + (size_t)t * LTOT + k0;
        uint32_t vd = base + FKSZ + t * FVSTR;
        #pragma unroll
        for (int i = 0; i < 8; i++) cpa16(vd + 16 * i, vs + 8 * i);
        asm volatile("cp.async.commit_group;");
    };

    const uint32_t aq_off = (w * 16 + (lane & 15)) * FQSTR + (lane >> 4) * 16;
    uint32_t bk_off[4];
    #pragma unroll
    for (int np = 0; np < 4; np++)
        bk_off[np] = (np * 16 + ((lane >> 4) << 3) + (lane & 7)) * FQSTR
                   + ((lane >> 3) & 1) * 16;
    uint32_t bv_off[8];
    #pragma unroll
    for (int np = 0; np < 8; np++)
        bv_off[np] = (np * 16 + ((lane >> 4) << 3) + (lane & 7)) * FVSTR
                   + ((lane >> 3) & 1) * 16;

    float o[16][4];
    #pragma unroll
    for (int i = 0; i < 16; i++)
        #pragma unroll
        for (int j = 0; j < 4; j++) o[i][j] = 0.f;
    float m0 = -1e30f, m1 = -1e30f, l0 = 0.f, l1 = 0.f;
    const float sc = 0.08838834764831845f;

    issue(0);
    const int NCH = LTOT / 64;
    for (int c = 0; c < NCH; c++) {
        if (c + 1 < NCH) { issue(c + 1); asm volatile("cp.async.wait_group 1;"); }
        else             { asm volatile("cp.async.wait_group 0;"); }
        __syncthreads();
        const uint32_t base = uK0 + (c & 1) * FBUF;
        float s[8][4];
        #pragma unroll
        for (int nt = 0; nt < 8; nt++)
            #pragma unroll
            for (int j = 0; j < 4; j++) s[nt][j] = 0.f;
        #pragma unroll
        for (int ks = 0; ks < 8; ks++) {
            uint32_t bf[8][2];
            #pragma unroll
            for (int np = 0; np < 4; np++)
                LDSM4(bf[np*2][0], bf[np*2][1], bf[np*2+1][0], bf[np*2+1][1],
                      base + bk_off[np] + ks * 32);
            uint32_t af[4];
            LDSM4(af[0], af[1], af[2], af[3], uQ + aq_off + ks * 32);
            #pragma unroll
            for (int nt = 0; nt < 8; nt++) mma16816(s[nt], af, bf[nt]);
        }
        float mx0 = -1e30f, mx1 = -1e30f;
        #pragma unroll
        for (int nt = 0; nt < 8; nt++) {
            mx0 = fmaxf(mx0, fmaxf(s[nt][0], s[nt][1]));
            mx1 = fmaxf(mx1, fmaxf(s[nt][2], s[nt][3]));
        }
        #pragma unroll
        for (int off = 1; off < 4; off <<= 1) {
            mx0 = fmaxf(mx0, __shfl_xor_sync(0xffffffffu, mx0, off));
            mx1 = fmaxf(mx1, __shfl_xor_sync(0xffffffffu, mx1, off));
        }
        float nm0 = fmaxf(m0, mx0 * sc), nm1 = fmaxf(m1, mx1 * sc);
        float cr0 = __expf(m0 - nm0), cr1 = __expf(m1 - nm1);
        float sum0 = 0.f, sum1 = 0.f;
        uint32_t pr0[8], pr1[8];
        #pragma unroll
        for (int nt = 0; nt < 8; nt++) {
            float p0 = __expf(s[nt][0] * sc - nm0);
            float p1 = __expf(s[nt][1] * sc - nm0);
            float p2 = __expf(s[nt][2] * sc - nm1);
            float p3 = __expf(s[nt][3] * sc - nm1);
            sum0 += p0 + p1; sum1 += p2 + p3;
            __half2 h0 = __halves2half2(__float2half(p0), __float2half(p1));
            __half2 h1 = __halves2half2(__float2half(p2), __float2half(p3));
            pr0[nt] = *(uint32_t*)&h0;
            pr1[nt] = *(uint32_t*)&h1;
        }
        #pragma unroll
        for (int off = 1; off < 4; off <<= 1) {
            sum0 += __shfl_xor_sync(0xffffffffu, sum0, off);
            sum1 += __shfl_xor_sync(0xffffffffu, sum1, off);
        }
        l0 = l0 * cr0 + sum0; l1 = l1 * cr1 + sum1;
        m0 = nm0; m1 = nm1;
        #pragma unroll
        for (int nt2 = 0; nt2 < 16; nt2++) {
            o[nt2][0] *= cr0; o[nt2][1] *= cr0;
            o[nt2][2] *= cr1; o[nt2][3] *= cr1;
        }
        const uint32_t vbase = base + FKSZ;
        #pragma unroll
        for (int ks2 = 0; ks2 < 4; ks2++) {
            uint32_t a[4] = { pr0[2*ks2], pr1[2*ks2], pr0[2*ks2+1], pr1[2*ks2+1] };
            #pragma unroll
            for (int np = 0; np < 8; np++) {
                uint32_t bf2[2][2];
                LDSM4(bf2[0][0], bf2[0][1], bf2[1][0], bf2[1][1],
                      vbase + bv_off[np] + ks2 * 32);
                mma16816(o[np*2],     a, bf2[0]);
                mma16816(o[np*2 + 1], a, bf2[1]);
            }
        }
        __syncthreads();
    }
    float i0 = 1.f / l0, i1 = 1.f / l1;
    const int g = lane >> 2, cp2 = (lane & 3) * 2;
    size_t ob = (size_t)(b * SEQ + q0 + w * 16 + g) * DIMM + h * HDD;
    #pragma unroll
    for (int nt2 = 0; nt2 < 16; nt2++) {
        __half2 v0 = __halves2half2(__float2half(o[nt2][0] * i0),
                                    __float2half(o[nt2][1] * i0));
        __half2 v1 = __halves2half2(__float2half(o[nt2][2] * i1),
                                    __float2half(o[nt2][3] * i1));
        *(__half2*)&g_attn_h[ob + nt2 * 8 + cp2] = v0;
        *(__half2*)&g_attn_h[ob + 8 * DIMM + nt2 * 8 + cp2] = v1;
    }
}

// ------------------------- router (tembdot also zeroes g_sums) --------------
__global__ __launch_bounds__(1024) void tembdot_kernel(const float* __restrict__ temb,
                                                       const float* __restrict__ Wg) {
    g_sums[threadIdx.x] = 0.f;
    g_sums[threadIdx.x + 1024] = 0.f;
    int wid = threadIdx.x >> 5, lane = threadIdx.x & 31;
    int b = wid / NE, e = wid % NE;
    const float* t = temb + b * DIMM;
    const float* w = Wg + (size_t)e * 2 * DIMM;
    float acc = 0.f;
    for (int d = lane; d < DIMM; d += 32) acc += t[d] * w[d];
    #pragma unroll
    for (int o = 16; o; o >>= 1) acc += __shfl_xor_sync(0xffffffffu, acc, o);
    if (lane == 0) g_tembdot[wid] = acc;
}

__global__ __launch_bounds__(128) void router_kernel(const float* __restrict__ Wg) {
    __shared__ float lg[NE];
    int tokid = blockIdx.x;
    int b = tokid >> 10, s = tokid & 1023;
    int w = threadIdx.x >> 5, lane = threadIdx.x & 31;
    const float* x = g_normed2 + (size_t)tokid * DIMM;
    for (int e = w * 4; e < w * 4 + 4; e++) {
        const float* wg = Wg + (size_t)e * 2 * DIMM + DIMM;
        float acc = 0.f;
        for (int d = lane; d < DIMM; d += 32) acc += x[d] * wg[d];
        #pragma unroll
        for (int o = 16; o; o >>= 1) acc += __shfl_xor_sync(0xffffffffu, acc, o);
        if (lane == 0) lg[e] = acc + g_tembdot[b * NE + e];
    }
    __syncthreads();
    if (threadIdx.x == 0) {
        float mx = -1e30f;
        for (int e = 0; e < NE; e++) mx = fmaxf(mx, lg[e]);
        float ex[NE], sm = 0.f;
        for (int e = 0; e < NE; e++) { ex[e] = __expf(lg[e] - mx); sm += ex[e]; }
        float inv = 1.f / sm;
        for (int e = 0; e < NE; e++)
            g_aff[((size_t)(b * NE + e)) * SEQ + s] = ex[e] * inv;
    }
}

// ------------------------- exact top-k via bitonic sort ---------------------
__global__ __launch_bounds__(512) void topk_kernel() {
    __shared__ float v[1024];
    __shared__ int   id[1024];
    int be = blockIdx.x;
    const float* rowp = g_aff + (size_t)be * SEQ;
    int t = threadIdx.x;
    for (int i = t; i < 1024; i += 512) { v[i] = rowp[i]; id[i] = i; }
    __syncthreads();
    for (int k = 2; k <= 1024; k <<= 1) {
        for (int j = k >> 1; j > 0; j >>= 1) {
            for (int i = t; i < 1024; i += 512) {
                int ixj = i ^ j;
                if (ixj > i) {
                    bool up = ((i & k) == 0);
                    float va = v[i], vb = v[ixj];
                    int ia = id[i], ib = id[ixj];
                    bool a_first = (va > vb) || (va == vb && ia < ib);
                    bool sw = up ? !a_first : a_first;
                    if (sw) { v[i] = vb; v[ixj] = va; id[i] = ib; id[ixj] = ia; }
                }
            }
            __syncthreads();
        }
    }
    if (t < CAP) {
        g_gating[be * CAP + t] = v[t];
        g_topidx[be * CAP + t] = id[t];
    }
}

__global__ void sum_acc_kernel() {
    int i = blockIdx.x * blockDim.x + threadIdx.x;
    if (i >= BSZ * NE * CAP) return;
    int be = i / CAP;
    int b = be / NE;
    int tok = b * SEQ + g_topidx[i];
    atomicAdd(&g_sums[tok], g_gating[i]);
}

__global__ void gate_norm_kernel() {
    int i = blockIdx.x * blockDim.x + threadIdx.x;
    if (i >= BSZ * NE * CAP) return;
    int c = i % CAP;
    int be = i / CAP;
    int b = be / NE, e = be % NE;
    int tok = b * SEQ + g_topidx[i];
    float g = g_gating[i] / (g_sums[tok] + 1e-12f) * 2.5f;
    int rowflat = (e * BSZ + b) * CAP + c;
    g_rowmap[rowflat] = tok;
    g_rscale[rowflat] = g;
}

// ------------------------- launcher -----------------------------------------
extern "C" void kernel_launch(void* const* d_in, const int* in_sizes, int n_in,
                              void* d_out, int out_size) {
    const float* hidden = (const float*)d_in[0];
    const float* enc    = (const float*)d_in[1];
    const float* temb   = (const float*)d_in[2];
    const float* W_mod  = (const float*)d_in[3];
    const float* b_mod  = (const float*)d_in[4];
    const float* W_enc  = (const float*)d_in[5];
    const float* b_enc  = (const float*)d_in[6];
    const float* Wq     = (const float*)d_in[7];
    const float* Wk     = (const float*)d_in[8];
    const float* Wv     = (const float*)d_in[9];
    const float* Wak    = (const float*)d_in[10];
    const float* Wav    = (const float*)d_in[11];
    const float* nq_w   = (const float*)d_in[12];
    const float* nk_w   = (const float*)d_in[13];
    const float* nak_w  = (const float*)d_in[14];
    const float* Wo     = (const float*)d_in[15];
    const float* Wg     = (const float*)d_in[16];
    const float* We_in  = (const float*)d_in[17];
    const float* We_out = (const float*)d_in[18];
    const float* Ws_in  = (const float*)d_in[19];
    const float* Ws_out = (const float*)d_in[20];
    float* out = (float*)d_out;

    void* pv;
    #define GF(sym) (cudaGetSymbolAddress(&pv, sym), (float*)pv)
    #define GH(sym) (cudaGetSymbolAddress(&pv, sym), (__half*)pv)
    #define GI(sym) (cudaGetSymbolAddress(&pv, sym), (int*)pv)
    float* p_hs1     = GF(g_hs1);
    float* p_normed2 = GF(g_normed2);
    float* p_scale1  = GF(g_scale1);
    float* p_scale2  = GF(g_scale2);
    float* p_tg1     = GF(g_tg1);
    float* p_tg2     = GF(g_tg2);
    int*   p_rowmap  = GI(g_rowmap);
    float* p_rscale  = GF(g_rscale);
    __half *p_enc_h = GH(g_enc_h);
    __half *p_Wenc_h = GH(g_Wenc_h);
    __half *p_Wqkv_h = GH(g_Wqkv_h);
    __half *p_Wakv_h = GH(g_Wakv_h);
    __half *p_Wo_h = GH(g_Wo_h);
    __half *p_Wein_h = GH(g_Wein_h);
    __half *p_Weout_h = GH(g_Weout_h);
    __half *p_Wsin_h = GH(g_Wsin_h);
    __half *p_Wsout_h = GH(g_Wsout_h);
    __half *p_ctx_h = GH(g_ctx_h);
    __half *p_img_h = GH(g_img_h);
    __half *p_attn_h = GH(g_attn_h);
    __half *p_mod2_h = GH(g_mod2_h);
    __half *p_actsh_h = GH(g_actsh_h);
    __half *p_actmoe_h = GH(g_actmoe_h);
    __half *p_qkv_h = GH(g_qkv_h);
    __half *p_akv_h = GH(g_akv_h);

    cudaFuncSetAttribute(mma_gemm<2,false>, cudaFuncAttributeMaxDynamicSharedMemorySize, MMSM);
    cudaFuncSetAttribute(mma_gemm<3,false>, cudaFuncAttributeMaxDynamicSharedMemorySize, MMSM);
    cudaFuncSetAttribute(mma_gemm<4,false>, cudaFuncAttributeMaxDynamicSharedMemorySize, MMSM);
    cudaFuncSetAttribute(mma_gemm<4,true>,  cudaFuncAttributeMaxDynamicSharedMemorySize, MMSM);
    cudaFuncSetAttribute(mma_gemm<5,false>, cudaFuncAttributeMaxDynamicSharedMemorySize, MMSM);
    cudaFuncSetAttribute(mma_gemm<6,false>, cudaFuncAttributeMaxDynamicSharedMemorySize, MMSM);
    cudaFuncSetAttribute(flash_kernel, cudaFuncAttributeMaxDynamicSharedMemorySize, FSM);

    const float* NFP = nullptr;
    const int*   NIP = nullptr;

    // 0. merged conversion table (10 plain segments)
    CvtTab tab;
    int nb = 0, si = 0;
    auto addseg = [&](const float* s, __half* d, long long n) {
        tab.src[si] = s; tab.dst[si] = d; tab.nelem[si] = n;
        tab.blkStart[si] = nb;
        nb += (int)((n + 4095) / 4096);
        si++;
    };
    addseg(W_enc, p_Wenc_h, (long long)DIMM*JD);
    addseg(Wq,  p_Wqkv_h,                           (long long)DIMM*DIMM);
    addseg(Wk,  p_Wqkv_h + (size_t)DIMM*DIMM,       (long long)IKV*DIMM);
    addseg(Wv,  p_Wqkv_h + (size_t)(DIMM+IKV)*DIMM, (long long)IKV*DIMM);
    addseg(Wak, p_Wakv_h,                           (long long)IKV*DIMM);
    addseg(Wav, p_Wakv_h + (size_t)IKV*DIMM,        (long long)IKV*DIMM);
    addseg(Wo,  p_Wo_h,  (long long)DIMM*DIMM);
    addseg(We_out, p_Weout_h, (long long)NE*DIMM*NI);
    addseg(Ws_out, p_Wsout_h, (long long)DIMM*NI);
    addseg(enc, p_enc_h, (long long)BSZ*TXT*JD);
    tab.nseg = si;
    tab.blkStart[si] = nb;
    for (int i = si + 1; i <= MAXSEG; i++) tab.blkStart[i] = nb;
    cvt_multi_kernel<<<nb, 256>>>(tab);
    cvt_ilv_kernel<<<NE*2*NI, 256>>>(We_in, p_Wein_h, NI);
    cvt_ilv_kernel<<<2*NI, 256>>>(Ws_in, p_Wsin_h, NI);

    // 1. modulation
    mod_kernel<<<1536, 256>>>(temb, W_mod, b_mod);
    // 2. context projection (+bias) -> half directly
    mma_gemm<5,false><<<dim3(12, 8, 1), 256, MMSM>>>(p_enc_h, p_Wenc_h, p_ctx_h,
        BSZ*TXT, DIMM, JD, 0, 0, 0, b_enc, NFP, NFP, NIP, NFP, NIP);
    // 3. LN1 * scale1 -> half
    ln_mod_kernel<<<NTOK, 256>>>(hidden, p_scale1, p_img_h, nullptr);
    // 4. merged projections (QKV for image; AK/AV for text) -> half
    mma_gemm<6,false><<<dim3(20, 16, 1), 256, MMSM>>>(p_img_h, p_Wqkv_h, p_qkv_h,
        NTOK, QKVN, DIMM, 0, 0, 0, NFP, NFP, NFP, NIP, NFP, NIP);
    mma_gemm<6,false><<<dim3(8, 8, 1), 256, MMSM>>>(p_ctx_h, p_Wakv_h, p_akv_h,
        BSZ*TXT, AKVN, DIMM, 0, 0, 0, NFP, NFP, NFP, NIP, NFP, NIP);
    // 5. merged Q/K norms + K/V repack
    qknorm_kernel<<<(NTOK*NH + BSZ*NKV*LTOT) / 8, 256>>>(nq_w, nk_w, nak_w);
    // 6. attention (mma, fp16)
    flash_kernel<<<dim3(SEQ/64, NH, BSZ), 128, FSM>>>();
    // 7. output proj + gated residual
    mma_gemm<2,false><<<dim3(12, 16, 1), 256, MMSM>>>(p_attn_h, p_Wo_h, p_hs1,
        NTOK, DIMM, DIMM, 0, 0, 0, NFP, hidden, p_tg1, NIP, NFP, NIP);
    // 8. LN2 -> mod2 half + normed2 fp32
    ln_mod_kernel<<<NTOK, 256>>>(p_hs1, p_scale2, p_mod2_h, p_normed2);
    // 9. router (tembdot also zeroes g_sums)
    tembdot_kernel<<<1, 1024>>>(temb, Wg);
    router_kernel<<<NTOK, 128>>>(Wg);
    topk_kernel<<<BSZ*NE, 512>>>();
    sum_acc_kernel<<<64, 256>>>();
    gate_norm_kernel<<<64, 256>>>();
    // 10. expert GEMM 1 (gathered A, interleaved weights, fused swiglu -> half)
    mma_gemm<4,true><<<dim3(21, 8, 16), 256, MMSM>>>(p_mod2_h, p_Wein_h, p_actmoe_h,
        BSZ*CAP, 2*NI, DIMM,
        0, (long long)2*NI*DIMM, (long long)BSZ*CAP*NI,
        NFP, NFP, NFP, NIP, NFP, p_rowmap);
    // 11. shared expert (fused swiglu -> half), then out-proj fused with
    //     hs1 residual + tg2 gate -> writes d_out directly
    mma_gemm<4,false><<<dim3(21, 16, 1), 256, MMSM>>>(p_mod2_h, p_Wsin_h, p_actsh_h,
        NTOK, 2*NI, DIMM, 0, 0, 0, NFP, NFP, NFP, NIP, NFP, NIP);
    mma_gemm<2,false><<<dim3(12, 16, 1), 256, MMSM>>>(p_actsh_h, p_Wsout_h, out,
        NTOK, DIMM, NI, 0, 0, 0, NFP, p_hs1, p_tg2, NIP, NFP, NIP);
    // 12. expert GEMM 2: gated atomic scatter (acc * rscale * tg2) onto d_out
    mma_gemm<3,false><<<dim3(12, 8, 16), 256, MMSM>>>(p_actmoe_h, p_Weout_h, out,
        BSZ*CAP, DIMM, NI,
        (long long)BSZ*CAP*NI, (long long)DIMM*NI, 0,
        NFP, NFP, p_tg2, p_rowmap, p_rscale, NIP);
}